// round 2
// baseline (speedup 1.0000x reference)
#include <cuda_runtime.h>
#include <math.h>

#define HEADS 24
#define HD    128
#define DIM   3072
#define S_IMG 2048
#define S_TXT 512
#define S_TOT 2560   // txt rows first, then img rows

// ---------------- scratch (static device memory; no allocations) ------------
__device__ float g_q[(size_t)S_TOT * DIM];
__device__ float g_k[(size_t)S_TOT * DIM];
__device__ float g_v[(size_t)S_TOT * DIM];
__device__ float g_attn[(size_t)S_TOT * DIM];
__device__ float g_scores[(size_t)HEADS * S_TOT * S_TOT];   // ~629 MB

// ---------------- GEMM: C = scale * A * B^T (+bias), batched ----------------
// A: [M,K] row-major lda, B: [N,K] row-major ldb (i.e. we multiply by B^T)
// 128x128 tile, BK=8, 256 threads, 8x8 per-thread microtile.
// All M,N multiples of 128; K multiple of 8; pointers 16B aligned.
__global__ __launch_bounds__(256) void gemm_tn(
    const float* __restrict__ A, int lda, long long strideA,
    const float* __restrict__ B, int ldb, long long strideB,
    float* __restrict__ C, int ldc, long long strideC,
    int K, const float* __restrict__ bias, float scale)
{
    __shared__ float As[8][128];
    __shared__ float Bs[8][128];

    const long long bz = blockIdx.z;
    A += bz * strideA;  B += bz * strideB;  C += bz * strideC;

    const int m0 = blockIdx.y * 128;
    const int n0 = blockIdx.x * 128;
    const int tid = threadIdx.x;
    const int tx = tid & 15;          // 0..15  -> n microtile
    const int ty = tid >> 4;          // 0..15  -> m microtile
    const int lRow = tid >> 1;        // 0..127
    const int lCol = (tid & 1) * 4;   // 0 or 4

    float acc[8][8];
    #pragma unroll
    for (int i = 0; i < 8; i++)
        #pragma unroll
        for (int j = 0; j < 8; j++) acc[i][j] = 0.f;

    const float* aPtr = &A[(long long)(m0 + lRow) * lda + lCol];
    const float* bPtr = &B[(long long)(n0 + lRow) * ldb + lCol];

    for (int k0 = 0; k0 < K; k0 += 8) {
        float4 av = *reinterpret_cast<const float4*>(aPtr + k0);
        float4 bv = *reinterpret_cast<const float4*>(bPtr + k0);
        As[lCol + 0][lRow] = av.x; As[lCol + 1][lRow] = av.y;
        As[lCol + 2][lRow] = av.z; As[lCol + 3][lRow] = av.w;
        Bs[lCol + 0][lRow] = bv.x; Bs[lCol + 1][lRow] = bv.y;
        Bs[lCol + 2][lRow] = bv.z; Bs[lCol + 3][lRow] = bv.w;
        __syncthreads();

        #pragma unroll
        for (int kk = 0; kk < 8; kk++) {
            float4 a0 = *reinterpret_cast<const float4*>(&As[kk][ty * 8]);
            float4 a1 = *reinterpret_cast<const float4*>(&As[kk][ty * 8 + 4]);
            float4 b0 = *reinterpret_cast<const float4*>(&Bs[kk][tx * 8]);
            float4 b1 = *reinterpret_cast<const float4*>(&Bs[kk][tx * 8 + 4]);
            float a[8] = {a0.x, a0.y, a0.z, a0.w, a1.x, a1.y, a1.z, a1.w};
            float b[8] = {b0.x, b0.y, b0.z, b0.w, b1.x, b1.y, b1.z, b1.w};
            #pragma unroll
            for (int i = 0; i < 8; i++)
                #pragma unroll
                for (int j = 0; j < 8; j++)
                    acc[i][j] = fmaf(a[i], b[j], acc[i][j]);
        }
        __syncthreads();
    }

    #pragma unroll
    for (int i = 0; i < 8; i++) {
        const int m = m0 + ty * 8 + i;
        #pragma unroll
        for (int j = 0; j < 8; j++) {
            const int n = n0 + tx * 8 + j;
            float v = acc[i][j] * scale;
            if (bias) v += bias[n];
            C[(long long)m * ldc + n] = v;
        }
    }
}

// ---------------- GEMM: C = A * B, batched (for P @ V) -----------------------
// A: [M,K] lda, B: [K,N] ldb row-major. Same tiling.
__global__ __launch_bounds__(256) void gemm_nn(
    const float* __restrict__ A, int lda, long long strideA,
    const float* __restrict__ B, int ldb, long long strideB,
    float* __restrict__ C, int ldc, long long strideC,
    int K)
{
    __shared__ float As[8][128];
    __shared__ float Bs[8][128];

    const long long bz = blockIdx.z;
    A += bz * strideA;  B += bz * strideB;  C += bz * strideC;

    const int m0 = blockIdx.y * 128;
    const int n0 = blockIdx.x * 128;
    const int tid = threadIdx.x;
    const int tx = tid & 15;
    const int ty = tid >> 4;
    const int aRow = tid >> 1;
    const int aCol = (tid & 1) * 4;
    const int bRow = tid >> 5;         // 0..7
    const int bCol = (tid & 31) * 4;   // 0..124

    float acc[8][8];
    #pragma unroll
    for (int i = 0; i < 8; i++)
        #pragma unroll
        for (int j = 0; j < 8; j++) acc[i][j] = 0.f;

    for (int k0 = 0; k0 < K; k0 += 8) {
        float4 av = *reinterpret_cast<const float4*>(&A[(long long)(m0 + aRow) * lda + k0 + aCol]);
        As[aCol + 0][aRow] = av.x; As[aCol + 1][aRow] = av.y;
        As[aCol + 2][aRow] = av.z; As[aCol + 3][aRow] = av.w;
        float4 bv = *reinterpret_cast<const float4*>(&B[(long long)(k0 + bRow) * ldb + n0 + bCol]);
        Bs[bRow][bCol + 0] = bv.x; Bs[bRow][bCol + 1] = bv.y;
        Bs[bRow][bCol + 2] = bv.z; Bs[bRow][bCol + 3] = bv.w;
        __syncthreads();

        #pragma unroll
        for (int kk = 0; kk < 8; kk++) {
            float4 a0 = *reinterpret_cast<const float4*>(&As[kk][ty * 8]);
            float4 a1 = *reinterpret_cast<const float4*>(&As[kk][ty * 8 + 4]);
            float4 b0 = *reinterpret_cast<const float4*>(&Bs[kk][tx * 8]);
            float4 b1 = *reinterpret_cast<const float4*>(&Bs[kk][tx * 8 + 4]);
            float a[8] = {a0.x, a0.y, a0.z, a0.w, a1.x, a1.y, a1.z, a1.w};
            float b[8] = {b0.x, b0.y, b0.z, b0.w, b1.x, b1.y, b1.z, b1.w};
            #pragma unroll
            for (int i = 0; i < 8; i++)
                #pragma unroll
                for (int j = 0; j < 8; j++)
                    acc[i][j] = fmaf(a[i], b[j], acc[i][j]);
        }
        __syncthreads();
    }

    #pragma unroll
    for (int i = 0; i < 8; i++) {
        const int m = m0 + ty * 8 + i;
        #pragma unroll
        for (int j = 0; j < 8; j++)
            C[(long long)m * ldc + (n0 + tx * 8 + j)] = acc[i][j];
    }
}

// ---------------- RMSNorm + RoPE over one (seq, head) vector of 128 ----------
__global__ void norm_rope_kernel(
    float* __restrict__ x,
    const float* __restrict__ w_txt, const float* __restrict__ w_img,
    const float* __restrict__ txt_cos, const float* __restrict__ txt_sin,
    const float* __restrict__ img_cos, const float* __restrict__ img_sin)
{
    const int s = blockIdx.x;             // 0..S_TOT-1 (txt first)
    const int h = blockIdx.y;
    const int d = threadIdx.x;            // 0..127
    float* p = x + (long long)s * DIM + h * HD;

    float v = p[d];
    float ss = v * v;
    #pragma unroll
    for (int off = 16; off > 0; off >>= 1)
        ss += __shfl_xor_sync(0xffffffffu, ss, off);
    __shared__ float wsum[4];
    if ((d & 31) == 0) wsum[d >> 5] = ss;
    __syncthreads();
    const float tot = wsum[0] + wsum[1] + wsum[2] + wsum[3];
    const float r = rsqrtf(tot * (1.0f / HD) + 1e-6f);

    const bool is_txt = (s < S_TXT);
    const float* w = is_txt ? w_txt : w_img;
    const float nv = v * r * w[d];

    const float other = __shfl_xor_sync(0xffffffffu, nv, 1);
    const float rot = (d & 1) ? other : -other;

    const long long srel = is_txt ? s : (s - S_TXT);
    const float c = (is_txt ? txt_cos : img_cos)[srel * HD + d];
    const float sn = (is_txt ? txt_sin : img_sin)[srel * HD + d];
    p[d] = nv * c + rot * sn;
}

// ---------------- row softmax -----------------------------------------------
__global__ void softmax_rows(float* __restrict__ sc, int n)
{
    const long long row = blockIdx.x;
    float* p = sc + row * (long long)n;
    __shared__ float red[256];
    const int t = threadIdx.x;

    float mx = -1e30f;
    for (int i = t; i < n; i += 256) mx = fmaxf(mx, p[i]);
    red[t] = mx; __syncthreads();
    for (int off = 128; off > 0; off >>= 1) {
        if (t < off) red[t] = fmaxf(red[t], red[t + off]);
        __syncthreads();
    }
    mx = red[0]; __syncthreads();

    float sum = 0.f;
    for (int i = t; i < n; i += 256) {
        const float e = __expf(p[i] - mx);
        p[i] = e;
        sum += e;
    }
    red[t] = sum; __syncthreads();
    for (int off = 128; off > 0; off >>= 1) {
        if (t < off) red[t] += red[t + off];
        __syncthreads();
    }
    const float inv = 1.0f / red[0];
    for (int i = t; i < n; i += 256) p[i] *= inv;
}

// ---------------- launch -----------------------------------------------------
extern "C" void kernel_launch(void* const* d_in, const int* in_sizes, int n_in,
                              void* d_out, int out_size)
{
    const float* hidden  = (const float*)d_in[0];
    const float* enc     = (const float*)d_in[1];
    const float* img_cos = (const float*)d_in[2];
    const float* img_sin = (const float*)d_in[3];
    const float* txt_cos = (const float*)d_in[4];
    const float* txt_sin = (const float*)d_in[5];

    const float *Wq,*bq,*Wk,*bk,*Wv,*bv,*Waq,*baq,*Wak,*bak,*Wav,*bav,*Wo,*bo,*Wao,*bao;
    if (in_sizes[7] == DIM) {
        // interleaved: Wq,bq,Wk,bk,Wv,bv,Waq,baq,Wak,bak,Wav,bav,Wo,bo,Wao,bao
        Wq =(const float*)d_in[6];  bq =(const float*)d_in[7];
        Wk =(const float*)d_in[8];  bk =(const float*)d_in[9];
        Wv =(const float*)d_in[10]; bv =(const float*)d_in[11];
        Waq=(const float*)d_in[12]; baq=(const float*)d_in[13];
        Wak=(const float*)d_in[14]; bak=(const float*)d_in[15];
        Wav=(const float*)d_in[16]; bav=(const float*)d_in[17];
        Wo =(const float*)d_in[18]; bo =(const float*)d_in[19];
        Wao=(const float*)d_in[20]; bao=(const float*)d_in[21];
    } else {
        // grouped: Wq,Wk,Wv,Waq,Wak,Wav,Wo,Wao then bq,bk,bv,baq,bak,bav,bo,bao
        Wq =(const float*)d_in[6];  Wk =(const float*)d_in[7];  Wv =(const float*)d_in[8];
        Waq=(const float*)d_in[9];  Wak=(const float*)d_in[10]; Wav=(const float*)d_in[11];
        Wo =(const float*)d_in[12]; Wao=(const float*)d_in[13];
        bq =(const float*)d_in[14]; bk =(const float*)d_in[15]; bv =(const float*)d_in[16];
        baq=(const float*)d_in[17]; bak=(const float*)d_in[18]; bav=(const float*)d_in[19];
        bo =(const float*)d_in[20]; bao=(const float*)d_in[21];
    }
    const float* nq_w  = (const float*)d_in[22];
    const float* nk_w  = (const float*)d_in[23];
    const float* naq_w = (const float*)d_in[24];
    const float* nak_w = (const float*)d_in[25];

    // Resolve scratch pointers once; cached so the capture call does only
    // kernel launches. cudaGetSymbolAddress is a pure lookup (capture-legal)
    // but caching removes even that from the captured path.
    static float *q = nullptr, *k = nullptr, *v = nullptr, *attn = nullptr, *scores = nullptr;
    if (!q) {
        cudaGetSymbolAddress((void**)&q,      g_q);
        cudaGetSymbolAddress((void**)&k,      g_k);
        cudaGetSymbolAddress((void**)&v,      g_v);
        cudaGetSymbolAddress((void**)&attn,   g_attn);
        cudaGetSymbolAddress((void**)&scores, g_scores);
    }

    const dim3 blk(256);
    const dim3 gProjImg(DIM / 128, S_IMG / 128, 1);
    const dim3 gProjTxt(DIM / 128, S_TXT / 128, 1);

    // QKV projections (txt rows 0..511, img rows 512..2559)
    gemm_tn<<<gProjImg, blk>>>(hidden, DIM, 0, Wq, DIM, 0,
                               q + (long long)S_TXT * DIM, DIM, 0, DIM, bq, 1.0f);
    gemm_tn<<<gProjImg, blk>>>(hidden, DIM, 0, Wk, DIM, 0,
                               k + (long long)S_TXT * DIM, DIM, 0, DIM, bk, 1.0f);
    gemm_tn<<<gProjImg, blk>>>(hidden, DIM, 0, Wv, DIM, 0,
                               v + (long long)S_TXT * DIM, DIM, 0, DIM, bv, 1.0f);
    gemm_tn<<<gProjTxt, blk>>>(enc, DIM, 0, Waq, DIM, 0, q, DIM, 0, DIM, baq, 1.0f);
    gemm_tn<<<gProjTxt, blk>>>(enc, DIM, 0, Wak, DIM, 0, k, DIM, 0, DIM, bak, 1.0f);
    gemm_tn<<<gProjTxt, blk>>>(enc, DIM, 0, Wav, DIM, 0, v, DIM, 0, DIM, bav, 1.0f);

    // RMSNorm + RoPE on q,k
    const dim3 gNR(S_TOT, HEADS);
    norm_rope_kernel<<<gNR, 128>>>(q, naq_w, nq_w, txt_cos, txt_sin, img_cos, img_sin);
    norm_rope_kernel<<<gNR, 128>>>(k, nak_w, nk_w, txt_cos, txt_sin, img_cos, img_sin);

    // scores = (Q K^T) / sqrt(HD), batched over heads
    const float scale = 0.08838834764831845f;  // 1/sqrt(128)
    gemm_tn<<<dim3(S_TOT / 128, S_TOT / 128, HEADS), blk>>>(
        q, DIM, HD, k, DIM, HD,
        scores, S_TOT, (long long)S_TOT * S_TOT, HD, nullptr, scale);

    // softmax rows
    softmax_rows<<<HEADS * S_TOT, 256>>>(scores, S_TOT);

    // attn = P @ V, batched over heads
    gemm_nn<<<dim3(HD / 128, S_TOT / 128, HEADS), blk>>>(
        scores, S_TOT, (long long)S_TOT * S_TOT,
        v, DIM, HD,
        attn, DIM, HD, S_TOT);

    // output projections: img_out first, then txt_out
    float* outp = (float*)d_out;
    gemm_tn<<<gProjImg, blk>>>(attn + (long long)S_TXT * DIM, DIM, 0, Wo, DIM, 0,
                               outp, DIM, 0, DIM, bo, 1.0f);
    gemm_tn<<<gProjTxt, blk>>>(attn, DIM, 0, Wao, DIM, 0,
                               outp + (long long)S_IMG * DIM, DIM, 0, DIM, bao, 1.0f);
}

// round 4
// speedup vs baseline: 2.6695x; 2.6695x over previous
#include <cuda_runtime.h>
#include <cuda_bf16.h>
#include <cstdint>
#include <math.h>

#define HEADS 24
#define HD    128
#define DIM   3072
#define S_IMG 2048
#define S_TXT 512
#define S_TOT 2560
#define WSZ   ((size_t)DIM * DIM)

// ---------------- scratch (static device memory; no allocations) ------------
__device__ float g_q[(size_t)S_TOT * DIM];
__device__ float g_k[(size_t)S_TOT * DIM];
__device__ float g_v[(size_t)S_TOT * DIM];
__device__ float g_attn[(size_t)S_TOT * DIM];
__device__ float g_scores[(size_t)HEADS * S_TOT * S_TOT];     // 629 MB

__device__ __nv_bfloat16 g_xhi[(size_t)S_TOT * DIM], g_xlo[(size_t)S_TOT * DIM];
__device__ __nv_bfloat16 g_whi[8 * WSZ], g_wlo[8 * WSZ];
__device__ __nv_bfloat16 g_qhi[(size_t)S_TOT * DIM], g_qlo[(size_t)S_TOT * DIM];
__device__ __nv_bfloat16 g_khi[(size_t)S_TOT * DIM], g_klo[(size_t)S_TOT * DIM];
__device__ __nv_bfloat16 g_vthi[(size_t)HEADS * HD * S_TOT], g_vtlo[(size_t)HEADS * HD * S_TOT];
__device__ __nv_bfloat16 g_phi[(size_t)HEADS * S_TOT * S_TOT], g_plo[(size_t)HEADS * S_TOT * S_TOT];
__device__ __nv_bfloat16 g_ahi[(size_t)S_TOT * DIM], g_alo[(size_t)S_TOT * DIM];

// ---------------- helpers ----------------------------------------------------
__device__ __forceinline__ uint32_t smem_u32(const void* p) {
    return (uint32_t)__cvta_generic_to_shared(p);
}

__device__ __forceinline__ void cp16(uint32_t dst, const void* src) {
    asm volatile("cp.async.cg.shared.global [%0], [%1], 16;" :: "r"(dst), "l"(src));
}

__device__ __forceinline__ void ldm_x4(uint32_t* r, uint32_t addr) {
    asm volatile("ldmatrix.sync.aligned.m8n8.x4.shared.b16 {%0,%1,%2,%3}, [%4];"
                 : "=r"(r[0]), "=r"(r[1]), "=r"(r[2]), "=r"(r[3]) : "r"(addr));
}

__device__ __forceinline__ void mma16816(float* c, const uint32_t* a, uint32_t b0, uint32_t b1) {
    asm volatile(
        "mma.sync.aligned.m16n8k16.row.col.f32.bf16.bf16.f32 "
        "{%0,%1,%2,%3}, {%4,%5,%6,%7}, {%8,%9}, {%0,%1,%2,%3};"
        : "+f"(c[0]), "+f"(c[1]), "+f"(c[2]), "+f"(c[3])
        : "r"(a[0]), "r"(a[1]), "r"(a[2]), "r"(a[3]), "r"(b0), "r"(b1));
}

// ---------------- split-bf16 tensor-core GEMM (mma.sync, base PTX) -----------
// C[m,n] (fp32) = scale * sum_k A[m,k]*B[n,k]  (+ bias[n]);  A,B as hi/lo bf16.
// CTA tile 128x128, K-chunk 32, double-buffered cp.async, 8 warps (4m x 2n).
// SMEM rows padded to 80B -> conflict-free ldmatrix without XOR swizzle.
// Rows m < S_TXT take (B2, bias2). remap=1 relocates output rows (img first).
#define TILEB   10240          /* 128 rows * 80 B */
#define BUFB    (4 * TILEB)    /* Ah Al Bh Bl     */
__global__ __launch_bounds__(256) void mma_gemm(
    const __nv_bfloat16* __restrict__ Ahi, const __nv_bfloat16* __restrict__ Alo,
    long long lda, long long strideA,
    const __nv_bfloat16* __restrict__ Bhi, const __nv_bfloat16* __restrict__ Blo,
    const __nv_bfloat16* __restrict__ B2hi, const __nv_bfloat16* __restrict__ B2lo,
    long long ldb, long long strideB,
    float* __restrict__ C, long long ldc, long long strideC,
    int K, const float* __restrict__ bias, const float* __restrict__ bias2,
    float scale, int remap)
{
    extern __shared__ char smem[];
    const uint32_t sb = smem_u32(smem);
    const int tid = threadIdx.x;
    const int wid = tid >> 5;
    const int lane = tid & 31;
    const int warp_m = wid & 3;       // 4 warps over M (32 rows each)
    const int warp_n = wid >> 2;      // 2 warps over N (64 cols each)

    const int m0 = blockIdx.y * 128;
    const int n0 = blockIdx.x * 128;
    const long long z = blockIdx.z;

    const bool alt = (m0 < S_TXT);
    const __nv_bfloat16* srcs[4];
    srcs[0] = Ahi + z * strideA;
    srcs[1] = Alo + z * strideA;
    srcs[2] = (alt ? B2hi : Bhi) + z * strideB;
    srcs[3] = (alt ? B2lo : Blo) + z * strideB;

    float acc[2][8][4];
    #pragma unroll
    for (int mi = 0; mi < 2; mi++)
        #pragma unroll
        for (int ni = 0; ni < 8; ni++)
            #pragma unroll
            for (int j = 0; j < 4; j++) acc[mi][ni][j] = 0.f;

    const int nc = K >> 5;

    // ---- async tile loader: 4 arrays x 128 rows x 4 x 16B segments ---------
    auto issue = [&](int c) {
        const int k0 = c * 32;
        const uint32_t base = sb + (uint32_t)((c & 1) * BUFB);
        #pragma unroll
        for (int it = 0; it < 8; it++) {
            const int idx = it * 256 + tid;
            const int arr = idx >> 9;
            const int rem = idx & 511;
            const int r = rem >> 2;
            const int s = rem & 3;
            const long long ld = (arr < 2) ? lda : ldb;
            const int rbase = (arr < 2) ? m0 : n0;
            const __nv_bfloat16* sp = srcs[arr] + (long long)(rbase + r) * ld + k0 + s * 8;
            cp16(base + (uint32_t)(arr * TILEB + r * 80 + s * 16), sp);
        }
    };

    issue(0);
    asm volatile("cp.async.commit_group;" ::: "memory");

    for (int c = 0; c < nc; c++) {
        if (c + 1 < nc) issue(c + 1);
        asm volatile("cp.async.commit_group;" ::: "memory");
        asm volatile("cp.async.wait_group 1;" ::: "memory");
        __syncthreads();

        const uint32_t base = sb + (uint32_t)((c & 1) * BUFB);
        const uint32_t aH = base, aL = base + TILEB;
        const uint32_t bH = base + 2 * TILEB, bL = base + 3 * TILEB;

        #pragma unroll
        for (int ks = 0; ks < 2; ks++) {
            // A fragments: row = warp_m*32 + mi*16 + lane%16, kseg = ks*2 + lane/16
            uint32_t a_h[2][4], a_l[2][4];
            const uint32_t arow = (uint32_t)(warp_m * 32 + (lane & 15));
            const uint32_t akseg = (uint32_t)(ks * 2 + (lane >> 4));
            #pragma unroll
            for (int mi = 0; mi < 2; mi++) {
                const uint32_t aoff = (arow + mi * 16) * 80 + akseg * 16;
                ldm_x4(a_h[mi], aH + aoff);
                ldm_x4(a_l[mi], aL + aoff);
            }
            // B fragments: pairs of 8-col tiles
            const uint32_t bn = (uint32_t)(warp_n * 64 + ((lane >> 4) << 3) + (lane & 7));
            const uint32_t bkseg = (uint32_t)(ks * 2 + ((lane >> 3) & 1));
            #pragma unroll
            for (int njp = 0; njp < 4; njp++) {
                uint32_t bh4[4], bl4[4];
                const uint32_t boff = (bn + njp * 16) * 80 + bkseg * 16;
                ldm_x4(bh4, bH + boff);
                ldm_x4(bl4, bL + boff);
                #pragma unroll
                for (int sub = 0; sub < 2; sub++) {
                    const int ni = njp * 2 + sub;
                    #pragma unroll
                    for (int mi = 0; mi < 2; mi++) {
                        mma16816(acc[mi][ni], a_h[mi], bh4[sub * 2], bh4[sub * 2 + 1]);
                        mma16816(acc[mi][ni], a_h[mi], bl4[sub * 2], bl4[sub * 2 + 1]);
                        mma16816(acc[mi][ni], a_l[mi], bh4[sub * 2], bh4[sub * 2 + 1]);
                    }
                }
            }
        }
        __syncthreads();
    }

    // ---- epilogue ----------------------------------------------------------
    const float* bp = (bias == nullptr) ? nullptr : (alt ? bias2 : bias);
    float* Cz = C + z * strideC;
    #pragma unroll
    for (int mi = 0; mi < 2; mi++) {
        const int r_lo = m0 + warp_m * 32 + mi * 16 + (lane >> 2);
        #pragma unroll
        for (int half = 0; half < 2; half++) {
            int r = r_lo + half * 8;
            long long orow = r;
            if (remap) orow = (r < S_TXT) ? (long long)(S_IMG + r) : (long long)(r - S_TXT);
            float* crow = Cz + orow * ldc;
            #pragma unroll
            for (int ni = 0; ni < 8; ni++) {
                const int col = n0 + warp_n * 64 + ni * 8 + (lane & 3) * 2;
                float2 o;
                o.x = acc[mi][ni][half * 2 + 0] * scale;
                o.y = acc[mi][ni][half * 2 + 1] * scale;
                if (bp) { o.x += bp[col]; o.y += bp[col + 1]; }
                *reinterpret_cast<float2*>(crow + col) = o;
            }
        }
    }
}

// ---------------- split helpers ----------------------------------------------
__device__ __forceinline__ void split4(float4 v, __nv_bfloat16* hi, __nv_bfloat16* lo,
                                       long long idx) {
    __nv_bfloat16 h0 = __float2bfloat16(v.x), h1 = __float2bfloat16(v.y);
    __nv_bfloat16 h2 = __float2bfloat16(v.z), h3 = __float2bfloat16(v.w);
    __nv_bfloat162 a; a.x = h0; a.y = h1;
    __nv_bfloat162 b; b.x = h2; b.y = h3;
    *reinterpret_cast<__nv_bfloat162*>(hi + idx)     = a;
    *reinterpret_cast<__nv_bfloat162*>(hi + idx + 2) = b;
    __nv_bfloat162 c; c.x = __float2bfloat16(v.x - __bfloat162float(h0));
                      c.y = __float2bfloat16(v.y - __bfloat162float(h1));
    __nv_bfloat162 d; d.x = __float2bfloat16(v.z - __bfloat162float(h2));
                      d.y = __float2bfloat16(v.w - __bfloat162float(h3));
    *reinterpret_cast<__nv_bfloat162*>(lo + idx)     = c;
    *reinterpret_cast<__nv_bfloat162*>(lo + idx + 2) = d;
}

__global__ void split_x_kernel(const float* __restrict__ hidden, const float* __restrict__ enc,
                               __nv_bfloat16* __restrict__ hi, __nv_bfloat16* __restrict__ lo) {
    const long long i4 = ((long long)blockIdx.x * 256 + threadIdx.x) * 4;
    const long long row = i4 / DIM;
    const float* src = (row < S_TXT) ? (enc + i4) : (hidden + i4 - (long long)S_TXT * DIM);
    split4(*reinterpret_cast<const float4*>(src), hi, lo, i4);
}

__global__ void split_plain(const float* __restrict__ src,
                            __nv_bfloat16* __restrict__ hi, __nv_bfloat16* __restrict__ lo) {
    const long long i4 = ((long long)blockIdx.x * 256 + threadIdx.x) * 4;
    split4(*reinterpret_cast<const float4*>(src + i4), hi, lo, i4);
}

// ---------------- RMSNorm + RoPE + split -------------------------------------
__global__ void norm_rope_split(
    const float* __restrict__ x,
    __nv_bfloat16* __restrict__ hi, __nv_bfloat16* __restrict__ lo,
    const float* __restrict__ w_txt, const float* __restrict__ w_img,
    const float* __restrict__ txt_cos, const float* __restrict__ txt_sin,
    const float* __restrict__ img_cos, const float* __restrict__ img_sin)
{
    const int s = blockIdx.x;
    const int h = blockIdx.y;
    const int d = threadIdx.x;
    const long long off = (long long)s * DIM + h * HD;

    float v = x[off + d];
    float ss = v * v;
    #pragma unroll
    for (int o = 16; o > 0; o >>= 1) ss += __shfl_xor_sync(0xffffffffu, ss, o);
    __shared__ float wsum[4];
    if ((d & 31) == 0) wsum[d >> 5] = ss;
    __syncthreads();
    const float tot = wsum[0] + wsum[1] + wsum[2] + wsum[3];
    const float r = rsqrtf(tot * (1.0f / HD) + 1e-6f);

    const bool is_txt = (s < S_TXT);
    const float* w = is_txt ? w_txt : w_img;
    const float nv = v * r * w[d];

    const float other = __shfl_xor_sync(0xffffffffu, nv, 1);
    const float rot = (d & 1) ? other : -other;

    const long long srel = is_txt ? s : (s - S_TXT);
    const float cc = (is_txt ? txt_cos : img_cos)[srel * HD + d];
    const float sn = (is_txt ? txt_sin : img_sin)[srel * HD + d];
    const float f = nv * cc + rot * sn;

    __nv_bfloat16 hh = __float2bfloat16(f);
    hi[off + d] = hh;
    lo[off + d] = __float2bfloat16(f - __bfloat162float(hh));
}

// ---------------- softmax + split --------------------------------------------
__global__ void softmax_split(const float* __restrict__ sc,
                              __nv_bfloat16* __restrict__ phi, __nv_bfloat16* __restrict__ plo)
{
    const long long row = blockIdx.x;
    const float* p = sc + row * (long long)S_TOT;
    __nv_bfloat16* ph = phi + row * (long long)S_TOT;
    __nv_bfloat16* pl = plo + row * (long long)S_TOT;
    __shared__ float red[256];
    const int t = threadIdx.x;

    float vals[10];
    float mx = -1e30f;
    #pragma unroll
    for (int j = 0; j < 10; j++) { vals[j] = p[t + j * 256]; mx = fmaxf(mx, vals[j]); }
    red[t] = mx; __syncthreads();
    for (int o = 128; o > 0; o >>= 1) {
        if (t < o) red[t] = fmaxf(red[t], red[t + o]);
        __syncthreads();
    }
    mx = red[0]; __syncthreads();

    float sum = 0.f;
    #pragma unroll
    for (int j = 0; j < 10; j++) { vals[j] = __expf(vals[j] - mx); sum += vals[j]; }
    red[t] = sum; __syncthreads();
    for (int o = 128; o > 0; o >>= 1) {
        if (t < o) red[t] += red[t + o];
        __syncthreads();
    }
    const float inv = 1.0f / red[0];
    #pragma unroll
    for (int j = 0; j < 10; j++) {
        const float f = vals[j] * inv;
        __nv_bfloat16 hh = __float2bfloat16(f);
        ph[t + j * 256] = hh;
        pl[t + j * 256] = __float2bfloat16(f - __bfloat162float(hh));
    }
}

// ---------------- V transpose + split:  v[s, DIM] -> vt[head][d][s] ----------
__global__ void vtrans_split(const float* __restrict__ v,
                             __nv_bfloat16* __restrict__ vhi, __nv_bfloat16* __restrict__ vlo)
{
    __shared__ float tile[32][33];
    const int c0 = blockIdx.x * 32;
    const int s0 = blockIdx.y * 32;
    const int tx = threadIdx.x, ty = threadIdx.y;

    #pragma unroll
    for (int r = ty; r < 32; r += 8)
        tile[r][tx] = v[(long long)(s0 + r) * DIM + c0 + tx];
    __syncthreads();
    #pragma unroll
    for (int r = ty; r < 32; r += 8) {
        const int c = c0 + r;
        const int head = c >> 7, d = c & 127;
        const long long o = (long long)head * HD * S_TOT + (long long)d * S_TOT + s0 + tx;
        const float f = tile[tx][r];
        __nv_bfloat16 hh = __float2bfloat16(f);
        vhi[o] = hh;
        vlo[o] = __float2bfloat16(f - __bfloat162float(hh));
    }
}

// ---------------- launch -----------------------------------------------------
extern "C" void kernel_launch(void* const* d_in, const int* in_sizes, int n_in,
                              void* d_out, int out_size)
{
    const float* hidden  = (const float*)d_in[0];
    const float* enc     = (const float*)d_in[1];
    const float* img_cos = (const float*)d_in[2];
    const float* img_sin = (const float*)d_in[3];
    const float* txt_cos = (const float*)d_in[4];
    const float* txt_sin = (const float*)d_in[5];

    const float *W[8];   // 0=Wq 1=Wk 2=Wv 3=Waq 4=Wak 5=Wav 6=Wo 7=Wao
    const float *bq, *bk, *bv, *baq, *bak, *bav, *bo, *bao;
    if (in_sizes[7] == DIM) {
        W[0] = (const float*)d_in[6];  bq  = (const float*)d_in[7];
        W[1] = (const float*)d_in[8];  bk  = (const float*)d_in[9];
        W[2] = (const float*)d_in[10]; bv  = (const float*)d_in[11];
        W[3] = (const float*)d_in[12]; baq = (const float*)d_in[13];
        W[4] = (const float*)d_in[14]; bak = (const float*)d_in[15];
        W[5] = (const float*)d_in[16]; bav = (const float*)d_in[17];
        W[6] = (const float*)d_in[18]; bo  = (const float*)d_in[19];
        W[7] = (const float*)d_in[20]; bao = (const float*)d_in[21];
    } else {
        for (int i = 0; i < 8; i++) W[i] = (const float*)d_in[6 + i];
        bq  = (const float*)d_in[14]; bk  = (const float*)d_in[15];
        bv  = (const float*)d_in[16]; baq = (const float*)d_in[17];
        bak = (const float*)d_in[18]; bav = (const float*)d_in[19];
        bo  = (const float*)d_in[20]; bao = (const float*)d_in[21];
    }
    const float* nq_w  = (const float*)d_in[22];
    const float* nk_w  = (const float*)d_in[23];
    const float* naq_w = (const float*)d_in[24];
    const float* nak_w = (const float*)d_in[25];

    constexpr int SMEMB = 2 * BUFB;   // 81920

    static float *q, *k, *v, *attn, *scores;
    static __nv_bfloat16 *xhi, *xlo, *whi, *wlo, *qhi, *qlo, *khi, *klo;
    static __nv_bfloat16 *vthi, *vtlo, *phi, *plo, *ahi, *alo;
    static bool inited = false;
    if (!inited) {
        cudaGetSymbolAddress((void**)&q,      g_q);
        cudaGetSymbolAddress((void**)&k,      g_k);
        cudaGetSymbolAddress((void**)&v,      g_v);
        cudaGetSymbolAddress((void**)&attn,   g_attn);
        cudaGetSymbolAddress((void**)&scores, g_scores);
        cudaGetSymbolAddress((void**)&xhi,  g_xhi);  cudaGetSymbolAddress((void**)&xlo,  g_xlo);
        cudaGetSymbolAddress((void**)&whi,  g_whi);  cudaGetSymbolAddress((void**)&wlo,  g_wlo);
        cudaGetSymbolAddress((void**)&qhi,  g_qhi);  cudaGetSymbolAddress((void**)&qlo,  g_qlo);
        cudaGetSymbolAddress((void**)&khi,  g_khi);  cudaGetSymbolAddress((void**)&klo,  g_klo);
        cudaGetSymbolAddress((void**)&vthi, g_vthi); cudaGetSymbolAddress((void**)&vtlo, g_vtlo);
        cudaGetSymbolAddress((void**)&phi,  g_phi);  cudaGetSymbolAddress((void**)&plo,  g_plo);
        cudaGetSymbolAddress((void**)&ahi,  g_ahi);  cudaGetSymbolAddress((void**)&alo,  g_alo);
        cudaFuncSetAttribute(mma_gemm, cudaFuncAttributeMaxDynamicSharedMemorySize, SMEMB);
        inited = true;
    }

    // 1. split inputs and weights to bf16 hi/lo
    split_x_kernel<<<(S_TOT * DIM) / 1024, 256>>>(hidden, enc, xhi, xlo);
    for (int wdx = 0; wdx < 8; wdx++)
        split_plain<<<(int)(WSZ / 1024), 256>>>(W[wdx], whi + wdx * WSZ, wlo + wdx * WSZ);

    // 2. fused QKV projections (txt rows m<512 take the encoder weights)
    const dim3 gP(DIM / 128, S_TOT / 128, 1);
    mma_gemm<<<gP, 256, SMEMB>>>(xhi, xlo, DIM, 0,
        whi + 0 * WSZ, wlo + 0 * WSZ, whi + 3 * WSZ, wlo + 3 * WSZ, DIM, 0,
        q, DIM, 0, DIM, bq, baq, 1.0f, 0);
    mma_gemm<<<gP, 256, SMEMB>>>(xhi, xlo, DIM, 0,
        whi + 1 * WSZ, wlo + 1 * WSZ, whi + 4 * WSZ, wlo + 4 * WSZ, DIM, 0,
        k, DIM, 0, DIM, bk, bak, 1.0f, 0);
    mma_gemm<<<gP, 256, SMEMB>>>(xhi, xlo, DIM, 0,
        whi + 2 * WSZ, wlo + 2 * WSZ, whi + 5 * WSZ, wlo + 5 * WSZ, DIM, 0,
        v, DIM, 0, DIM, bv, bav, 1.0f, 0);

    // 3. RMSNorm + RoPE + split on q, k;  transpose + split v
    const dim3 gNR(S_TOT, HEADS);
    norm_rope_split<<<gNR, 128>>>(q, qhi, qlo, naq_w, nq_w, txt_cos, txt_sin, img_cos, img_sin);
    norm_rope_split<<<gNR, 128>>>(k, khi, klo, nak_w, nk_w, txt_cos, txt_sin, img_cos, img_sin);
    vtrans_split<<<dim3(DIM / 32, S_TOT / 32), dim3(32, 8)>>>(v, vthi, vtlo);

    // 4. scores = QK^T / sqrt(HD) per head
    mma_gemm<<<dim3(S_TOT / 128, S_TOT / 128, HEADS), 256, SMEMB>>>(
        qhi, qlo, DIM, HD,
        khi, klo, khi, klo, DIM, HD,
        scores, S_TOT, (long long)S_TOT * S_TOT,
        HD, nullptr, nullptr, 0.08838834764831845f, 0);

    // 5. softmax + split
    softmax_split<<<HEADS * S_TOT, 256>>>(scores, phi, plo);

    // 6. attn = P @ V  (B = V^T per head, K-major)
    mma_gemm<<<dim3(1, S_TOT / 128, HEADS), 256, SMEMB>>>(
        phi, plo, S_TOT, (long long)S_TOT * S_TOT,
        vthi, vtlo, vthi, vtlo, S_TOT, (long long)HD * S_TOT,
        attn, DIM, HD, S_TOT, nullptr, nullptr, 1.0f, 0);

    // 7. output projection (txt rows -> Wao/bao, remapped after img block)
    split_plain<<<(S_TOT * DIM) / 1024, 256>>>(attn, ahi, alo);
    mma_gemm<<<gP, 256, SMEMB>>>(ahi, alo, DIM, 0,
        whi + 6 * WSZ, wlo + 6 * WSZ, whi + 7 * WSZ, wlo + 7 * WSZ, DIM, 0,
        (float*)d_out, DIM, 0, DIM, bo, bao, 1.0f, 1);
}

// round 5
// speedup vs baseline: 3.1458x; 1.1784x over previous
#include <cuda_runtime.h>
#include <cuda_bf16.h>
#include <cstdint>
#include <math.h>

#define HEADS 24
#define HD    128
#define DIM   3072
#define S_IMG 2048
#define S_TXT 512
#define S_TOT 2560
#define WSZ   ((size_t)DIM * DIM)

// ---------------- scratch (static device memory; no allocations) ------------
__device__ float g_q[(size_t)S_TOT * DIM];
__device__ float g_k[(size_t)S_TOT * DIM];
__device__ float g_v[(size_t)S_TOT * DIM];

__device__ __nv_bfloat16 g_xhi[(size_t)S_TOT * DIM], g_xlo[(size_t)S_TOT * DIM];
__device__ __nv_bfloat16 g_whi[8 * WSZ], g_wlo[8 * WSZ];
__device__ __nv_bfloat16 g_qhi[(size_t)S_TOT * DIM], g_qlo[(size_t)S_TOT * DIM];
__device__ __nv_bfloat16 g_khi[(size_t)S_TOT * DIM], g_klo[(size_t)S_TOT * DIM];
__device__ __nv_bfloat16 g_vthi[(size_t)HEADS * HD * S_TOT], g_vtlo[(size_t)HEADS * HD * S_TOT];
__device__ __nv_bfloat16 g_ahi[(size_t)S_TOT * DIM], g_alo[(size_t)S_TOT * DIM];

// ---------------- helpers ----------------------------------------------------
__device__ __forceinline__ uint32_t smem_u32(const void* p) {
    return (uint32_t)__cvta_generic_to_shared(p);
}

__device__ __forceinline__ void cp16(uint32_t dst, const void* src) {
    asm volatile("cp.async.cg.shared.global [%0], [%1], 16;" :: "r"(dst), "l"(src));
}

__device__ __forceinline__ void ldm_x4(uint32_t* r, uint32_t addr) {
    asm volatile("ldmatrix.sync.aligned.m8n8.x4.shared.b16 {%0,%1,%2,%3}, [%4];"
                 : "=r"(r[0]), "=r"(r[1]), "=r"(r[2]), "=r"(r[3]) : "r"(addr));
}

__device__ __forceinline__ void mma16816(float* c, const uint32_t* a, uint32_t b0, uint32_t b1) {
    asm volatile(
        "mma.sync.aligned.m16n8k16.row.col.f32.bf16.bf16.f32 "
        "{%0,%1,%2,%3}, {%4,%5,%6,%7}, {%8,%9}, {%0,%1,%2,%3};"
        : "+f"(c[0]), "+f"(c[1]), "+f"(c[2]), "+f"(c[3])
        : "r"(a[0]), "r"(a[1]), "r"(a[2]), "r"(a[3]), "r"(b0), "r"(b1));
}

// pack (a,b) into bf16x2 hi fragment and residual lo fragment
__device__ __forceinline__ void packhl(float a, float b, uint32_t& hi, uint32_t& lo) {
    __nv_bfloat16 ah = __float2bfloat16(a), bh = __float2bfloat16(b);
    __nv_bfloat162 H; H.x = ah; H.y = bh;
    hi = *reinterpret_cast<uint32_t*>(&H);
    __nv_bfloat162 L;
    L.x = __float2bfloat16(a - __bfloat162float(ah));
    L.y = __float2bfloat16(b - __bfloat162float(bh));
    lo = *reinterpret_cast<uint32_t*>(&L);
}

// ---------------- split-bf16 projection GEMM (256x128 tile) ------------------
// C[m,n] = sum_k A[m,k]*B[n,k] + bias[n].  A,B as hi/lo bf16; K = DIM fixed.
// Rows m < S_TXT take (B2, bias2). remap=1 relocates output rows (img first).
#define GTA 20480              /* 256 rows * 80 B */
#define GTB 10240              /* 128 rows * 80 B */
#define GBUF (2 * GTA + 2 * GTB)
#define GSM  (2 * GBUF)        /* 122880 */
__global__ __launch_bounds__(256) void mma_gemm(
    const __nv_bfloat16* __restrict__ Ahi, const __nv_bfloat16* __restrict__ Alo,
    const __nv_bfloat16* __restrict__ Bhi, const __nv_bfloat16* __restrict__ Blo,
    const __nv_bfloat16* __restrict__ B2hi, const __nv_bfloat16* __restrict__ B2lo,
    float* __restrict__ C,
    const float* __restrict__ bias, const float* __restrict__ bias2, int remap)
{
    extern __shared__ char smem[];
    const uint32_t sb = smem_u32(smem);
    const int tid = threadIdx.x;
    const int wid = tid >> 5;
    const int lane = tid & 31;
    const int wm = wid & 3;           // 4 warps x 64 rows
    const int wn = wid >> 2;          // 2 warps x 64 cols

    const int m0 = blockIdx.y * 256;
    const int n0 = blockIdx.x * 128;
    const bool alt = (m0 < S_TXT);
    const __nv_bfloat16* bh = alt ? B2hi : Bhi;
    const __nv_bfloat16* bl = alt ? B2lo : Blo;

    float acc[4][8][4];
    #pragma unroll
    for (int mi = 0; mi < 4; mi++)
        #pragma unroll
        for (int ni = 0; ni < 8; ni++)
            #pragma unroll
            for (int j = 0; j < 4; j++) acc[mi][ni][j] = 0.f;

    auto issue = [&](int c) {
        const uint32_t base = sb + (uint32_t)((c & 1) * GBUF);
        const int k0 = c * 32;
        #pragma unroll
        for (int i = 0; i < 12; i++) {
            const int idx = i * 256 + tid;
            if (idx < 2048) {                         // A tiles (hi, lo)
                const int arr = idx >> 10, rem = idx & 1023;
                const int r = rem >> 2, s4 = rem & 3;
                const __nv_bfloat16* s = arr ? Alo : Ahi;
                cp16(base + (uint32_t)(arr * GTA + r * 80 + s4 * 16),
                     s + (long long)(m0 + r) * DIM + k0 + s4 * 8);
            } else {                                  // B tiles (hi, lo)
                const int idx2 = idx - 2048;
                const int arr = idx2 >> 9, rem = idx2 & 511;
                const int r = rem >> 2, s4 = rem & 3;
                const __nv_bfloat16* s = arr ? bl : bh;
                cp16(base + (uint32_t)(2 * GTA + arr * GTB + r * 80 + s4 * 16),
                     s + (long long)(n0 + r) * DIM + k0 + s4 * 8);
            }
        }
    };

    const int nc = DIM / 32;   // 96
    issue(0);
    asm volatile("cp.async.commit_group;" ::: "memory");

    for (int c = 0; c < nc; c++) {
        if (c + 1 < nc) issue(c + 1);
        asm volatile("cp.async.commit_group;" ::: "memory");
        asm volatile("cp.async.wait_group 1;" ::: "memory");
        __syncthreads();

        const uint32_t base = sb + (uint32_t)((c & 1) * GBUF);
        const uint32_t aH = base, aL = base + GTA;
        const uint32_t bH = base + 2 * GTA, bL = base + 2 * GTA + GTB;

        #pragma unroll
        for (int ks = 0; ks < 2; ks++) {
            uint32_t ah4[4][4], al4[4][4];
            const uint32_t arow = (uint32_t)(wm * 64 + (lane & 15));
            const uint32_t akof = (uint32_t)((ks * 2 + (lane >> 4)) * 16);
            #pragma unroll
            for (int mi = 0; mi < 4; mi++) {
                const uint32_t aoff = (arow + mi * 16) * 80 + akof;
                ldm_x4(ah4[mi], aH + aoff);
                ldm_x4(al4[mi], aL + aoff);
            }
            const uint32_t bn = (uint32_t)(wn * 64 + ((lane >> 4) << 3) + (lane & 7));
            const uint32_t bkof = (uint32_t)((ks * 2 + ((lane >> 3) & 1)) * 16);
            #pragma unroll
            for (int njp = 0; njp < 4; njp++) {
                uint32_t bh4[4], bl4[4];
                const uint32_t boff = (bn + njp * 16) * 80 + bkof;
                ldm_x4(bh4, bH + boff);
                ldm_x4(bl4, bL + boff);
                #pragma unroll
                for (int sub = 0; sub < 2; sub++) {
                    const int ni = njp * 2 + sub;
                    #pragma unroll
                    for (int mi = 0; mi < 4; mi++) {
                        mma16816(acc[mi][ni], ah4[mi], bh4[sub * 2], bh4[sub * 2 + 1]);
                        mma16816(acc[mi][ni], ah4[mi], bl4[sub * 2], bl4[sub * 2 + 1]);
                        mma16816(acc[mi][ni], al4[mi], bh4[sub * 2], bh4[sub * 2 + 1]);
                    }
                }
            }
        }
        __syncthreads();
    }

    const float* bp = alt ? bias2 : bias;
    #pragma unroll
    for (int mi = 0; mi < 4; mi++) {
        const int rb = m0 + wm * 64 + mi * 16 + (lane >> 2);
        #pragma unroll
        for (int half = 0; half < 2; half++) {
            const int r = rb + half * 8;
            long long orow = r;
            if (remap) orow = (r < S_TXT) ? (long long)(S_IMG + r) : (long long)(r - S_TXT);
            float* crow = C + orow * DIM;
            #pragma unroll
            for (int ni = 0; ni < 8; ni++) {
                const int col = n0 + wn * 64 + ni * 8 + (lane & 3) * 2;
                float2 o;
                o.x = acc[mi][ni][half * 2 + 0] + bp[col];
                o.y = acc[mi][ni][half * 2 + 1] + bp[col + 1];
                *reinterpret_cast<float2*>(crow + col) = o;
            }
        }
    }
}

// ---------------- flash attention (fused scores+softmax+PV) ------------------
// grid (S_TOT/128, HEADS); 8 warps, each owns 16 Q rows.  Q frags in regs,
// K/V chunks streamed through a 4-slot cp.async ring (slot = hi+lo chunk pair),
// online softmax, P converted to bf16 hi/lo frags in regs, fp32 O accum,
// output written directly as hi/lo bf16 split.
#define FB    20480            /* ring slot: 10240 hi + 10240 lo */
#define FRING (4 * FB)         /* 81920 */
#define NBLK  (S_TOT / 128)    /* 20 */
#define NITEM (NBLK * 8)       /* 160: per block 4 K-chunk items + 4 V-chunk items */
__global__ __launch_bounds__(256) void flash_attn(
    const __nv_bfloat16* __restrict__ qhi, const __nv_bfloat16* __restrict__ qlo,
    const __nv_bfloat16* __restrict__ khi, const __nv_bfloat16* __restrict__ klo,
    const __nv_bfloat16* __restrict__ vthi, const __nv_bfloat16* __restrict__ vtlo,
    __nv_bfloat16* __restrict__ ahi, __nv_bfloat16* __restrict__ alo)
{
    extern __shared__ char smem[];
    const uint32_t sb = smem_u32(smem);
    const int tid = threadIdx.x, wid = tid >> 5, lane = tid & 31;
    const int qm0 = blockIdx.x * 128;
    const int h = blockIdx.y;

    // ---- Q fragments (hi/lo) into registers, staged through smem ----------
    uint32_t qh[8][4], ql[8][4];
    #pragma unroll
    for (int pass = 0; pass < 2; pass++) {
        const __nv_bfloat16* src = pass ? qlo : qhi;
        #pragma unroll
        for (int i = 0; i < 8; i++) {
            const int idx = i * 256 + tid;               // 0..2047
            const int r = idx >> 4, seg = idx & 15;
            cp16(sb + (uint32_t)((seg >> 2) * 10240 + r * 80 + (seg & 3) * 16),
                 src + (long long)(qm0 + r) * DIM + h * HD + seg * 8);
        }
        asm volatile("cp.async.commit_group;" ::: "memory");
        asm volatile("cp.async.wait_group 0;" ::: "memory");
        __syncthreads();
        #pragma unroll
        for (int j = 0; j < 8; j++) {
            const uint32_t addr = sb + (uint32_t)((j >> 1) * 10240
                + (wid * 16 + (lane & 15)) * 80 + ((j & 1) * 2 + (lane >> 4)) * 16);
            if (pass == 0) ldm_x4(qh[j], addr);
            else           ldm_x4(ql[j], addr);
        }
        __syncthreads();
    }

    float oacc[16][4];
    #pragma unroll
    for (int di = 0; di < 16; di++)
        #pragma unroll
        for (int j = 0; j < 4; j++) oacc[di][j] = 0.f;
    float sacc[16][4];
    uint32_t ph[8][4], pl[8][4];
    float m0r = -1e30f, m1r = -1e30f, l0 = 0.f, l1 = 0.f;

    auto issue_item = [&](int j) {
        const int t = j >> 3, sub = j & 7, pc = sub & 3;
        const uint32_t slot = sb + (uint32_t)((j & 3) * FB);
        if ((sub >> 2) == 0) {            // K chunk pc of s-block t
            #pragma unroll
            for (int i = 0; i < 2; i++) {
                const int idx = i * 256 + tid;
                const int r = idx >> 2, s4 = idx & 3;
                const long long g = (long long)(t * 128 + r) * DIM + h * HD + pc * 32 + s4 * 8;
                cp16(slot + (uint32_t)(r * 80 + s4 * 16), khi + g);
                cp16(slot + (uint32_t)(10240 + r * 80 + s4 * 16), klo + g);
            }
        } else {                          // V^T chunk pc of s-block t
            #pragma unroll
            for (int i = 0; i < 2; i++) {
                const int idx = i * 256 + tid;
                const int r = idx >> 2, s4 = idx & 3;
                const long long g = (long long)(h * 128 + r) * S_TOT + t * 128 + pc * 32 + s4 * 8;
                cp16(slot + (uint32_t)(r * 80 + s4 * 16), vthi + g);
                cp16(slot + (uint32_t)(10240 + r * 80 + s4 * 16), vtlo + g);
            }
        }
    };

    // prologue: 3 items in flight
    issue_item(0); asm volatile("cp.async.commit_group;" ::: "memory");
    issue_item(1); asm volatile("cp.async.commit_group;" ::: "memory");
    issue_item(2); asm volatile("cp.async.commit_group;" ::: "memory");

    const uint32_t bnrow = (uint32_t)(((lane >> 4) << 3) + (lane & 7));
    const uint32_t bksel = (uint32_t)((lane >> 3) & 1);

    for (int j = 0; j < NITEM; j++) {
        if (j + 3 < NITEM) issue_item(j + 3);
        asm volatile("cp.async.commit_group;" ::: "memory");
        asm volatile("cp.async.wait_group 3;" ::: "memory");
        __syncthreads();

        const int sub = j & 7, phase = sub >> 2, c = sub & 3;
        const uint32_t slot = sb + (uint32_t)((j & 3) * FB);

        if (phase == 0) {
            if (c == 0) {
                #pragma unroll
                for (int ni = 0; ni < 16; ni++)
                    #pragma unroll
                    for (int jj = 0; jj < 4; jj++) sacc[ni][jj] = 0.f;
            }
            #pragma unroll
            for (int ks2 = 0; ks2 < 2; ks2++) {
                const int j8 = c * 2 + ks2;
                const uint32_t kof = (uint32_t)((ks2 * 2 + bksel) * 16);
                #pragma unroll
                for (int njp = 0; njp < 8; njp++) {
                    uint32_t bh4[4], bl4[4];
                    const uint32_t boff = (njp * 16 + bnrow) * 80 + kof;
                    ldm_x4(bh4, slot + boff);
                    ldm_x4(bl4, slot + 10240 + boff);
                    #pragma unroll
                    for (int s2 = 0; s2 < 2; s2++) {
                        const int ni = njp * 2 + s2;
                        mma16816(sacc[ni], qh[j8], bh4[s2 * 2], bh4[s2 * 2 + 1]);
                        mma16816(sacc[ni], qh[j8], bl4[s2 * 2], bl4[s2 * 2 + 1]);
                        mma16816(sacc[ni], ql[j8], bh4[s2 * 2], bh4[s2 * 2 + 1]);
                    }
                }
            }
            if (c == 3) {
                // ---- online softmax over this 128-col S block --------------
                const float sc = 0.08838834764831845f;
                float mb0 = -1e30f, mb1 = -1e30f;
                #pragma unroll
                for (int ni = 0; ni < 16; ni++) {
                    sacc[ni][0] *= sc; sacc[ni][1] *= sc;
                    sacc[ni][2] *= sc; sacc[ni][3] *= sc;
                    mb0 = fmaxf(mb0, fmaxf(sacc[ni][0], sacc[ni][1]));
                    mb1 = fmaxf(mb1, fmaxf(sacc[ni][2], sacc[ni][3]));
                }
                mb0 = fmaxf(mb0, __shfl_xor_sync(0xffffffffu, mb0, 1));
                mb0 = fmaxf(mb0, __shfl_xor_sync(0xffffffffu, mb0, 2));
                mb1 = fmaxf(mb1, __shfl_xor_sync(0xffffffffu, mb1, 1));
                mb1 = fmaxf(mb1, __shfl_xor_sync(0xffffffffu, mb1, 2));
                const float mn0 = fmaxf(m0r, mb0), mn1 = fmaxf(m1r, mb1);
                const float a0 = __expf(m0r - mn0), a1 = __expf(m1r - mn1);
                m0r = mn0; m1r = mn1;
                l0 *= a0; l1 *= a1;
                #pragma unroll
                for (int di = 0; di < 16; di++) {
                    oacc[di][0] *= a0; oacc[di][1] *= a0;
                    oacc[di][2] *= a1; oacc[di][3] *= a1;
                }
                float rs0 = 0.f, rs1 = 0.f;
                #pragma unroll
                for (int ni = 0; ni < 16; ni++) {
                    const float p0 = __expf(sacc[ni][0] - mn0);
                    const float p1 = __expf(sacc[ni][1] - mn0);
                    const float p2 = __expf(sacc[ni][2] - mn1);
                    const float p3 = __expf(sacc[ni][3] - mn1);
                    rs0 += p0 + p1; rs1 += p2 + p3;
                    const int j8 = ni >> 1;
                    if ((ni & 1) == 0) {
                        packhl(p0, p1, ph[j8][0], pl[j8][0]);
                        packhl(p2, p3, ph[j8][1], pl[j8][1]);
                    } else {
                        packhl(p0, p1, ph[j8][2], pl[j8][2]);
                        packhl(p2, p3, ph[j8][3], pl[j8][3]);
                    }
                }
                l0 += rs0; l1 += rs1;
            }
        } else {
            // ---- O += P * V  (k = s-local of chunk c) ----------------------
            #pragma unroll
            for (int ks2 = 0; ks2 < 2; ks2++) {
                const int j8 = c * 2 + ks2;
                const uint32_t kof = (uint32_t)((ks2 * 2 + bksel) * 16);
                #pragma unroll
                for (int djp = 0; djp < 8; djp++) {
                    uint32_t bh4[4], bl4[4];
                    const uint32_t boff = (djp * 16 + bnrow) * 80 + kof;
                    ldm_x4(bh4, slot + boff);
                    ldm_x4(bl4, slot + 10240 + boff);
                    #pragma unroll
                    for (int s2 = 0; s2 < 2; s2++) {
                        const int di = djp * 2 + s2;
                        mma16816(oacc[di], ph[j8], bh4[s2 * 2], bh4[s2 * 2 + 1]);
                        mma16816(oacc[di], ph[j8], bl4[s2 * 2], bl4[s2 * 2 + 1]);
                        mma16816(oacc[di], pl[j8], bh4[s2 * 2], bh4[s2 * 2 + 1]);
                    }
                }
            }
        }
        __syncthreads();
    }

    // ---- normalize and store hi/lo split -----------------------------------
    l0 += __shfl_xor_sync(0xffffffffu, l0, 1);
    l0 += __shfl_xor_sync(0xffffffffu, l0, 2);
    l1 += __shfl_xor_sync(0xffffffffu, l1, 1);
    l1 += __shfl_xor_sync(0xffffffffu, l1, 2);
    const float i0 = 1.0f / l0, i1 = 1.0f / l1;
    const int r0 = qm0 + wid * 16 + (lane >> 2);
    const int r1 = r0 + 8;
    #pragma unroll
    for (int di = 0; di < 16; di++) {
        const int col = h * HD + di * 8 + (lane & 3) * 2;
        uint32_t hi32, lo32;
        packhl(oacc[di][0] * i0, oacc[di][1] * i0, hi32, lo32);
        *reinterpret_cast<uint32_t*>(ahi + (long long)r0 * DIM + col) = hi32;
        *reinterpret_cast<uint32_t*>(alo + (long long)r0 * DIM + col) = lo32;
        packhl(oacc[di][2] * i1, oacc[di][3] * i1, hi32, lo32);
        *reinterpret_cast<uint32_t*>(ahi + (long long)r1 * DIM + col) = hi32;
        *reinterpret_cast<uint32_t*>(alo + (long long)r1 * DIM + col) = lo32;
    }
}

// ---------------- split helpers ----------------------------------------------
__device__ __forceinline__ void split4(float4 v, __nv_bfloat16* hi, __nv_bfloat16* lo,
                                       long long idx) {
    __nv_bfloat16 h0 = __float2bfloat16(v.x), h1 = __float2bfloat16(v.y);
    __nv_bfloat16 h2 = __float2bfloat16(v.z), h3 = __float2bfloat16(v.w);
    __nv_bfloat162 a; a.x = h0; a.y = h1;
    __nv_bfloat162 b; b.x = h2; b.y = h3;
    *reinterpret_cast<__nv_bfloat162*>(hi + idx)     = a;
    *reinterpret_cast<__nv_bfloat162*>(hi + idx + 2) = b;
    __nv_bfloat162 c; c.x = __float2bfloat16(v.x - __bfloat162float(h0));
                      c.y = __float2bfloat16(v.y - __bfloat162float(h1));
    __nv_bfloat162 d; d.x = __float2bfloat16(v.z - __bfloat162float(h2));
                      d.y = __float2bfloat16(v.w - __bfloat162float(h3));
    *reinterpret_cast<__nv_bfloat162*>(lo + idx)     = c;
    *reinterpret_cast<__nv_bfloat162*>(lo + idx + 2) = d;
}

__global__ void split_x_kernel(const float* __restrict__ hidden, const float* __restrict__ enc,
                               __nv_bfloat16* __restrict__ hi, __nv_bfloat16* __restrict__ lo) {
    const long long i4 = ((long long)blockIdx.x * 256 + threadIdx.x) * 4;
    const long long row = i4 / DIM;
    const float* src = (row < S_TXT) ? (enc + i4) : (hidden + i4 - (long long)S_TXT * DIM);
    split4(*reinterpret_cast<const float4*>(src), hi, lo, i4);
}

__global__ void split_plain(const float* __restrict__ src,
                            __nv_bfloat16* __restrict__ hi, __nv_bfloat16* __restrict__ lo) {
    const long long i4 = ((long long)blockIdx.x * 256 + threadIdx.x) * 4;
    split4(*reinterpret_cast<const float4*>(src + i4), hi, lo, i4);
}

// ---------------- RMSNorm + RoPE + split -------------------------------------
__global__ void norm_rope_split(
    const float* __restrict__ x,
    __nv_bfloat16* __restrict__ hi, __nv_bfloat16* __restrict__ lo,
    const float* __restrict__ w_txt, const float* __restrict__ w_img,
    const float* __restrict__ txt_cos, const float* __restrict__ txt_sin,
    const float* __restrict__ img_cos, const float* __restrict__ img_sin)
{
    const int s = blockIdx.x;
    const int h = blockIdx.y;
    const int d = threadIdx.x;
    const long long off = (long long)s * DIM + h * HD;

    float v = x[off + d];
    float ss = v * v;
    #pragma unroll
    for (int o = 16; o > 0; o >>= 1) ss += __shfl_xor_sync(0xffffffffu, ss, o);
    __shared__ float wsum[4];
    if ((d & 31) == 0) wsum[d >> 5] = ss;
    __syncthreads();
    const float tot = wsum[0] + wsum[1] + wsum[2] + wsum[3];
    const float r = rsqrtf(tot * (1.0f / HD) + 1e-6f);

    const bool is_txt = (s < S_TXT);
    const float* w = is_txt ? w_txt : w_img;
    const float nv = v * r * w[d];

    const float other = __shfl_xor_sync(0xffffffffu, nv, 1);
    const float rot = (d & 1) ? other : -other;

    const long long srel = is_txt ? s : (s - S_TXT);
    const float cc = (is_txt ? txt_cos : img_cos)[srel * HD + d];
    const float sn = (is_txt ? txt_sin : img_sin)[srel * HD + d];
    const float f = nv * cc + rot * sn;

    __nv_bfloat16 hh = __float2bfloat16(f);
    hi[off + d] = hh;
    lo[off + d] = __float2bfloat16(f - __bfloat162float(hh));
}

// ---------------- V transpose + split:  v[s, DIM] -> vt[head][d][s] ----------
__global__ void vtrans_split(const float* __restrict__ v,
                             __nv_bfloat16* __restrict__ vhi, __nv_bfloat16* __restrict__ vlo)
{
    __shared__ float tile[32][33];
    const int c0 = blockIdx.x * 32;
    const int s0 = blockIdx.y * 32;
    const int tx = threadIdx.x, ty = threadIdx.y;

    #pragma unroll
    for (int r = ty; r < 32; r += 8)
        tile[r][tx] = v[(long long)(s0 + r) * DIM + c0 + tx];
    __syncthreads();
    #pragma unroll
    for (int r = ty; r < 32; r += 8) {
        const int c = c0 + r;
        const int head = c >> 7, d = c & 127;
        const long long o = (long long)head * HD * S_TOT + (long long)d * S_TOT + s0 + tx;
        const float f = tile[tx][r];
        __nv_bfloat16 hh = __float2bfloat16(f);
        vhi[o] = hh;
        vlo[o] = __float2bfloat16(f - __bfloat162float(hh));
    }
}

// ---------------- launch -----------------------------------------------------
extern "C" void kernel_launch(void* const* d_in, const int* in_sizes, int n_in,
                              void* d_out, int out_size)
{
    const float* hidden  = (const float*)d_in[0];
    const float* enc     = (const float*)d_in[1];
    const float* img_cos = (const float*)d_in[2];
    const float* img_sin = (const float*)d_in[3];
    const float* txt_cos = (const float*)d_in[4];
    const float* txt_sin = (const float*)d_in[5];

    const float *W[8];   // 0=Wq 1=Wk 2=Wv 3=Waq 4=Wak 5=Wav 6=Wo 7=Wao
    const float *bq, *bk, *bv, *baq, *bak, *bav, *bo, *bao;
    if (in_sizes[7] == DIM) {
        W[0] = (const float*)d_in[6];  bq  = (const float*)d_in[7];
        W[1] = (const float*)d_in[8];  bk  = (const float*)d_in[9];
        W[2] = (const float*)d_in[10]; bv  = (const float*)d_in[11];
        W[3] = (const float*)d_in[12]; baq = (const float*)d_in[13];
        W[4] = (const float*)d_in[14]; bak = (const float*)d_in[15];
        W[5] = (const float*)d_in[16]; bav = (const float*)d_in[17];
        W[6] = (const float*)d_in[18]; bo  = (const float*)d_in[19];
        W[7] = (const float*)d_in[20]; bao = (const float*)d_in[21];
    } else {
        for (int i = 0; i < 8; i++) W[i] = (const float*)d_in[6 + i];
        bq  = (const float*)d_in[14]; bk  = (const float*)d_in[15];
        bv  = (const float*)d_in[16]; baq = (const float*)d_in[17];
        bak = (const float*)d_in[18]; bav = (const float*)d_in[19];
        bo  = (const float*)d_in[20]; bao = (const float*)d_in[21];
    }
    const float* nq_w  = (const float*)d_in[22];
    const float* nk_w  = (const float*)d_in[23];
    const float* naq_w = (const float*)d_in[24];
    const float* nak_w = (const float*)d_in[25];

    static float *q, *k, *v;
    static __nv_bfloat16 *xhi, *xlo, *whi, *wlo, *qhi, *qlo, *khi, *klo;
    static __nv_bfloat16 *vthi, *vtlo, *ahi, *alo;
    static bool inited = false;
    if (!inited) {
        cudaGetSymbolAddress((void**)&q,    g_q);
        cudaGetSymbolAddress((void**)&k,    g_k);
        cudaGetSymbolAddress((void**)&v,    g_v);
        cudaGetSymbolAddress((void**)&xhi,  g_xhi);  cudaGetSymbolAddress((void**)&xlo,  g_xlo);
        cudaGetSymbolAddress((void**)&whi,  g_whi);  cudaGetSymbolAddress((void**)&wlo,  g_wlo);
        cudaGetSymbolAddress((void**)&qhi,  g_qhi);  cudaGetSymbolAddress((void**)&qlo,  g_qlo);
        cudaGetSymbolAddress((void**)&khi,  g_khi);  cudaGetSymbolAddress((void**)&klo,  g_klo);
        cudaGetSymbolAddress((void**)&vthi, g_vthi); cudaGetSymbolAddress((void**)&vtlo, g_vtlo);
        cudaGetSymbolAddress((void**)&ahi,  g_ahi);  cudaGetSymbolAddress((void**)&alo,  g_alo);
        cudaFuncSetAttribute(mma_gemm, cudaFuncAttributeMaxDynamicSharedMemorySize, GSM);
        cudaFuncSetAttribute(flash_attn, cudaFuncAttributeMaxDynamicSharedMemorySize, FRING);
        inited = true;
    }

    // 1. split inputs and weights to bf16 hi/lo
    split_x_kernel<<<(S_TOT * DIM) / 1024, 256>>>(hidden, enc, xhi, xlo);
    for (int wdx = 0; wdx < 8; wdx++)
        split_plain<<<(int)(WSZ / 1024), 256>>>(W[wdx], whi + wdx * WSZ, wlo + wdx * WSZ);

    // 2. fused QKV projections (rows m<512 take the encoder weights)
    const dim3 gP(DIM / 128, S_TOT / 256, 1);   // (24, 10)
    mma_gemm<<<gP, 256, GSM>>>(xhi, xlo,
        whi + 0 * WSZ, wlo + 0 * WSZ, whi + 3 * WSZ, wlo + 3 * WSZ, q, bq, baq, 0);
    mma_gemm<<<gP, 256, GSM>>>(xhi, xlo,
        whi + 1 * WSZ, wlo + 1 * WSZ, whi + 4 * WSZ, wlo + 4 * WSZ, k, bk, bak, 0);
    mma_gemm<<<gP, 256, GSM>>>(xhi, xlo,
        whi + 2 * WSZ, wlo + 2 * WSZ, whi + 5 * WSZ, wlo + 5 * WSZ, v, bv, bav, 0);

    // 3. RMSNorm + RoPE + split on q, k;  transpose + split v
    const dim3 gNR(S_TOT, HEADS);
    norm_rope_split<<<gNR, 128>>>(q, qhi, qlo, naq_w, nq_w, txt_cos, txt_sin, img_cos, img_sin);
    norm_rope_split<<<gNR, 128>>>(k, khi, klo, nak_w, nk_w, txt_cos, txt_sin, img_cos, img_sin);
    vtrans_split<<<dim3(DIM / 32, S_TOT / 32), dim3(32, 8)>>>(v, vthi, vtlo);

    // 4. fused attention: scores + softmax + PV, writes hi/lo split of attn
    flash_attn<<<dim3(S_TOT / 128, HEADS), 256, FRING>>>(
        qhi, qlo, khi, klo, vthi, vtlo, ahi, alo);

    // 5. output projection (txt rows -> Wao/bao, remapped: img block first)
    mma_gemm<<<gP, 256, GSM>>>(ahi, alo,
        whi + 6 * WSZ, wlo + 6 * WSZ, whi + 7 * WSZ, wlo + 7 * WSZ,
        (float*)d_out, bo, bao, 1);
}

// round 6
// speedup vs baseline: 3.8388x; 1.2203x over previous
#include <cuda_runtime.h>
#include <cuda_bf16.h>
#include <cuda_fp16.h>
#include <cstdint>
#include <math.h>

#define HEADS 24
#define HD    128
#define DIM   3072
#define S_IMG 2048
#define S_TXT 512
#define S_TOT 2560
#define WSZ   ((size_t)DIM * DIM)

// ---------------- scratch (static device memory; no allocations) ------------
__device__ float g_q[(size_t)S_TOT * DIM];
__device__ float g_k[(size_t)S_TOT * DIM];
__device__ float g_v[(size_t)S_TOT * DIM];

__device__ __nv_bfloat16 g_xhi[(size_t)S_TOT * DIM], g_xlo[(size_t)S_TOT * DIM];
__device__ __nv_bfloat16 g_whi[4 * WSZ], g_wlo[4 * WSZ];     // Wq Wk Waq Wak
__device__ __nv_bfloat16 g_qhi[(size_t)S_TOT * DIM], g_qlo[(size_t)S_TOT * DIM];
__device__ __nv_bfloat16 g_khi[(size_t)S_TOT * DIM], g_klo[(size_t)S_TOT * DIM];
__device__ __nv_bfloat16 g_vthi[(size_t)HEADS * HD * S_TOT], g_vtlo[(size_t)HEADS * HD * S_TOT];

__device__ __half g_x16[(size_t)S_TOT * DIM];
__device__ __half g_w16[4 * WSZ];                            // Wv Wav Wo Wao
__device__ __half g_a16[(size_t)S_TOT * DIM];

// ---------------- helpers ----------------------------------------------------
__device__ __forceinline__ uint32_t smem_u32(const void* p) {
    return (uint32_t)__cvta_generic_to_shared(p);
}

__device__ __forceinline__ void cp16(uint32_t dst, const void* src) {
    asm volatile("cp.async.cg.shared.global [%0], [%1], 16;" :: "r"(dst), "l"(src));
}

__device__ __forceinline__ void ldm_x4(uint32_t* r, uint32_t addr) {
    asm volatile("ldmatrix.sync.aligned.m8n8.x4.shared.b16 {%0,%1,%2,%3}, [%4];"
                 : "=r"(r[0]), "=r"(r[1]), "=r"(r[2]), "=r"(r[3]) : "r"(addr));
}

__device__ __forceinline__ void mma16816(float* c, const uint32_t* a, uint32_t b0, uint32_t b1) {
    asm volatile(
        "mma.sync.aligned.m16n8k16.row.col.f32.bf16.bf16.f32 "
        "{%0,%1,%2,%3}, {%4,%5,%6,%7}, {%8,%9}, {%0,%1,%2,%3};"
        : "+f"(c[0]), "+f"(c[1]), "+f"(c[2]), "+f"(c[3])
        : "r"(a[0]), "r"(a[1]), "r"(a[2]), "r"(a[3]), "r"(b0), "r"(b1));
}

__device__ __forceinline__ void mma16816h(float* c, const uint32_t* a, uint32_t b0, uint32_t b1) {
    asm volatile(
        "mma.sync.aligned.m16n8k16.row.col.f32.f16.f16.f32 "
        "{%0,%1,%2,%3}, {%4,%5,%6,%7}, {%8,%9}, {%0,%1,%2,%3};"
        : "+f"(c[0]), "+f"(c[1]), "+f"(c[2]), "+f"(c[3])
        : "r"(a[0]), "r"(a[1]), "r"(a[2]), "r"(a[3]), "r"(b0), "r"(b1));
}

// pack (a,b) into bf16x2 hi fragment and residual lo fragment
__device__ __forceinline__ void packhl(float a, float b, uint32_t& hi, uint32_t& lo) {
    __nv_bfloat16 ah = __float2bfloat16(a), bh = __float2bfloat16(b);
    __nv_bfloat162 H; H.x = ah; H.y = bh;
    hi = *reinterpret_cast<uint32_t*>(&H);
    __nv_bfloat162 L;
    L.x = __float2bfloat16(a - __bfloat162float(ah));
    L.y = __float2bfloat16(b - __bfloat162float(bh));
    lo = *reinterpret_cast<uint32_t*>(&L);
}

// ---------------- split-bf16 projection GEMM (256x128 tile, 3-term) ----------
#define GTA 20480              /* 256 rows * 80 B */
#define GTB 10240              /* 128 rows * 80 B */
#define GBUF (2 * GTA + 2 * GTB)
#define GSM  (2 * GBUF)        /* 122880 */
__global__ __launch_bounds__(256) void mma_gemm(
    const __nv_bfloat16* __restrict__ Ahi, const __nv_bfloat16* __restrict__ Alo,
    const __nv_bfloat16* __restrict__ Bhi, const __nv_bfloat16* __restrict__ Blo,
    const __nv_bfloat16* __restrict__ B2hi, const __nv_bfloat16* __restrict__ B2lo,
    float* __restrict__ C,
    const float* __restrict__ bias, const float* __restrict__ bias2)
{
    extern __shared__ char smem[];
    const uint32_t sb = smem_u32(smem);
    const int tid = threadIdx.x;
    const int wid = tid >> 5;
    const int lane = tid & 31;
    const int wm = wid & 3;           // 4 warps x 64 rows
    const int wn = wid >> 2;          // 2 warps x 64 cols

    const int m0 = blockIdx.y * 256;
    const int n0 = blockIdx.x * 128;
    const bool alt = (m0 < S_TXT);
    const __nv_bfloat16* bh = alt ? B2hi : Bhi;
    const __nv_bfloat16* bl = alt ? B2lo : Blo;

    float acc[4][8][4];
    #pragma unroll
    for (int mi = 0; mi < 4; mi++)
        #pragma unroll
        for (int ni = 0; ni < 8; ni++)
            #pragma unroll
            for (int j = 0; j < 4; j++) acc[mi][ni][j] = 0.f;

    auto issue = [&](int c) {
        const uint32_t base = sb + (uint32_t)((c & 1) * GBUF);
        const int k0 = c * 32;
        #pragma unroll
        for (int i = 0; i < 12; i++) {
            const int idx = i * 256 + tid;
            if (idx < 2048) {                         // A tiles (hi, lo)
                const int arr = idx >> 10, rem = idx & 1023;
                const int r = rem >> 2, s4 = rem & 3;
                const __nv_bfloat16* s = arr ? Alo : Ahi;
                cp16(base + (uint32_t)(arr * GTA + r * 80 + s4 * 16),
                     s + (long long)(m0 + r) * DIM + k0 + s4 * 8);
            } else {                                  // B tiles (hi, lo)
                const int idx2 = idx - 2048;
                const int arr = idx2 >> 9, rem = idx2 & 511;
                const int r = rem >> 2, s4 = rem & 3;
                const __nv_bfloat16* s = arr ? bl : bh;
                cp16(base + (uint32_t)(2 * GTA + arr * GTB + r * 80 + s4 * 16),
                     s + (long long)(n0 + r) * DIM + k0 + s4 * 8);
            }
        }
    };

    const int nc = DIM / 32;   // 96
    issue(0);
    asm volatile("cp.async.commit_group;" ::: "memory");

    for (int c = 0; c < nc; c++) {
        if (c + 1 < nc) issue(c + 1);
        asm volatile("cp.async.commit_group;" ::: "memory");
        asm volatile("cp.async.wait_group 1;" ::: "memory");
        __syncthreads();

        const uint32_t base = sb + (uint32_t)((c & 1) * GBUF);
        const uint32_t aH = base, aL = base + GTA;
        const uint32_t bH = base + 2 * GTA, bL = base + 2 * GTA + GTB;

        #pragma unroll
        for (int ks = 0; ks < 2; ks++) {
            uint32_t ah4[4][4], al4[4][4];
            const uint32_t arow = (uint32_t)(wm * 64 + (lane & 15));
            const uint32_t akof = (uint32_t)((ks * 2 + (lane >> 4)) * 16);
            #pragma unroll
            for (int mi = 0; mi < 4; mi++) {
                const uint32_t aoff = (arow + mi * 16) * 80 + akof;
                ldm_x4(ah4[mi], aH + aoff);
                ldm_x4(al4[mi], aL + aoff);
            }
            const uint32_t bn = (uint32_t)(wn * 64 + ((lane >> 4) << 3) + (lane & 7));
            const uint32_t bkof = (uint32_t)((ks * 2 + ((lane >> 3) & 1)) * 16);
            #pragma unroll
            for (int njp = 0; njp < 4; njp++) {
                uint32_t bh4[4], bl4[4];
                const uint32_t boff = (bn + njp * 16) * 80 + bkof;
                ldm_x4(bh4, bH + boff);
                ldm_x4(bl4, bL + boff);
                #pragma unroll
                for (int sub = 0; sub < 2; sub++) {
                    const int ni = njp * 2 + sub;
                    #pragma unroll
                    for (int mi = 0; mi < 4; mi++) {
                        mma16816(acc[mi][ni], ah4[mi], bh4[sub * 2], bh4[sub * 2 + 1]);
                        mma16816(acc[mi][ni], ah4[mi], bl4[sub * 2], bl4[sub * 2 + 1]);
                        mma16816(acc[mi][ni], al4[mi], bh4[sub * 2], bh4[sub * 2 + 1]);
                    }
                }
            }
        }
        __syncthreads();
    }

    const float* bp = alt ? bias2 : bias;
    #pragma unroll
    for (int mi = 0; mi < 4; mi++) {
        const int rb = m0 + wm * 64 + mi * 16 + (lane >> 2);
        #pragma unroll
        for (int half = 0; half < 2; half++) {
            const int r = rb + half * 8;
            float* crow = C + (long long)r * DIM;
            #pragma unroll
            for (int ni = 0; ni < 8; ni++) {
                const int col = n0 + wn * 64 + ni * 8 + (lane & 3) * 2;
                float2 o;
                o.x = acc[mi][ni][half * 2 + 0] + bp[col];
                o.y = acc[mi][ni][half * 2 + 1] + bp[col + 1];
                *reinterpret_cast<float2*>(crow + col) = o;
            }
        }
    }
}

// ---------------- fp16 single-term GEMM (256x128 tile) -----------------------
// C = A * B^T + bias, fp16 inputs, fp32 accum. Rows m < S_TXT take (B2,bias2).
// remap=1 relocates output rows (img block first).
#define HTA 20480
#define HTB 10240
#define HBUF (HTA + HTB)
#define HSM  (2 * HBUF)        /* 61440 */
__global__ __launch_bounds__(256) void mma_gemm_h(
    const __half* __restrict__ A,
    const __half* __restrict__ B, const __half* __restrict__ B2,
    float* __restrict__ C,
    const float* __restrict__ bias, const float* __restrict__ bias2, int remap)
{
    extern __shared__ char smem[];
    const uint32_t sb = smem_u32(smem);
    const int tid = threadIdx.x;
    const int wid = tid >> 5;
    const int lane = tid & 31;
    const int wm = wid & 3;
    const int wn = wid >> 2;

    const int m0 = blockIdx.y * 256;
    const int n0 = blockIdx.x * 128;
    const bool alt = (m0 < S_TXT);
    const __half* bsrc = alt ? B2 : B;

    float acc[4][8][4];
    #pragma unroll
    for (int mi = 0; mi < 4; mi++)
        #pragma unroll
        for (int ni = 0; ni < 8; ni++)
            #pragma unroll
            for (int j = 0; j < 4; j++) acc[mi][ni][j] = 0.f;

    auto issue = [&](int c) {
        const uint32_t base = sb + (uint32_t)((c & 1) * HBUF);
        const int k0 = c * 32;
        #pragma unroll
        for (int i = 0; i < 6; i++) {
            const int idx = i * 256 + tid;            // 0..1535
            if (idx < 1024) {                         // A tile
                const int r = idx >> 2, s4 = idx & 3;
                cp16(base + (uint32_t)(r * 80 + s4 * 16),
                     A + (long long)(m0 + r) * DIM + k0 + s4 * 8);
            } else {                                  // B tile
                const int idx2 = idx - 1024;
                const int r = idx2 >> 2, s4 = idx2 & 3;
                cp16(base + (uint32_t)(HTA + r * 80 + s4 * 16),
                     bsrc + (long long)(n0 + r) * DIM + k0 + s4 * 8);
            }
        }
    };

    const int nc = DIM / 32;
    issue(0);
    asm volatile("cp.async.commit_group;" ::: "memory");

    for (int c = 0; c < nc; c++) {
        if (c + 1 < nc) issue(c + 1);
        asm volatile("cp.async.commit_group;" ::: "memory");
        asm volatile("cp.async.wait_group 1;" ::: "memory");
        __syncthreads();

        const uint32_t base = sb + (uint32_t)((c & 1) * HBUF);
        const uint32_t aB = base, bB = base + HTA;

        #pragma unroll
        for (int ks = 0; ks < 2; ks++) {
            uint32_t a4[4][4];
            const uint32_t arow = (uint32_t)(wm * 64 + (lane & 15));
            const uint32_t akof = (uint32_t)((ks * 2 + (lane >> 4)) * 16);
            #pragma unroll
            for (int mi = 0; mi < 4; mi++)
                ldm_x4(a4[mi], aB + (arow + mi * 16) * 80 + akof);

            const uint32_t bn = (uint32_t)(wn * 64 + ((lane >> 4) << 3) + (lane & 7));
            const uint32_t bkof = (uint32_t)((ks * 2 + ((lane >> 3) & 1)) * 16);
            #pragma unroll
            for (int njp = 0; njp < 4; njp++) {
                uint32_t b4[4];
                ldm_x4(b4, bB + (bn + njp * 16) * 80 + bkof);
                #pragma unroll
                for (int sub = 0; sub < 2; sub++) {
                    const int ni = njp * 2 + sub;
                    #pragma unroll
                    for (int mi = 0; mi < 4; mi++)
                        mma16816h(acc[mi][ni], a4[mi], b4[sub * 2], b4[sub * 2 + 1]);
                }
            }
        }
        __syncthreads();
    }

    const float* bp = alt ? bias2 : bias;
    #pragma unroll
    for (int mi = 0; mi < 4; mi++) {
        const int rb = m0 + wm * 64 + mi * 16 + (lane >> 2);
        #pragma unroll
        for (int half = 0; half < 2; half++) {
            const int r = rb + half * 8;
            long long orow = r;
            if (remap) orow = (r < S_TXT) ? (long long)(S_IMG + r) : (long long)(r - S_TXT);
            float* crow = C + orow * DIM;
            #pragma unroll
            for (int ni = 0; ni < 8; ni++) {
                const int col = n0 + wn * 64 + ni * 8 + (lane & 3) * 2;
                float2 o;
                o.x = acc[mi][ni][half * 2 + 0] + bp[col];
                o.y = acc[mi][ni][half * 2 + 1] + bp[col + 1];
                *reinterpret_cast<float2*>(crow + col) = o;
            }
        }
    }
}

// ---------------- flash attention (fused scores+softmax+PV) ------------------
#define FB    20480            /* ring slot: 10240 hi + 10240 lo */
#define FRING (4 * FB)         /* 81920 */
#define NBLK  (S_TOT / 128)    /* 20 */
#define NITEM (NBLK * 8)
__global__ __launch_bounds__(256) void flash_attn(
    const __nv_bfloat16* __restrict__ qhi, const __nv_bfloat16* __restrict__ qlo,
    const __nv_bfloat16* __restrict__ khi, const __nv_bfloat16* __restrict__ klo,
    const __nv_bfloat16* __restrict__ vthi, const __nv_bfloat16* __restrict__ vtlo,
    __half* __restrict__ a16)
{
    extern __shared__ char smem[];
    const uint32_t sb = smem_u32(smem);
    const int tid = threadIdx.x, wid = tid >> 5, lane = tid & 31;
    const int qm0 = blockIdx.x * 128;
    const int h = blockIdx.y;

    // ---- Q fragments (hi/lo) into registers, staged through smem ----------
    uint32_t qh[8][4], ql[8][4];
    #pragma unroll
    for (int pass = 0; pass < 2; pass++) {
        const __nv_bfloat16* src = pass ? qlo : qhi;
        #pragma unroll
        for (int i = 0; i < 8; i++) {
            const int idx = i * 256 + tid;
            const int r = idx >> 4, seg = idx & 15;
            cp16(sb + (uint32_t)((seg >> 2) * 10240 + r * 80 + (seg & 3) * 16),
                 src + (long long)(qm0 + r) * DIM + h * HD + seg * 8);
        }
        asm volatile("cp.async.commit_group;" ::: "memory");
        asm volatile("cp.async.wait_group 0;" ::: "memory");
        __syncthreads();
        #pragma unroll
        for (int j = 0; j < 8; j++) {
            const uint32_t addr = sb + (uint32_t)((j >> 1) * 10240
                + (wid * 16 + (lane & 15)) * 80 + ((j & 1) * 2 + (lane >> 4)) * 16);
            if (pass == 0) ldm_x4(qh[j], addr);
            else           ldm_x4(ql[j], addr);
        }
        __syncthreads();
    }

    float oacc[16][4];
    #pragma unroll
    for (int di = 0; di < 16; di++)
        #pragma unroll
        for (int j = 0; j < 4; j++) oacc[di][j] = 0.f;
    float sacc[16][4];
    uint32_t ph[8][4], pl[8][4];
    float m0r = -1e30f, m1r = -1e30f, l0 = 0.f, l1 = 0.f;

    auto issue_item = [&](int j) {
        const int t = j >> 3, sub = j & 7, pc = sub & 3;
        const uint32_t slot = sb + (uint32_t)((j & 3) * FB);
        if ((sub >> 2) == 0) {            // K chunk pc of s-block t
            #pragma unroll
            for (int i = 0; i < 2; i++) {
                const int idx = i * 256 + tid;
                const int r = idx >> 2, s4 = idx & 3;
                const long long g = (long long)(t * 128 + r) * DIM + h * HD + pc * 32 + s4 * 8;
                cp16(slot + (uint32_t)(r * 80 + s4 * 16), khi + g);
                cp16(slot + (uint32_t)(10240 + r * 80 + s4 * 16), klo + g);
            }
        } else {                          // V^T chunk pc of s-block t
            #pragma unroll
            for (int i = 0; i < 2; i++) {
                const int idx = i * 256 + tid;
                const int r = idx >> 2, s4 = idx & 3;
                const long long g = (long long)(h * 128 + r) * S_TOT + t * 128 + pc * 32 + s4 * 8;
                cp16(slot + (uint32_t)(r * 80 + s4 * 16), vthi + g);
                cp16(slot + (uint32_t)(10240 + r * 80 + s4 * 16), vtlo + g);
            }
        }
    };

    issue_item(0); asm volatile("cp.async.commit_group;" ::: "memory");
    issue_item(1); asm volatile("cp.async.commit_group;" ::: "memory");
    issue_item(2); asm volatile("cp.async.commit_group;" ::: "memory");

    const uint32_t bnrow = (uint32_t)(((lane >> 4) << 3) + (lane & 7));
    const uint32_t bksel = (uint32_t)((lane >> 3) & 1);

    for (int j = 0; j < NITEM; j++) {
        if (j + 3 < NITEM) issue_item(j + 3);
        asm volatile("cp.async.commit_group;" ::: "memory");
        asm volatile("cp.async.wait_group 3;" ::: "memory");
        __syncthreads();

        const int sub = j & 7, phase = sub >> 2, c = sub & 3;
        const uint32_t slot = sb + (uint32_t)((j & 3) * FB);

        if (phase == 0) {
            if (c == 0) {
                #pragma unroll
                for (int ni = 0; ni < 16; ni++)
                    #pragma unroll
                    for (int jj = 0; jj < 4; jj++) sacc[ni][jj] = 0.f;
            }
            #pragma unroll
            for (int ks2 = 0; ks2 < 2; ks2++) {
                const int j8 = c * 2 + ks2;
                const uint32_t kof = (uint32_t)((ks2 * 2 + bksel) * 16);
                #pragma unroll
                for (int njp = 0; njp < 8; njp++) {
                    uint32_t bh4[4], bl4[4];
                    const uint32_t boff = (njp * 16 + bnrow) * 80 + kof;
                    ldm_x4(bh4, slot + boff);
                    ldm_x4(bl4, slot + 10240 + boff);
                    #pragma unroll
                    for (int s2 = 0; s2 < 2; s2++) {
                        const int ni = njp * 2 + s2;
                        mma16816(sacc[ni], qh[j8], bh4[s2 * 2], bh4[s2 * 2 + 1]);
                        mma16816(sacc[ni], qh[j8], bl4[s2 * 2], bl4[s2 * 2 + 1]);
                        mma16816(sacc[ni], ql[j8], bh4[s2 * 2], bh4[s2 * 2 + 1]);
                    }
                }
            }
            if (c == 3) {
                const float sc = 0.08838834764831845f;
                float mb0 = -1e30f, mb1 = -1e30f;
                #pragma unroll
                for (int ni = 0; ni < 16; ni++) {
                    sacc[ni][0] *= sc; sacc[ni][1] *= sc;
                    sacc[ni][2] *= sc; sacc[ni][3] *= sc;
                    mb0 = fmaxf(mb0, fmaxf(sacc[ni][0], sacc[ni][1]));
                    mb1 = fmaxf(mb1, fmaxf(sacc[ni][2], sacc[ni][3]));
                }
                mb0 = fmaxf(mb0, __shfl_xor_sync(0xffffffffu, mb0, 1));
                mb0 = fmaxf(mb0, __shfl_xor_sync(0xffffffffu, mb0, 2));
                mb1 = fmaxf(mb1, __shfl_xor_sync(0xffffffffu, mb1, 1));
                mb1 = fmaxf(mb1, __shfl_xor_sync(0xffffffffu, mb1, 2));
                const float mn0 = fmaxf(m0r, mb0), mn1 = fmaxf(m1r, mb1);
                const float a0 = __expf(m0r - mn0), a1 = __expf(m1r - mn1);
                m0r = mn0; m1r = mn1;
                l0 *= a0; l1 *= a1;
                #pragma unroll
                for (int di = 0; di < 16; di++) {
                    oacc[di][0] *= a0; oacc[di][1] *= a0;
                    oacc[di][2] *= a1; oacc[di][3] *= a1;
                }
                float rs0 = 0.f, rs1 = 0.f;
                #pragma unroll
                for (int ni = 0; ni < 16; ni++) {
                    const float p0 = __expf(sacc[ni][0] - mn0);
                    const float p1 = __expf(sacc[ni][1] - mn0);
                    const float p2 = __expf(sacc[ni][2] - mn1);
                    const float p3 = __expf(sacc[ni][3] - mn1);
                    rs0 += p0 + p1; rs1 += p2 + p3;
                    const int j8 = ni >> 1;
                    if ((ni & 1) == 0) {
                        packhl(p0, p1, ph[j8][0], pl[j8][0]);
                        packhl(p2, p3, ph[j8][1], pl[j8][1]);
                    } else {
                        packhl(p0, p1, ph[j8][2], pl[j8][2]);
                        packhl(p2, p3, ph[j8][3], pl[j8][3]);
                    }
                }
                l0 += rs0; l1 += rs1;
            }
        } else {
            #pragma unroll
            for (int ks2 = 0; ks2 < 2; ks2++) {
                const int j8 = c * 2 + ks2;
                const uint32_t kof = (uint32_t)((ks2 * 2 + bksel) * 16);
                #pragma unroll
                for (int djp = 0; djp < 8; djp++) {
                    uint32_t bh4[4], bl4[4];
                    const uint32_t boff = (djp * 16 + bnrow) * 80 + kof;
                    ldm_x4(bh4, slot + boff);
                    ldm_x4(bl4, slot + 10240 + boff);
                    #pragma unroll
                    for (int s2 = 0; s2 < 2; s2++) {
                        const int di = djp * 2 + s2;
                        mma16816(oacc[di], ph[j8], bh4[s2 * 2], bh4[s2 * 2 + 1]);
                        mma16816(oacc[di], ph[j8], bl4[s2 * 2], bl4[s2 * 2 + 1]);
                        mma16816(oacc[di], pl[j8], bh4[s2 * 2], bh4[s2 * 2 + 1]);
                    }
                }
            }
        }
        __syncthreads();
    }

    // ---- normalize and store fp16 ------------------------------------------
    l0 += __shfl_xor_sync(0xffffffffu, l0, 1);
    l0 += __shfl_xor_sync(0xffffffffu, l0, 2);
    l1 += __shfl_xor_sync(0xffffffffu, l1, 1);
    l1 += __shfl_xor_sync(0xffffffffu, l1, 2);
    const float i0 = 1.0f / l0, i1 = 1.0f / l1;
    const int r0 = qm0 + wid * 16 + (lane >> 2);
    const int r1 = r0 + 8;
    #pragma unroll
    for (int di = 0; di < 16; di++) {
        const int col = h * HD + di * 8 + (lane & 3) * 2;
        __half2 o0 = __floats2half2_rn(oacc[di][0] * i0, oacc[di][1] * i0);
        __half2 o1 = __floats2half2_rn(oacc[di][2] * i1, oacc[di][3] * i1);
        *reinterpret_cast<__half2*>(a16 + (long long)r0 * DIM + col) = o0;
        *reinterpret_cast<__half2*>(a16 + (long long)r1 * DIM + col) = o1;
    }
}

// ---------------- split / convert helpers ------------------------------------
__device__ __forceinline__ void split4(float4 v, __nv_bfloat16* hi, __nv_bfloat16* lo,
                                       long long idx) {
    __nv_bfloat16 h0 = __float2bfloat16(v.x), h1 = __float2bfloat16(v.y);
    __nv_bfloat16 h2 = __float2bfloat16(v.z), h3 = __float2bfloat16(v.w);
    __nv_bfloat162 a; a.x = h0; a.y = h1;
    __nv_bfloat162 b; b.x = h2; b.y = h3;
    *reinterpret_cast<__nv_bfloat162*>(hi + idx)     = a;
    *reinterpret_cast<__nv_bfloat162*>(hi + idx + 2) = b;
    __nv_bfloat162 c; c.x = __float2bfloat16(v.x - __bfloat162float(h0));
                      c.y = __float2bfloat16(v.y - __bfloat162float(h1));
    __nv_bfloat162 d; d.x = __float2bfloat16(v.z - __bfloat162float(h2));
                      d.y = __float2bfloat16(v.w - __bfloat162float(h3));
    *reinterpret_cast<__nv_bfloat162*>(lo + idx)     = c;
    *reinterpret_cast<__nv_bfloat162*>(lo + idx + 2) = d;
}

// x = [txt rows from enc; img rows from hidden] -> bf16 hi/lo AND fp16
__global__ void split_x3(const float* __restrict__ hidden, const float* __restrict__ enc,
                         __nv_bfloat16* __restrict__ hi, __nv_bfloat16* __restrict__ lo,
                         __half* __restrict__ h16) {
    const long long i4 = ((long long)blockIdx.x * 256 + threadIdx.x) * 4;
    const long long row = i4 / DIM;
    const float* src = (row < S_TXT) ? (enc + i4) : (hidden + i4 - (long long)S_TXT * DIM);
    const float4 v = *reinterpret_cast<const float4*>(src);
    split4(v, hi, lo, i4);
    *reinterpret_cast<__half2*>(h16 + i4)     = __floats2half2_rn(v.x, v.y);
    *reinterpret_cast<__half2*>(h16 + i4 + 2) = __floats2half2_rn(v.z, v.w);
}

__global__ void split_plain(const float* __restrict__ src,
                            __nv_bfloat16* __restrict__ hi, __nv_bfloat16* __restrict__ lo) {
    const long long i4 = ((long long)blockIdx.x * 256 + threadIdx.x) * 4;
    split4(*reinterpret_cast<const float4*>(src + i4), hi, lo, i4);
}

__global__ void cvt_h16(const float* __restrict__ src, __half* __restrict__ dst) {
    const long long i4 = ((long long)blockIdx.x * 256 + threadIdx.x) * 4;
    const float4 v = *reinterpret_cast<const float4*>(src + i4);
    *reinterpret_cast<__half2*>(dst + i4)     = __floats2half2_rn(v.x, v.y);
    *reinterpret_cast<__half2*>(dst + i4 + 2) = __floats2half2_rn(v.z, v.w);
}

// ---------------- RMSNorm + RoPE + split -------------------------------------
__global__ void norm_rope_split(
    const float* __restrict__ x,
    __nv_bfloat16* __restrict__ hi, __nv_bfloat16* __restrict__ lo,
    const float* __restrict__ w_txt, const float* __restrict__ w_img,
    const float* __restrict__ txt_cos, const float* __restrict__ txt_sin,
    const float* __restrict__ img_cos, const float* __restrict__ img_sin)
{
    const int s = blockIdx.x;
    const int h = blockIdx.y;
    const int d = threadIdx.x;
    const long long off = (long long)s * DIM + h * HD;

    float v = x[off + d];
    float ss = v * v;
    #pragma unroll
    for (int o = 16; o > 0; o >>= 1) ss += __shfl_xor_sync(0xffffffffu, ss, o);
    __shared__ float wsum[4];
    if ((d & 31) == 0) wsum[d >> 5] = ss;
    __syncthreads();
    const float tot = wsum[0] + wsum[1] + wsum[2] + wsum[3];
    const float r = rsqrtf(tot * (1.0f / HD) + 1e-6f);

    const bool is_txt = (s < S_TXT);
    const float* w = is_txt ? w_txt : w_img;
    const float nv = v * r * w[d];

    const float other = __shfl_xor_sync(0xffffffffu, nv, 1);
    const float rot = (d & 1) ? other : -other;

    const long long srel = is_txt ? s : (s - S_TXT);
    const float cc = (is_txt ? txt_cos : img_cos)[srel * HD + d];
    const float sn = (is_txt ? txt_sin : img_sin)[srel * HD + d];
    const float f = nv * cc + rot * sn;

    __nv_bfloat16 hh = __float2bfloat16(f);
    hi[off + d] = hh;
    lo[off + d] = __float2bfloat16(f - __bfloat162float(hh));
}

// ---------------- V transpose + split:  v[s, DIM] -> vt[head][d][s] ----------
__global__ void vtrans_split(const float* __restrict__ v,
                             __nv_bfloat16* __restrict__ vhi, __nv_bfloat16* __restrict__ vlo)
{
    __shared__ float tile[32][33];
    const int c0 = blockIdx.x * 32;
    const int s0 = blockIdx.y * 32;
    const int tx = threadIdx.x, ty = threadIdx.y;

    #pragma unroll
    for (int r = ty; r < 32; r += 8)
        tile[r][tx] = v[(long long)(s0 + r) * DIM + c0 + tx];
    __syncthreads();
    #pragma unroll
    for (int r = ty; r < 32; r += 8) {
        const int c = c0 + r;
        const int head = c >> 7, d = c & 127;
        const long long o = (long long)head * HD * S_TOT + (long long)d * S_TOT + s0 + tx;
        const float f = tile[tx][r];
        __nv_bfloat16 hh = __float2bfloat16(f);
        vhi[o] = hh;
        vlo[o] = __float2bfloat16(f - __bfloat162float(hh));
    }
}

// ---------------- launch -----------------------------------------------------
extern "C" void kernel_launch(void* const* d_in, const int* in_sizes, int n_in,
                              void* d_out, int out_size)
{
    const float* hidden  = (const float*)d_in[0];
    const float* enc     = (const float*)d_in[1];
    const float* img_cos = (const float*)d_in[2];
    const float* img_sin = (const float*)d_in[3];
    const float* txt_cos = (const float*)d_in[4];
    const float* txt_sin = (const float*)d_in[5];

    const float *W[8];   // 0=Wq 1=Wk 2=Wv 3=Waq 4=Wak 5=Wav 6=Wo 7=Wao
    const float *bq, *bk, *bv, *baq, *bak, *bav, *bo, *bao;
    if (in_sizes[7] == DIM) {
        W[0] = (const float*)d_in[6];  bq  = (const float*)d_in[7];
        W[1] = (const float*)d_in[8];  bk  = (const float*)d_in[9];
        W[2] = (const float*)d_in[10]; bv  = (const float*)d_in[11];
        W[3] = (const float*)d_in[12]; baq = (const float*)d_in[13];
        W[4] = (const float*)d_in[14]; bak = (const float*)d_in[15];
        W[5] = (const float*)d_in[16]; bav = (const float*)d_in[17];
        W[6] = (const float*)d_in[18]; bo  = (const float*)d_in[19];
        W[7] = (const float*)d_in[20]; bao = (const float*)d_in[21];
    } else {
        for (int i = 0; i < 8; i++) W[i] = (const float*)d_in[6 + i];
        bq  = (const float*)d_in[14]; bk  = (const float*)d_in[15];
        bv  = (const float*)d_in[16]; baq = (const float*)d_in[17];
        bak = (const float*)d_in[18]; bav = (const float*)d_in[19];
        bo  = (const float*)d_in[20]; bao = (const float*)d_in[21];
    }
    const float* nq_w  = (const float*)d_in[22];
    const float* nk_w  = (const float*)d_in[23];
    const float* naq_w = (const float*)d_in[24];
    const float* nak_w = (const float*)d_in[25];

    static float *q, *k, *v;
    static __nv_bfloat16 *xhi, *xlo, *whi, *wlo, *qhi, *qlo, *khi, *klo, *vthi, *vtlo;
    static __half *x16, *w16, *a16;
    static bool inited = false;
    if (!inited) {
        cudaGetSymbolAddress((void**)&q,    g_q);
        cudaGetSymbolAddress((void**)&k,    g_k);
        cudaGetSymbolAddress((void**)&v,    g_v);
        cudaGetSymbolAddress((void**)&xhi,  g_xhi);  cudaGetSymbolAddress((void**)&xlo,  g_xlo);
        cudaGetSymbolAddress((void**)&whi,  g_whi);  cudaGetSymbolAddress((void**)&wlo,  g_wlo);
        cudaGetSymbolAddress((void**)&qhi,  g_qhi);  cudaGetSymbolAddress((void**)&qlo,  g_qlo);
        cudaGetSymbolAddress((void**)&khi,  g_khi);  cudaGetSymbolAddress((void**)&klo,  g_klo);
        cudaGetSymbolAddress((void**)&vthi, g_vthi); cudaGetSymbolAddress((void**)&vtlo, g_vtlo);
        cudaGetSymbolAddress((void**)&x16,  g_x16);
        cudaGetSymbolAddress((void**)&w16,  g_w16);
        cudaGetSymbolAddress((void**)&a16,  g_a16);
        cudaFuncSetAttribute(mma_gemm,   cudaFuncAttributeMaxDynamicSharedMemorySize, GSM);
        cudaFuncSetAttribute(mma_gemm_h, cudaFuncAttributeMaxDynamicSharedMemorySize, HSM);
        cudaFuncSetAttribute(flash_attn, cudaFuncAttributeMaxDynamicSharedMemorySize, FRING);
        inited = true;
    }

    // 1. convert inputs/weights.  bf16 hi/lo: x, Wq, Wk, Waq, Wak.
    //    fp16: x, Wv, Wav, Wo, Wao.
    split_x3<<<(S_TOT * DIM) / 1024, 256>>>(hidden, enc, xhi, xlo, x16);
    split_plain<<<(int)(WSZ / 1024), 256>>>(W[0], whi + 0 * WSZ, wlo + 0 * WSZ);  // Wq
    split_plain<<<(int)(WSZ / 1024), 256>>>(W[1], whi + 1 * WSZ, wlo + 1 * WSZ);  // Wk
    split_plain<<<(int)(WSZ / 1024), 256>>>(W[3], whi + 2 * WSZ, wlo + 2 * WSZ);  // Waq
    split_plain<<<(int)(WSZ / 1024), 256>>>(W[4], whi + 3 * WSZ, wlo + 3 * WSZ);  // Wak
    cvt_h16<<<(int)(WSZ / 1024), 256>>>(W[2], w16 + 0 * WSZ);                     // Wv
    cvt_h16<<<(int)(WSZ / 1024), 256>>>(W[5], w16 + 1 * WSZ);                     // Wav
    cvt_h16<<<(int)(WSZ / 1024), 256>>>(W[6], w16 + 2 * WSZ);                     // Wo
    cvt_h16<<<(int)(WSZ / 1024), 256>>>(W[7], w16 + 3 * WSZ);                     // Wao

    // 2. projections: Q,K 3-term bf16;  V single fp16
    const dim3 gP(DIM / 128, S_TOT / 256, 1);   // (24, 10)
    mma_gemm<<<gP, 256, GSM>>>(xhi, xlo,
        whi + 0 * WSZ, wlo + 0 * WSZ, whi + 2 * WSZ, wlo + 2 * WSZ, q, bq, baq);
    mma_gemm<<<gP, 256, GSM>>>(xhi, xlo,
        whi + 1 * WSZ, wlo + 1 * WSZ, whi + 3 * WSZ, wlo + 3 * WSZ, k, bk, bak);
    mma_gemm_h<<<gP, 256, HSM>>>(x16, w16 + 0 * WSZ, w16 + 1 * WSZ, v, bv, bav, 0);

    // 3. RMSNorm + RoPE + split on q, k;  transpose + split v
    const dim3 gNR(S_TOT, HEADS);
    norm_rope_split<<<gNR, 128>>>(q, qhi, qlo, naq_w, nq_w, txt_cos, txt_sin, img_cos, img_sin);
    norm_rope_split<<<gNR, 128>>>(k, khi, klo, nak_w, nk_w, txt_cos, txt_sin, img_cos, img_sin);
    vtrans_split<<<dim3(DIM / 32, S_TOT / 32), dim3(32, 8)>>>(v, vthi, vtlo);

    // 4. fused attention: scores + softmax + PV -> fp16 attn
    flash_attn<<<dim3(S_TOT / 128, HEADS), 256, FRING>>>(
        qhi, qlo, khi, klo, vthi, vtlo, a16);

    // 5. output projection (fp16 single-term; txt rows -> Wao/bao, remapped)
    mma_gemm_h<<<gP, 256, HSM>>>(a16, w16 + 2 * WSZ, w16 + 3 * WSZ,
        (float*)d_out, bo, bao, 1);
}

// round 7
// speedup vs baseline: 4.7563x; 1.2390x over previous
#include <cuda_runtime.h>
#include <cuda_fp16.h>
#include <cstdint>
#include <math.h>

#define HEADS 24
#define HD    128
#define DIM   3072
#define S_IMG 2048
#define S_TXT 512
#define S_TOT 2560
#define WSZ   ((size_t)DIM * DIM)

// ---------------- scratch (static device memory; no allocations) ------------
__device__ float g_q[(size_t)S_TOT * DIM];
__device__ float g_k[(size_t)S_TOT * DIM];
__device__ float g_v[(size_t)S_TOT * DIM];

__device__ __half g_xh[(size_t)S_TOT * DIM], g_xl[(size_t)S_TOT * DIM];
__device__ __half g_w16[8 * WSZ];            // Wq Wk Wv Waq Wak Wav Wo Wao
__device__ __half g_qh[(size_t)S_TOT * DIM], g_ql[(size_t)S_TOT * DIM];
__device__ __half g_kh[(size_t)S_TOT * DIM], g_kl[(size_t)S_TOT * DIM];
__device__ __half g_vt[(size_t)HEADS * HD * S_TOT];
__device__ __half g_a16[(size_t)S_TOT * DIM];

// ---------------- helpers ----------------------------------------------------
__device__ __forceinline__ uint32_t smem_u32(const void* p) {
    return (uint32_t)__cvta_generic_to_shared(p);
}

__device__ __forceinline__ void cp16(uint32_t dst, const void* src) {
    asm volatile("cp.async.cg.shared.global [%0], [%1], 16;" :: "r"(dst), "l"(src));
}

__device__ __forceinline__ void ldm_x4(uint32_t* r, uint32_t addr) {
    asm volatile("ldmatrix.sync.aligned.m8n8.x4.shared.b16 {%0,%1,%2,%3}, [%4];"
                 : "=r"(r[0]), "=r"(r[1]), "=r"(r[2]), "=r"(r[3]) : "r"(addr));
}

__device__ __forceinline__ void mma16816h(float* c, const uint32_t* a, uint32_t b0, uint32_t b1) {
    asm volatile(
        "mma.sync.aligned.m16n8k16.row.col.f32.f16.f16.f32 "
        "{%0,%1,%2,%3}, {%4,%5,%6,%7}, {%8,%9}, {%0,%1,%2,%3};"
        : "+f"(c[0]), "+f"(c[1]), "+f"(c[2]), "+f"(c[3])
        : "r"(a[0]), "r"(a[1]), "r"(a[2]), "r"(a[3]), "r"(b0), "r"(b1));
}

// pack (a,b) into fp16x2 hi fragment and residual lo fragment  (~22-bit pair)
__device__ __forceinline__ void packhl16(float a, float b, uint32_t& hi, uint32_t& lo) {
    __half ah = __float2half_rn(a), bh = __float2half_rn(b);
    __half2 H; H.x = ah; H.y = bh;
    hi = *reinterpret_cast<uint32_t*>(&H);
    __half2 L;
    L.x = __float2half_rn(a - __half2float(ah));
    L.y = __float2half_rn(b - __half2float(bh));
    lo = *reinterpret_cast<uint32_t*>(&L);
}

// ---------------- 2-term fp16 GEMM (256x128 tile): Q/K projections -----------
// C = (Ah + Al) * B^T + bias.  A 2-term fp16 (22-bit), B single fp16.
// Rows m < S_TXT take (B2, bias2).
#define GTA 20480              /* 256 rows * 80 B */
#define GTB 10240              /* 128 rows * 80 B */
#define GBUF (2 * GTA + GTB)   /* 51200 */
#define GSM  (2 * GBUF)        /* 102400 */
__global__ __launch_bounds__(256) void mma_gemm2(
    const __half* __restrict__ Ah, const __half* __restrict__ Al,
    const __half* __restrict__ B, const __half* __restrict__ B2,
    float* __restrict__ C,
    const float* __restrict__ bias, const float* __restrict__ bias2)
{
    extern __shared__ char smem[];
    const uint32_t sb = smem_u32(smem);
    const int tid = threadIdx.x;
    const int wid = tid >> 5;
    const int lane = tid & 31;
    const int wm = wid & 3;           // 4 warps x 64 rows
    const int wn = wid >> 2;          // 2 warps x 64 cols

    const int m0 = blockIdx.y * 256;
    const int n0 = blockIdx.x * 128;
    const bool alt = (m0 < S_TXT);
    const __half* bsrc = alt ? B2 : B;

    float acc[4][8][4];
    #pragma unroll
    for (int mi = 0; mi < 4; mi++)
        #pragma unroll
        for (int ni = 0; ni < 8; ni++)
            #pragma unroll
            for (int j = 0; j < 4; j++) acc[mi][ni][j] = 0.f;

    auto issue = [&](int c) {
        const uint32_t base = sb + (uint32_t)((c & 1) * GBUF);
        const int k0 = c * 32;
        #pragma unroll
        for (int i = 0; i < 10; i++) {
            const int idx = i * 256 + tid;            // 0..2559
            if (idx < 2048) {                         // A tiles (hi, lo)
                const int arr = idx >> 10, rem = idx & 1023;
                const int r = rem >> 2, s4 = rem & 3;
                const __half* s = arr ? Al : Ah;
                cp16(base + (uint32_t)(arr * GTA + r * 80 + s4 * 16),
                     s + (long long)(m0 + r) * DIM + k0 + s4 * 8);
            } else {                                  // B tile
                const int idx2 = idx - 2048;
                const int r = idx2 >> 2, s4 = idx2 & 3;
                cp16(base + (uint32_t)(2 * GTA + r * 80 + s4 * 16),
                     bsrc + (long long)(n0 + r) * DIM + k0 + s4 * 8);
            }
        }
    };

    const int nc = DIM / 32;   // 96
    issue(0);
    asm volatile("cp.async.commit_group;" ::: "memory");

    for (int c = 0; c < nc; c++) {
        if (c + 1 < nc) issue(c + 1);
        asm volatile("cp.async.commit_group;" ::: "memory");
        asm volatile("cp.async.wait_group 1;" ::: "memory");
        __syncthreads();

        const uint32_t base = sb + (uint32_t)((c & 1) * GBUF);
        const uint32_t aH = base, aL = base + GTA, bB = base + 2 * GTA;

        #pragma unroll
        for (int ks = 0; ks < 2; ks++) {
            uint32_t ah4[4][4], al4[4][4];
            const uint32_t arow = (uint32_t)(wm * 64 + (lane & 15));
            const uint32_t akof = (uint32_t)((ks * 2 + (lane >> 4)) * 16);
            #pragma unroll
            for (int mi = 0; mi < 4; mi++) {
                const uint32_t aoff = (arow + mi * 16) * 80 + akof;
                ldm_x4(ah4[mi], aH + aoff);
                ldm_x4(al4[mi], aL + aoff);
            }
            const uint32_t bn = (uint32_t)(wn * 64 + ((lane >> 4) << 3) + (lane & 7));
            const uint32_t bkof = (uint32_t)((ks * 2 + ((lane >> 3) & 1)) * 16);
            #pragma unroll
            for (int njp = 0; njp < 4; njp++) {
                uint32_t b4[4];
                ldm_x4(b4, bB + (bn + njp * 16) * 80 + bkof);
                #pragma unroll
                for (int sub = 0; sub < 2; sub++) {
                    const int ni = njp * 2 + sub;
                    #pragma unroll
                    for (int mi = 0; mi < 4; mi++) {
                        mma16816h(acc[mi][ni], ah4[mi], b4[sub * 2], b4[sub * 2 + 1]);
                        mma16816h(acc[mi][ni], al4[mi], b4[sub * 2], b4[sub * 2 + 1]);
                    }
                }
            }
        }
        __syncthreads();
    }

    const float* bp = alt ? bias2 : bias;
    #pragma unroll
    for (int mi = 0; mi < 4; mi++) {
        const int rb = m0 + wm * 64 + mi * 16 + (lane >> 2);
        #pragma unroll
        for (int half = 0; half < 2; half++) {
            const int r = rb + half * 8;
            float* crow = C + (long long)r * DIM;
            #pragma unroll
            for (int ni = 0; ni < 8; ni++) {
                const int col = n0 + wn * 64 + ni * 8 + (lane & 3) * 2;
                float2 o;
                o.x = acc[mi][ni][half * 2 + 0] + bp[col];
                o.y = acc[mi][ni][half * 2 + 1] + bp[col + 1];
                *reinterpret_cast<float2*>(crow + col) = o;
            }
        }
    }
}

// ---------------- fp16 single-term GEMM (256x128 tile): V / out projection ---
#define HTA 20480
#define HTB 10240
#define HBUF (HTA + HTB)
#define HSM  (2 * HBUF)        /* 61440 */
__global__ __launch_bounds__(256) void mma_gemm_h(
    const __half* __restrict__ A,
    const __half* __restrict__ B, const __half* __restrict__ B2,
    float* __restrict__ C,
    const float* __restrict__ bias, const float* __restrict__ bias2, int remap)
{
    extern __shared__ char smem[];
    const uint32_t sb = smem_u32(smem);
    const int tid = threadIdx.x;
    const int wid = tid >> 5;
    const int lane = tid & 31;
    const int wm = wid & 3;
    const int wn = wid >> 2;

    const int m0 = blockIdx.y * 256;
    const int n0 = blockIdx.x * 128;
    const bool alt = (m0 < S_TXT);
    const __half* bsrc = alt ? B2 : B;

    float acc[4][8][4];
    #pragma unroll
    for (int mi = 0; mi < 4; mi++)
        #pragma unroll
        for (int ni = 0; ni < 8; ni++)
            #pragma unroll
            for (int j = 0; j < 4; j++) acc[mi][ni][j] = 0.f;

    auto issue = [&](int c) {
        const uint32_t base = sb + (uint32_t)((c & 1) * HBUF);
        const int k0 = c * 32;
        #pragma unroll
        for (int i = 0; i < 6; i++) {
            const int idx = i * 256 + tid;            // 0..1535
            if (idx < 1024) {                         // A tile
                const int r = idx >> 2, s4 = idx & 3;
                cp16(base + (uint32_t)(r * 80 + s4 * 16),
                     A + (long long)(m0 + r) * DIM + k0 + s4 * 8);
            } else {                                  // B tile
                const int idx2 = idx - 1024;
                const int r = idx2 >> 2, s4 = idx2 & 3;
                cp16(base + (uint32_t)(HTA + r * 80 + s4 * 16),
                     bsrc + (long long)(n0 + r) * DIM + k0 + s4 * 8);
            }
        }
    };

    const int nc = DIM / 32;
    issue(0);
    asm volatile("cp.async.commit_group;" ::: "memory");

    for (int c = 0; c < nc; c++) {
        if (c + 1 < nc) issue(c + 1);
        asm volatile("cp.async.commit_group;" ::: "memory");
        asm volatile("cp.async.wait_group 1;" ::: "memory");
        __syncthreads();

        const uint32_t base = sb + (uint32_t)((c & 1) * HBUF);
        const uint32_t aB = base, bB = base + HTA;

        #pragma unroll
        for (int ks = 0; ks < 2; ks++) {
            uint32_t a4[4][4];
            const uint32_t arow = (uint32_t)(wm * 64 + (lane & 15));
            const uint32_t akof = (uint32_t)((ks * 2 + (lane >> 4)) * 16);
            #pragma unroll
            for (int mi = 0; mi < 4; mi++)
                ldm_x4(a4[mi], aB + (arow + mi * 16) * 80 + akof);

            const uint32_t bn = (uint32_t)(wn * 64 + ((lane >> 4) << 3) + (lane & 7));
            const uint32_t bkof = (uint32_t)((ks * 2 + ((lane >> 3) & 1)) * 16);
            #pragma unroll
            for (int njp = 0; njp < 4; njp++) {
                uint32_t b4[4];
                ldm_x4(b4, bB + (bn + njp * 16) * 80 + bkof);
                #pragma unroll
                for (int sub = 0; sub < 2; sub++) {
                    const int ni = njp * 2 + sub;
                    #pragma unroll
                    for (int mi = 0; mi < 4; mi++)
                        mma16816h(acc[mi][ni], a4[mi], b4[sub * 2], b4[sub * 2 + 1]);
                }
            }
        }
        __syncthreads();
    }

    const float* bp = alt ? bias2 : bias;
    #pragma unroll
    for (int mi = 0; mi < 4; mi++) {
        const int rb = m0 + wm * 64 + mi * 16 + (lane >> 2);
        #pragma unroll
        for (int half = 0; half < 2; half++) {
            const int r = rb + half * 8;
            long long orow = r;
            if (remap) orow = (r < S_TXT) ? (long long)(S_IMG + r) : (long long)(r - S_TXT);
            float* crow = C + orow * DIM;
            #pragma unroll
            for (int ni = 0; ni < 8; ni++) {
                const int col = n0 + wn * 64 + ni * 8 + (lane & 3) * 2;
                float2 o;
                o.x = acc[mi][ni][half * 2 + 0] + bp[col];
                o.y = acc[mi][ni][half * 2 + 1] + bp[col + 1];
                *reinterpret_cast<float2*>(crow + col) = o;
            }
        }
    }
}

// ---------------- flash attention (fused scores+softmax+PV, fp16) ------------
// q 2-term fp16 (regs), k single fp16, P 2-term fp16 (regs), V^T single fp16.
#define FB    10240            /* ring slot: one 128x32 fp16 tile */
#define FRING (4 * FB)         /* 40960 */
#define NBLK  (S_TOT / 128)    /* 20 */
#define NITEM (NBLK * 8)
__global__ __launch_bounds__(256) void flash_attn(
    const __half* __restrict__ qhp, const __half* __restrict__ qlp,
    const __half* __restrict__ khp,
    const __half* __restrict__ vtp,
    __half* __restrict__ a16)
{
    extern __shared__ char smem[];
    const uint32_t sb = smem_u32(smem);
    const int tid = threadIdx.x, wid = tid >> 5, lane = tid & 31;
    const int qm0 = blockIdx.x * 128;
    const int h = blockIdx.y;

    // ---- Q fragments (hi/lo) into registers, staged through ring area ------
    uint32_t qh[8][4], ql[8][4];
    #pragma unroll
    for (int pass = 0; pass < 2; pass++) {
        const __half* src = pass ? qlp : qhp;
        #pragma unroll
        for (int i = 0; i < 8; i++) {
            const int idx = i * 256 + tid;               // 0..2047
            const int r = idx >> 4, seg = idx & 15;
            cp16(sb + (uint32_t)((seg >> 2) * FB + r * 80 + (seg & 3) * 16),
                 src + (long long)(qm0 + r) * DIM + h * HD + seg * 8);
        }
        asm volatile("cp.async.commit_group;" ::: "memory");
        asm volatile("cp.async.wait_group 0;" ::: "memory");
        __syncthreads();
        #pragma unroll
        for (int j = 0; j < 8; j++) {
            const uint32_t addr = sb + (uint32_t)((j >> 1) * FB
                + (wid * 16 + (lane & 15)) * 80 + ((j & 1) * 2 + (lane >> 4)) * 16);
            if (pass == 0) ldm_x4(qh[j], addr);
            else           ldm_x4(ql[j], addr);
        }
        __syncthreads();
    }

    float oacc[16][4];
    #pragma unroll
    for (int di = 0; di < 16; di++)
        #pragma unroll
        for (int j = 0; j < 4; j++) oacc[di][j] = 0.f;
    float sacc[16][4];
    uint32_t ph[8][4], pl[8][4];
    float m0r = -1e30f, m1r = -1e30f, l0 = 0.f, l1 = 0.f;

    auto issue_item = [&](int j) {
        const int t = j >> 3, sub = j & 7, pc = sub & 3;
        const uint32_t slot = sb + (uint32_t)((j & 3) * FB);
        if ((sub >> 2) == 0) {            // K chunk pc of s-block t
            #pragma unroll
            for (int i = 0; i < 2; i++) {
                const int idx = i * 256 + tid;
                const int r = idx >> 2, s4 = idx & 3;
                cp16(slot + (uint32_t)(r * 80 + s4 * 16),
                     khp + (long long)(t * 128 + r) * DIM + h * HD + pc * 32 + s4 * 8);
            }
        } else {                          // V^T chunk pc of s-block t
            #pragma unroll
            for (int i = 0; i < 2; i++) {
                const int idx = i * 256 + tid;
                const int r = idx >> 2, s4 = idx & 3;
                cp16(slot + (uint32_t)(r * 80 + s4 * 16),
                     vtp + (long long)(h * 128 + r) * S_TOT + t * 128 + pc * 32 + s4 * 8);
            }
        }
    };

    issue_item(0); asm volatile("cp.async.commit_group;" ::: "memory");
    issue_item(1); asm volatile("cp.async.commit_group;" ::: "memory");
    issue_item(2); asm volatile("cp.async.commit_group;" ::: "memory");

    const uint32_t bnrow = (uint32_t)(((lane >> 4) << 3) + (lane & 7));
    const uint32_t bksel = (uint32_t)((lane >> 3) & 1);

    for (int j = 0; j < NITEM; j++) {
        if (j + 3 < NITEM) issue_item(j + 3);
        asm volatile("cp.async.commit_group;" ::: "memory");
        asm volatile("cp.async.wait_group 3;" ::: "memory");
        __syncthreads();

        const int sub = j & 7, phase = sub >> 2, c = sub & 3;
        const uint32_t slot = sb + (uint32_t)((j & 3) * FB);

        if (phase == 0) {
            if (c == 0) {
                #pragma unroll
                for (int ni = 0; ni < 16; ni++)
                    #pragma unroll
                    for (int jj = 0; jj < 4; jj++) sacc[ni][jj] = 0.f;
            }
            #pragma unroll
            for (int ks2 = 0; ks2 < 2; ks2++) {
                const int j8 = c * 2 + ks2;
                const uint32_t kof = (uint32_t)((ks2 * 2 + bksel) * 16);
                #pragma unroll
                for (int njp = 0; njp < 8; njp++) {
                    uint32_t b4[4];
                    ldm_x4(b4, slot + (njp * 16 + bnrow) * 80 + kof);
                    #pragma unroll
                    for (int s2 = 0; s2 < 2; s2++) {
                        const int ni = njp * 2 + s2;
                        mma16816h(sacc[ni], qh[j8], b4[s2 * 2], b4[s2 * 2 + 1]);
                        mma16816h(sacc[ni], ql[j8], b4[s2 * 2], b4[s2 * 2 + 1]);
                    }
                }
            }
            if (c == 3) {
                // ---- online softmax over this 128-col S block --------------
                const float sc = 0.08838834764831845f;
                float mb0 = -1e30f, mb1 = -1e30f;
                #pragma unroll
                for (int ni = 0; ni < 16; ni++) {
                    sacc[ni][0] *= sc; sacc[ni][1] *= sc;
                    sacc[ni][2] *= sc; sacc[ni][3] *= sc;
                    mb0 = fmaxf(mb0, fmaxf(sacc[ni][0], sacc[ni][1]));
                    mb1 = fmaxf(mb1, fmaxf(sacc[ni][2], sacc[ni][3]));
                }
                mb0 = fmaxf(mb0, __shfl_xor_sync(0xffffffffu, mb0, 1));
                mb0 = fmaxf(mb0, __shfl_xor_sync(0xffffffffu, mb0, 2));
                mb1 = fmaxf(mb1, __shfl_xor_sync(0xffffffffu, mb1, 1));
                mb1 = fmaxf(mb1, __shfl_xor_sync(0xffffffffu, mb1, 2));
                const float mn0 = fmaxf(m0r, mb0), mn1 = fmaxf(m1r, mb1);
                const float a0 = __expf(m0r - mn0), a1 = __expf(m1r - mn1);
                m0r = mn0; m1r = mn1;
                l0 *= a0; l1 *= a1;
                #pragma unroll
                for (int di = 0; di < 16; di++) {
                    oacc[di][0] *= a0; oacc[di][1] *= a0;
                    oacc[di][2] *= a1; oacc[di][3] *= a1;
                }
                float rs0 = 0.f, rs1 = 0.f;
                #pragma unroll
                for (int ni = 0; ni < 16; ni++) {
                    const float p0 = __expf(sacc[ni][0] - mn0);
                    const float p1 = __expf(sacc[ni][1] - mn0);
                    const float p2 = __expf(sacc[ni][2] - mn1);
                    const float p3 = __expf(sacc[ni][3] - mn1);
                    rs0 += p0 + p1; rs1 += p2 + p3;
                    const int j8 = ni >> 1;
                    if ((ni & 1) == 0) {
                        packhl16(p0, p1, ph[j8][0], pl[j8][0]);
                        packhl16(p2, p3, ph[j8][1], pl[j8][1]);
                    } else {
                        packhl16(p0, p1, ph[j8][2], pl[j8][2]);
                        packhl16(p2, p3, ph[j8][3], pl[j8][3]);
                    }
                }
                l0 += rs0; l1 += rs1;
            }
        } else {
            // ---- O += P * V --------------------------------------------------
            #pragma unroll
            for (int ks2 = 0; ks2 < 2; ks2++) {
                const int j8 = c * 2 + ks2;
                const uint32_t kof = (uint32_t)((ks2 * 2 + bksel) * 16);
                #pragma unroll
                for (int djp = 0; djp < 8; djp++) {
                    uint32_t b4[4];
                    ldm_x4(b4, slot + (djp * 16 + bnrow) * 80 + kof);
                    #pragma unroll
                    for (int s2 = 0; s2 < 2; s2++) {
                        const int di = djp * 2 + s2;
                        mma16816h(oacc[di], ph[j8], b4[s2 * 2], b4[s2 * 2 + 1]);
                        mma16816h(oacc[di], pl[j8], b4[s2 * 2], b4[s2 * 2 + 1]);
                    }
                }
            }
        }
        __syncthreads();
    }

    // ---- normalize and store fp16 ------------------------------------------
    l0 += __shfl_xor_sync(0xffffffffu, l0, 1);
    l0 += __shfl_xor_sync(0xffffffffu, l0, 2);
    l1 += __shfl_xor_sync(0xffffffffu, l1, 1);
    l1 += __shfl_xor_sync(0xffffffffu, l1, 2);
    const float i0 = 1.0f / l0, i1 = 1.0f / l1;
    const int r0 = qm0 + wid * 16 + (lane >> 2);
    const int r1 = r0 + 8;
    #pragma unroll
    for (int di = 0; di < 16; di++) {
        const int col = h * HD + di * 8 + (lane & 3) * 2;
        __half2 o0 = __floats2half2_rn(oacc[di][0] * i0, oacc[di][1] * i0);
        __half2 o1 = __floats2half2_rn(oacc[di][2] * i1, oacc[di][3] * i1);
        *reinterpret_cast<__half2*>(a16 + (long long)r0 * DIM + col) = o0;
        *reinterpret_cast<__half2*>(a16 + (long long)r1 * DIM + col) = o1;
    }
}

// ---------------- conversion kernels -----------------------------------------
// x = [txt rows from enc; img rows from hidden] -> fp16 hi/lo pair
__global__ void split_x16(const float* __restrict__ hidden, const float* __restrict__ enc,
                          __half* __restrict__ hi, __half* __restrict__ lo) {
    const long long i4 = ((long long)blockIdx.x * 256 + threadIdx.x) * 4;
    const long long row = i4 / DIM;
    const float* src = (row < S_TXT) ? (enc + i4) : (hidden + i4 - (long long)S_TXT * DIM);
    const float4 v = *reinterpret_cast<const float4*>(src);
    __half h0 = __float2half_rn(v.x), h1 = __float2half_rn(v.y);
    __half h2 = __float2half_rn(v.z), h3 = __float2half_rn(v.w);
    __half2 a; a.x = h0; a.y = h1;
    __half2 b; b.x = h2; b.y = h3;
    *reinterpret_cast<__half2*>(hi + i4)     = a;
    *reinterpret_cast<__half2*>(hi + i4 + 2) = b;
    __half2 c; c.x = __float2half_rn(v.x - __half2float(h0));
               c.y = __float2half_rn(v.y - __half2float(h1));
    __half2 d; d.x = __float2half_rn(v.z - __half2float(h2));
               d.y = __float2half_rn(v.w - __half2float(h3));
    *reinterpret_cast<__half2*>(lo + i4)     = c;
    *reinterpret_cast<__half2*>(lo + i4 + 2) = d;
}

struct WPtrs { const float* p[8]; };
// all 8 weights -> fp16 in one launch (blockIdx.y selects the weight)
__global__ void cvt_w16(WPtrs W, __half* __restrict__ dst) {
    const long long i4 = ((long long)blockIdx.x * 256 + threadIdx.x) * 4;
    const float* src = W.p[blockIdx.y];
    __half* d = dst + (size_t)blockIdx.y * WSZ;
    const float4 v = *reinterpret_cast<const float4*>(src + i4);
    *reinterpret_cast<__half2*>(d + i4)     = __floats2half2_rn(v.x, v.y);
    *reinterpret_cast<__half2*>(d + i4 + 2) = __floats2half2_rn(v.z, v.w);
}

// ---------------- RMSNorm + RoPE -> fp16 hi/lo -------------------------------
__global__ void norm_rope16(
    const float* __restrict__ x,
    __half* __restrict__ hi, __half* __restrict__ lo,
    const float* __restrict__ w_txt, const float* __restrict__ w_img,
    const float* __restrict__ txt_cos, const float* __restrict__ txt_sin,
    const float* __restrict__ img_cos, const float* __restrict__ img_sin)
{
    const int s = blockIdx.x;
    const int h = blockIdx.y;
    const int d = threadIdx.x;
    const long long off = (long long)s * DIM + h * HD;

    float v = x[off + d];
    float ss = v * v;
    #pragma unroll
    for (int o = 16; o > 0; o >>= 1) ss += __shfl_xor_sync(0xffffffffu, ss, o);
    __shared__ float wsum[4];
    if ((d & 31) == 0) wsum[d >> 5] = ss;
    __syncthreads();
    const float tot = wsum[0] + wsum[1] + wsum[2] + wsum[3];
    const float r = rsqrtf(tot * (1.0f / HD) + 1e-6f);

    const bool is_txt = (s < S_TXT);
    const float* w = is_txt ? w_txt : w_img;
    const float nv = v * r * w[d];

    const float other = __shfl_xor_sync(0xffffffffu, nv, 1);
    const float rot = (d & 1) ? other : -other;

    const long long srel = is_txt ? s : (s - S_TXT);
    const float cc = (is_txt ? txt_cos : img_cos)[srel * HD + d];
    const float sn = (is_txt ? txt_sin : img_sin)[srel * HD + d];
    const float f = nv * cc + rot * sn;

    __half hh = __float2half_rn(f);
    hi[off + d] = hh;
    lo[off + d] = __float2half_rn(f - __half2float(hh));
}

// ---------------- V transpose: v[s, DIM] -> vt[head][d][s] fp16 --------------
__global__ void vtrans16(const float* __restrict__ v, __half* __restrict__ vt)
{
    __shared__ float tile[32][33];
    const int c0 = blockIdx.x * 32;
    const int s0 = blockIdx.y * 32;
    const int tx = threadIdx.x, ty = threadIdx.y;

    #pragma unroll
    for (int r = ty; r < 32; r += 8)
        tile[r][tx] = v[(long long)(s0 + r) * DIM + c0 + tx];
    __syncthreads();
    #pragma unroll
    for (int r = ty; r < 32; r += 8) {
        const int c = c0 + r;
        const int head = c >> 7, d = c & 127;
        vt[(long long)head * HD * S_TOT + (long long)d * S_TOT + s0 + tx] =
            __float2half_rn(tile[tx][r]);
    }
}

// ---------------- launch -----------------------------------------------------
extern "C" void kernel_launch(void* const* d_in, const int* in_sizes, int n_in,
                              void* d_out, int out_size)
{
    const float* hidden  = (const float*)d_in[0];
    const float* enc     = (const float*)d_in[1];
    const float* img_cos = (const float*)d_in[2];
    const float* img_sin = (const float*)d_in[3];
    const float* txt_cos = (const float*)d_in[4];
    const float* txt_sin = (const float*)d_in[5];

    const float *W[8];   // 0=Wq 1=Wk 2=Wv 3=Waq 4=Wak 5=Wav 6=Wo 7=Wao
    const float *bq, *bk, *bv, *baq, *bak, *bav, *bo, *bao;
    if (in_sizes[7] == DIM) {
        W[0] = (const float*)d_in[6];  bq  = (const float*)d_in[7];
        W[1] = (const float*)d_in[8];  bk  = (const float*)d_in[9];
        W[2] = (const float*)d_in[10]; bv  = (const float*)d_in[11];
        W[3] = (const float*)d_in[12]; baq = (const float*)d_in[13];
        W[4] = (const float*)d_in[14]; bak = (const float*)d_in[15];
        W[5] = (const float*)d_in[16]; bav = (const float*)d_in[17];
        W[6] = (const float*)d_in[18]; bo  = (const float*)d_in[19];
        W[7] = (const float*)d_in[20]; bao = (const float*)d_in[21];
    } else {
        for (int i = 0; i < 8; i++) W[i] = (const float*)d_in[6 + i];
        bq  = (const float*)d_in[14]; bk  = (const float*)d_in[15];
        bv  = (const float*)d_in[16]; baq = (const float*)d_in[17];
        bak = (const float*)d_in[18]; bav = (const float*)d_in[19];
        bo  = (const float*)d_in[20]; bao = (const float*)d_in[21];
    }
    const float* nq_w  = (const float*)d_in[22];
    const float* nk_w  = (const float*)d_in[23];
    const float* naq_w = (const float*)d_in[24];
    const float* nak_w = (const float*)d_in[25];

    static float *q, *k, *v;
    static __half *xh, *xl, *w16, *qh, *ql, *kh, *kl, *vt, *a16;
    static bool inited = false;
    if (!inited) {
        cudaGetSymbolAddress((void**)&q,   g_q);
        cudaGetSymbolAddress((void**)&k,   g_k);
        cudaGetSymbolAddress((void**)&v,   g_v);
        cudaGetSymbolAddress((void**)&xh,  g_xh);  cudaGetSymbolAddress((void**)&xl, g_xl);
        cudaGetSymbolAddress((void**)&w16, g_w16);
        cudaGetSymbolAddress((void**)&qh,  g_qh);  cudaGetSymbolAddress((void**)&ql, g_ql);
        cudaGetSymbolAddress((void**)&kh,  g_kh);  cudaGetSymbolAddress((void**)&kl, g_kl);
        cudaGetSymbolAddress((void**)&vt,  g_vt);
        cudaGetSymbolAddress((void**)&a16, g_a16);
        cudaFuncSetAttribute(mma_gemm2,  cudaFuncAttributeMaxDynamicSharedMemorySize, GSM);
        cudaFuncSetAttribute(mma_gemm_h, cudaFuncAttributeMaxDynamicSharedMemorySize, HSM);
        cudaFuncSetAttribute(flash_attn, cudaFuncAttributeMaxDynamicSharedMemorySize, FRING);
        inited = true;
    }

    // 1. conversions: x -> 2-term fp16;  all 8 weights -> fp16 (one launch)
    split_x16<<<(S_TOT * DIM) / 1024, 256>>>(hidden, enc, xh, xl);
    WPtrs wp; for (int i = 0; i < 8; i++) wp.p[i] = W[i];
    cvt_w16<<<dim3((int)(WSZ / 1024), 8), 256>>>(wp, w16);

    // 2. projections: Q,K 2-term fp16;  V single fp16 (A = xh)
    const dim3 gP(DIM / 128, S_TOT / 256, 1);   // (24, 10)
    mma_gemm2<<<gP, 256, GSM>>>(xh, xl, w16 + 0 * WSZ, w16 + 3 * WSZ, q, bq, baq);
    mma_gemm2<<<gP, 256, GSM>>>(xh, xl, w16 + 1 * WSZ, w16 + 4 * WSZ, k, bk, bak);
    mma_gemm_h<<<gP, 256, HSM>>>(xh, w16 + 2 * WSZ, w16 + 5 * WSZ, v, bv, bav, 0);

    // 3. RMSNorm + RoPE -> fp16 pairs;  V transpose -> fp16
    const dim3 gNR(S_TOT, HEADS);
    norm_rope16<<<gNR, 128>>>(q, qh, ql, naq_w, nq_w, txt_cos, txt_sin, img_cos, img_sin);
    norm_rope16<<<gNR, 128>>>(k, kh, kl, nak_w, nk_w, txt_cos, txt_sin, img_cos, img_sin);
    vtrans16<<<dim3(DIM / 32, S_TOT / 32), dim3(32, 8)>>>(v, vt);

    // 4. fused attention -> fp16 attn
    flash_attn<<<dim3(S_TOT / 128, HEADS), 256, FRING>>>(qh, ql, kh, vt, a16);

    // 5. output projection (fp16; txt rows -> Wao/bao, remapped: img first)
    mma_gemm_h<<<gP, 256, HSM>>>(a16, w16 + 6 * WSZ, w16 + 7 * WSZ,
        (float*)d_out, bo, bao, 1);
}

// round 8
// speedup vs baseline: 4.9666x; 1.0442x over previous
#include <cuda_runtime.h>
#include <cuda_fp16.h>
#include <cstdint>
#include <math.h>

#define HEADS 24
#define HD    128
#define DIM   3072
#define S_IMG 2048
#define S_TXT 512
#define S_TOT 2560
#define WSZ   ((size_t)DIM * DIM)

// ---------------- scratch (static device memory; no allocations) ------------
__device__ float g_q[(size_t)S_TOT * DIM];
__device__ float g_k[(size_t)S_TOT * DIM];
__device__ float g_v[(size_t)S_TOT * DIM];

__device__ __half g_xh[(size_t)S_TOT * DIM], g_xl[(size_t)S_TOT * DIM];
__device__ __half g_w16[8 * WSZ];            // Wq Wk Wv Waq Wak Wav Wo Wao
__device__ __half g_qh[(size_t)S_TOT * DIM], g_ql[(size_t)S_TOT * DIM];
__device__ __half g_kh[(size_t)S_TOT * DIM], g_kl[(size_t)S_TOT * DIM];
__device__ __half g_vt[(size_t)HEADS * HD * S_TOT];
__device__ __half g_a16[(size_t)S_TOT * DIM];

// ---------------- helpers ----------------------------------------------------
__device__ __forceinline__ uint32_t smem_u32(const void* p) {
    return (uint32_t)__cvta_generic_to_shared(p);
}

__device__ __forceinline__ void cp16(uint32_t dst, const void* src) {
    asm volatile("cp.async.cg.shared.global [%0], [%1], 16;" :: "r"(dst), "l"(src));
}

__device__ __forceinline__ void ldm_x4(uint32_t* r, uint32_t addr) {
    asm volatile("ldmatrix.sync.aligned.m8n8.x4.shared.b16 {%0,%1,%2,%3}, [%4];"
                 : "=r"(r[0]), "=r"(r[1]), "=r"(r[2]), "=r"(r[3]) : "r"(addr));
}

__device__ __forceinline__ void mma16816h(float* c, const uint32_t* a, uint32_t b0, uint32_t b1) {
    asm volatile(
        "mma.sync.aligned.m16n8k16.row.col.f32.f16.f16.f32 "
        "{%0,%1,%2,%3}, {%4,%5,%6,%7}, {%8,%9}, {%0,%1,%2,%3};"
        : "+f"(c[0]), "+f"(c[1]), "+f"(c[2]), "+f"(c[3])
        : "r"(a[0]), "r"(a[1]), "r"(a[2]), "r"(a[3]), "r"(b0), "r"(b1));
}

// pack (a,b) into fp16x2 hi fragment and residual lo fragment  (~22-bit pair)
__device__ __forceinline__ void packhl16(float a, float b, uint32_t& hi, uint32_t& lo) {
    __half ah = __float2half_rn(a), bh = __float2half_rn(b);
    __half2 H; H.x = ah; H.y = bh;
    hi = *reinterpret_cast<uint32_t*>(&H);
    __half2 L;
    L.x = __float2half_rn(a - __half2float(ah));
    L.y = __float2half_rn(b - __half2float(bh));
    lo = *reinterpret_cast<uint32_t*>(&L);
}

// ---------------- 2-term fp16 GEMM (128x128 tile, 2 CTAs/SM) -----------------
// C = (Ah + Al) * B^T + bias.  Rows m < S_TXT take (B2, bias2).
#define G2T 10240              /* 128 rows * 80 B */
#define G2BUF (3 * G2T)        /* Ah Al B = 30720 */
#define G2SM  (2 * G2BUF)      /* 61440 */
__global__ __launch_bounds__(256, 2) void mma_gemm2(
    const __half* __restrict__ Ah, const __half* __restrict__ Al,
    const __half* __restrict__ B, const __half* __restrict__ B2,
    float* __restrict__ C,
    const float* __restrict__ bias, const float* __restrict__ bias2)
{
    extern __shared__ char smem[];
    const uint32_t sb = smem_u32(smem);
    const int tid = threadIdx.x;
    const int wid = tid >> 5;
    const int lane = tid & 31;
    const int wm = wid & 3;           // 4 warps x 32 rows
    const int wn = wid >> 2;          // 2 warps x 64 cols

    const int m0 = blockIdx.y * 128;
    const int n0 = blockIdx.x * 128;
    const bool alt = (m0 < S_TXT);
    const __half* bsrc = alt ? B2 : B;

    float acc[2][8][4];
    #pragma unroll
    for (int mi = 0; mi < 2; mi++)
        #pragma unroll
        for (int ni = 0; ni < 8; ni++)
            #pragma unroll
            for (int j = 0; j < 4; j++) acc[mi][ni][j] = 0.f;

    auto issue = [&](int c) {
        const uint32_t base = sb + (uint32_t)((c & 1) * G2BUF);
        const int k0 = c * 32;
        #pragma unroll
        for (int i = 0; i < 6; i++) {
            const int idx = i * 256 + tid;            // 0..1535
            const int arr = idx >> 9;                 // 0=Ah 1=Al 2=B
            const int rem = idx & 511;
            const int r = rem >> 2, s4 = rem & 3;
            const __half* s = (arr == 0) ? Ah : (arr == 1) ? Al : bsrc;
            const int rbase = (arr == 2) ? n0 : m0;
            cp16(base + (uint32_t)(arr * G2T + r * 80 + s4 * 16),
                 s + (long long)(rbase + r) * DIM + k0 + s4 * 8);
        }
    };

    const int nc = DIM / 32;   // 96
    issue(0);
    asm volatile("cp.async.commit_group;" ::: "memory");

    for (int c = 0; c < nc; c++) {
        if (c + 1 < nc) issue(c + 1);
        asm volatile("cp.async.commit_group;" ::: "memory");
        asm volatile("cp.async.wait_group 1;" ::: "memory");
        __syncthreads();

        const uint32_t base = sb + (uint32_t)((c & 1) * G2BUF);
        const uint32_t aH = base, aL = base + G2T, bB = base + 2 * G2T;

        #pragma unroll
        for (int ks = 0; ks < 2; ks++) {
            uint32_t ah4[2][4], al4[2][4];
            const uint32_t arow = (uint32_t)(wm * 32 + (lane & 15));
            const uint32_t akof = (uint32_t)((ks * 2 + (lane >> 4)) * 16);
            #pragma unroll
            for (int mi = 0; mi < 2; mi++) {
                const uint32_t aoff = (arow + mi * 16) * 80 + akof;
                ldm_x4(ah4[mi], aH + aoff);
                ldm_x4(al4[mi], aL + aoff);
            }
            const uint32_t bn = (uint32_t)(wn * 64 + ((lane >> 4) << 3) + (lane & 7));
            const uint32_t bkof = (uint32_t)((ks * 2 + ((lane >> 3) & 1)) * 16);
            #pragma unroll
            for (int njp = 0; njp < 4; njp++) {
                uint32_t b4[4];
                ldm_x4(b4, bB + (bn + njp * 16) * 80 + bkof);
                #pragma unroll
                for (int sub = 0; sub < 2; sub++) {
                    const int ni = njp * 2 + sub;
                    #pragma unroll
                    for (int mi = 0; mi < 2; mi++) {
                        mma16816h(acc[mi][ni], ah4[mi], b4[sub * 2], b4[sub * 2 + 1]);
                        mma16816h(acc[mi][ni], al4[mi], b4[sub * 2], b4[sub * 2 + 1]);
                    }
                }
            }
        }
        __syncthreads();
    }

    const float* bp = alt ? bias2 : bias;
    #pragma unroll
    for (int mi = 0; mi < 2; mi++) {
        const int rb = m0 + wm * 32 + mi * 16 + (lane >> 2);
        #pragma unroll
        for (int half = 0; half < 2; half++) {
            const int r = rb + half * 8;
            float* crow = C + (long long)r * DIM;
            #pragma unroll
            for (int ni = 0; ni < 8; ni++) {
                const int col = n0 + wn * 64 + ni * 8 + (lane & 3) * 2;
                float2 o;
                o.x = acc[mi][ni][half * 2 + 0] + bp[col];
                o.y = acc[mi][ni][half * 2 + 1] + bp[col + 1];
                *reinterpret_cast<float2*>(crow + col) = o;
            }
        }
    }
}

// ---------------- fp16 single-term GEMM (128x128 tile, 2 CTAs/SM) ------------
#define HT  10240
#define HBUF (2 * HT)          /* A B = 20480 */
#define HSM  (2 * HBUF)        /* 40960 */
__global__ __launch_bounds__(256, 2) void mma_gemm_h(
    const __half* __restrict__ A,
    const __half* __restrict__ B, const __half* __restrict__ B2,
    float* __restrict__ C,
    const float* __restrict__ bias, const float* __restrict__ bias2, int remap)
{
    extern __shared__ char smem[];
    const uint32_t sb = smem_u32(smem);
    const int tid = threadIdx.x;
    const int wid = tid >> 5;
    const int lane = tid & 31;
    const int wm = wid & 3;
    const int wn = wid >> 2;

    const int m0 = blockIdx.y * 128;
    const int n0 = blockIdx.x * 128;
    const bool alt = (m0 < S_TXT);
    const __half* bsrc = alt ? B2 : B;

    float acc[2][8][4];
    #pragma unroll
    for (int mi = 0; mi < 2; mi++)
        #pragma unroll
        for (int ni = 0; ni < 8; ni++)
            #pragma unroll
            for (int j = 0; j < 4; j++) acc[mi][ni][j] = 0.f;

    auto issue = [&](int c) {
        const uint32_t base = sb + (uint32_t)((c & 1) * HBUF);
        const int k0 = c * 32;
        #pragma unroll
        for (int i = 0; i < 4; i++) {
            const int idx = i * 256 + tid;            // 0..1023
            const int arr = idx >> 9;                 // 0=A 1=B
            const int rem = idx & 511;
            const int r = rem >> 2, s4 = rem & 3;
            const __half* s = arr ? bsrc : A;
            const int rbase = arr ? n0 : m0;
            cp16(base + (uint32_t)(arr * HT + r * 80 + s4 * 16),
                 s + (long long)(rbase + r) * DIM + k0 + s4 * 8);
        }
    };

    const int nc = DIM / 32;
    issue(0);
    asm volatile("cp.async.commit_group;" ::: "memory");

    for (int c = 0; c < nc; c++) {
        if (c + 1 < nc) issue(c + 1);
        asm volatile("cp.async.commit_group;" ::: "memory");
        asm volatile("cp.async.wait_group 1;" ::: "memory");
        __syncthreads();

        const uint32_t base = sb + (uint32_t)((c & 1) * HBUF);
        const uint32_t aB = base, bB = base + HT;

        #pragma unroll
        for (int ks = 0; ks < 2; ks++) {
            uint32_t a4[2][4];
            const uint32_t arow = (uint32_t)(wm * 32 + (lane & 15));
            const uint32_t akof = (uint32_t)((ks * 2 + (lane >> 4)) * 16);
            #pragma unroll
            for (int mi = 0; mi < 2; mi++)
                ldm_x4(a4[mi], aB + (arow + mi * 16) * 80 + akof);

            const uint32_t bn = (uint32_t)(wn * 64 + ((lane >> 4) << 3) + (lane & 7));
            const uint32_t bkof = (uint32_t)((ks * 2 + ((lane >> 3) & 1)) * 16);
            #pragma unroll
            for (int njp = 0; njp < 4; njp++) {
                uint32_t b4[4];
                ldm_x4(b4, bB + (bn + njp * 16) * 80 + bkof);
                #pragma unroll
                for (int sub = 0; sub < 2; sub++) {
                    const int ni = njp * 2 + sub;
                    #pragma unroll
                    for (int mi = 0; mi < 2; mi++)
                        mma16816h(acc[mi][ni], a4[mi], b4[sub * 2], b4[sub * 2 + 1]);
                }
            }
        }
        __syncthreads();
    }

    const float* bp = alt ? bias2 : bias;
    #pragma unroll
    for (int mi = 0; mi < 2; mi++) {
        const int rb = m0 + wm * 32 + mi * 16 + (lane >> 2);
        #pragma unroll
        for (int half = 0; half < 2; half++) {
            const int r = rb + half * 8;
            long long orow = r;
            if (remap) orow = (r < S_TXT) ? (long long)(S_IMG + r) : (long long)(r - S_TXT);
            float* crow = C + orow * DIM;
            #pragma unroll
            for (int ni = 0; ni < 8; ni++) {
                const int col = n0 + wn * 64 + ni * 8 + (lane & 3) * 2;
                float2 o;
                o.x = acc[mi][ni][half * 2 + 0] + bp[col];
                o.y = acc[mi][ni][half * 2 + 1] + bp[col + 1];
                *reinterpret_cast<float2*>(crow + col) = o;
            }
        }
    }
}

// ---------------- flash attention (fused scores+softmax+PV, fp16) ------------
#define FB    10240            /* ring slot: one 128x32 fp16 tile */
#define FRING (4 * FB)         /* 40960 */
#define NBLK  (S_TOT / 128)    /* 20 */
#define NITEM (NBLK * 8)
__global__ __launch_bounds__(256) void flash_attn(
    const __half* __restrict__ qhp, const __half* __restrict__ qlp,
    const __half* __restrict__ khp,
    const __half* __restrict__ vtp,
    __half* __restrict__ a16)
{
    extern __shared__ char smem[];
    const uint32_t sb = smem_u32(smem);
    const int tid = threadIdx.x, wid = tid >> 5, lane = tid & 31;
    const int qm0 = blockIdx.x * 128;
    const int h = blockIdx.y;

    // ---- Q fragments (hi/lo) into registers, staged through ring area ------
    uint32_t qh[8][4], ql[8][4];
    #pragma unroll
    for (int pass = 0; pass < 2; pass++) {
        const __half* src = pass ? qlp : qhp;
        #pragma unroll
        for (int i = 0; i < 8; i++) {
            const int idx = i * 256 + tid;               // 0..2047
            const int r = idx >> 4, seg = idx & 15;
            cp16(sb + (uint32_t)((seg >> 2) * FB + r * 80 + (seg & 3) * 16),
                 src + (long long)(qm0 + r) * DIM + h * HD + seg * 8);
        }
        asm volatile("cp.async.commit_group;" ::: "memory");
        asm volatile("cp.async.wait_group 0;" ::: "memory");
        __syncthreads();
        #pragma unroll
        for (int j = 0; j < 8; j++) {
            const uint32_t addr = sb + (uint32_t)((j >> 1) * FB
                + (wid * 16 + (lane & 15)) * 80 + ((j & 1) * 2 + (lane >> 4)) * 16);
            if (pass == 0) ldm_x4(qh[j], addr);
            else           ldm_x4(ql[j], addr);
        }
        __syncthreads();
    }

    float oacc[16][4];
    #pragma unroll
    for (int di = 0; di < 16; di++)
        #pragma unroll
        for (int j = 0; j < 4; j++) oacc[di][j] = 0.f;
    float sacc[16][4];
    uint32_t ph[8][4], pl[8][4];
    float m0r = -1e30f, m1r = -1e30f, l0 = 0.f, l1 = 0.f;

    auto issue_item = [&](int j) {
        const int t = j >> 3, sub = j & 7, pc = sub & 3;
        const uint32_t slot = sb + (uint32_t)((j & 3) * FB);
        if ((sub >> 2) == 0) {            // K chunk pc of s-block t
            #pragma unroll
            for (int i = 0; i < 2; i++) {
                const int idx = i * 256 + tid;
                const int r = idx >> 2, s4 = idx & 3;
                cp16(slot + (uint32_t)(r * 80 + s4 * 16),
                     khp + (long long)(t * 128 + r) * DIM + h * HD + pc * 32 + s4 * 8);
            }
        } else {                          // V^T chunk pc of s-block t
            #pragma unroll
            for (int i = 0; i < 2; i++) {
                const int idx = i * 256 + tid;
                const int r = idx >> 2, s4 = idx & 3;
                cp16(slot + (uint32_t)(r * 80 + s4 * 16),
                     vtp + (long long)(h * 128 + r) * S_TOT + t * 128 + pc * 32 + s4 * 8);
            }
        }
    };

    issue_item(0); asm volatile("cp.async.commit_group;" ::: "memory");
    issue_item(1); asm volatile("cp.async.commit_group;" ::: "memory");
    issue_item(2); asm volatile("cp.async.commit_group;" ::: "memory");

    const uint32_t bnrow = (uint32_t)(((lane >> 4) << 3) + (lane & 7));
    const uint32_t bksel = (uint32_t)((lane >> 3) & 1);

    for (int j = 0; j < NITEM; j++) {
        if (j + 3 < NITEM) issue_item(j + 3);
        asm volatile("cp.async.commit_group;" ::: "memory");
        asm volatile("cp.async.wait_group 3;" ::: "memory");
        __syncthreads();

        const int sub = j & 7, phase = sub >> 2, c = sub & 3;
        const uint32_t slot = sb + (uint32_t)((j & 3) * FB);

        if (phase == 0) {
            if (c == 0) {
                #pragma unroll
                for (int ni = 0; ni < 16; ni++)
                    #pragma unroll
                    for (int jj = 0; jj < 4; jj++) sacc[ni][jj] = 0.f;
            }
            #pragma unroll
            for (int ks2 = 0; ks2 < 2; ks2++) {
                const int j8 = c * 2 + ks2;
                const uint32_t kof = (uint32_t)((ks2 * 2 + bksel) * 16);
                #pragma unroll
                for (int njp = 0; njp < 8; njp++) {
                    uint32_t b4[4];
                    ldm_x4(b4, slot + (njp * 16 + bnrow) * 80 + kof);
                    #pragma unroll
                    for (int s2 = 0; s2 < 2; s2++) {
                        const int ni = njp * 2 + s2;
                        mma16816h(sacc[ni], qh[j8], b4[s2 * 2], b4[s2 * 2 + 1]);
                        mma16816h(sacc[ni], ql[j8], b4[s2 * 2], b4[s2 * 2 + 1]);
                    }
                }
            }
            if (c == 3) {
                // ---- online softmax over this 128-col S block --------------
                const float sc = 0.08838834764831845f;
                float mb0 = -1e30f, mb1 = -1e30f;
                #pragma unroll
                for (int ni = 0; ni < 16; ni++) {
                    sacc[ni][0] *= sc; sacc[ni][1] *= sc;
                    sacc[ni][2] *= sc; sacc[ni][3] *= sc;
                    mb0 = fmaxf(mb0, fmaxf(sacc[ni][0], sacc[ni][1]));
                    mb1 = fmaxf(mb1, fmaxf(sacc[ni][2], sacc[ni][3]));
                }
                mb0 = fmaxf(mb0, __shfl_xor_sync(0xffffffffu, mb0, 1));
                mb0 = fmaxf(mb0, __shfl_xor_sync(0xffffffffu, mb0, 2));
                mb1 = fmaxf(mb1, __shfl_xor_sync(0xffffffffu, mb1, 1));
                mb1 = fmaxf(mb1, __shfl_xor_sync(0xffffffffu, mb1, 2));
                const float mn0 = fmaxf(m0r, mb0), mn1 = fmaxf(m1r, mb1);
                const float a0 = __expf(m0r - mn0), a1 = __expf(m1r - mn1);
                m0r = mn0; m1r = mn1;
                l0 *= a0; l1 *= a1;
                #pragma unroll
                for (int di = 0; di < 16; di++) {
                    oacc[di][0] *= a0; oacc[di][1] *= a0;
                    oacc[di][2] *= a1; oacc[di][3] *= a1;
                }
                float rs0 = 0.f, rs1 = 0.f;
                #pragma unroll
                for (int ni = 0; ni < 16; ni++) {
                    const float p0 = __expf(sacc[ni][0] - mn0);
                    const float p1 = __expf(sacc[ni][1] - mn0);
                    const float p2 = __expf(sacc[ni][2] - mn1);
                    const float p3 = __expf(sacc[ni][3] - mn1);
                    rs0 += p0 + p1; rs1 += p2 + p3;
                    const int j8 = ni >> 1;
                    if ((ni & 1) == 0) {
                        packhl16(p0, p1, ph[j8][0], pl[j8][0]);
                        packhl16(p2, p3, ph[j8][1], pl[j8][1]);
                    } else {
                        packhl16(p0, p1, ph[j8][2], pl[j8][2]);
                        packhl16(p2, p3, ph[j8][3], pl[j8][3]);
                    }
                }
                l0 += rs0; l1 += rs1;
            }
        } else {
            // ---- O += P * V --------------------------------------------------
            #pragma unroll
            for (int ks2 = 0; ks2 < 2; ks2++) {
                const int j8 = c * 2 + ks2;
                const uint32_t kof = (uint32_t)((ks2 * 2 + bksel) * 16);
                #pragma unroll
                for (int djp = 0; djp < 8; djp++) {
                    uint32_t b4[4];
                    ldm_x4(b4, slot + (djp * 16 + bnrow) * 80 + kof);
                    #pragma unroll
                    for (int s2 = 0; s2 < 2; s2++) {
                        const int di = djp * 2 + s2;
                        mma16816h(oacc[di], ph[j8], b4[s2 * 2], b4[s2 * 2 + 1]);
                        mma16816h(oacc[di], pl[j8], b4[s2 * 2], b4[s2 * 2 + 1]);
                    }
                }
            }
        }
        __syncthreads();
    }

    // ---- normalize and store fp16 ------------------------------------------
    l0 += __shfl_xor_sync(0xffffffffu, l0, 1);
    l0 += __shfl_xor_sync(0xffffffffu, l0, 2);
    l1 += __shfl_xor_sync(0xffffffffu, l1, 1);
    l1 += __shfl_xor_sync(0xffffffffu, l1, 2);
    const float i0 = 1.0f / l0, i1 = 1.0f / l1;
    const int r0 = qm0 + wid * 16 + (lane >> 2);
    const int r1 = r0 + 8;
    #pragma unroll
    for (int di = 0; di < 16; di++) {
        const int col = h * HD + di * 8 + (lane & 3) * 2;
        __half2 o0 = __floats2half2_rn(oacc[di][0] * i0, oacc[di][1] * i0);
        __half2 o1 = __floats2half2_rn(oacc[di][2] * i1, oacc[di][3] * i1);
        *reinterpret_cast<__half2*>(a16 + (long long)r0 * DIM + col) = o0;
        *reinterpret_cast<__half2*>(a16 + (long long)r1 * DIM + col) = o1;
    }
}

// ---------------- conversion kernels -----------------------------------------
__global__ void split_x16(const float* __restrict__ hidden, const float* __restrict__ enc,
                          __half* __restrict__ hi, __half* __restrict__ lo) {
    const long long i4 = ((long long)blockIdx.x * 256 + threadIdx.x) * 4;
    const long long row = i4 / DIM;
    const float* src = (row < S_TXT) ? (enc + i4) : (hidden + i4 - (long long)S_TXT * DIM);
    const float4 v = *reinterpret_cast<const float4*>(src);
    __half h0 = __float2half_rn(v.x), h1 = __float2half_rn(v.y);
    __half h2 = __float2half_rn(v.z), h3 = __float2half_rn(v.w);
    __half2 a; a.x = h0; a.y = h1;
    __half2 b; b.x = h2; b.y = h3;
    *reinterpret_cast<__half2*>(hi + i4)     = a;
    *reinterpret_cast<__half2*>(hi + i4 + 2) = b;
    __half2 c; c.x = __float2half_rn(v.x - __half2float(h0));
               c.y = __float2half_rn(v.y - __half2float(h1));
    __half2 d; d.x = __float2half_rn(v.z - __half2float(h2));
               d.y = __float2half_rn(v.w - __half2float(h3));
    *reinterpret_cast<__half2*>(lo + i4)     = c;
    *reinterpret_cast<__half2*>(lo + i4 + 2) = d;
}

struct WPtrs { const float* p[8]; };
__global__ void cvt_w16(WPtrs W, __half* __restrict__ dst) {
    const long long i4 = ((long long)blockIdx.x * 256 + threadIdx.x) * 4;
    const float* src = W.p[blockIdx.y];
    __half* d = dst + (size_t)blockIdx.y * WSZ;
    const float4 v = *reinterpret_cast<const float4*>(src + i4);
    *reinterpret_cast<__half2*>(d + i4)     = __floats2half2_rn(v.x, v.y);
    *reinterpret_cast<__half2*>(d + i4 + 2) = __floats2half2_rn(v.z, v.w);
}

// ---------------- RMSNorm + RoPE -> fp16 hi/lo -------------------------------
__global__ void norm_rope16(
    const float* __restrict__ x,
    __half* __restrict__ hi, __half* __restrict__ lo,
    const float* __restrict__ w_txt, const float* __restrict__ w_img,
    const float* __restrict__ txt_cos, const float* __restrict__ txt_sin,
    const float* __restrict__ img_cos, const float* __restrict__ img_sin)
{
    const int s = blockIdx.x;
    const int h = blockIdx.y;
    const int d = threadIdx.x;
    const long long off = (long long)s * DIM + h * HD;

    float v = x[off + d];
    float ss = v * v;
    #pragma unroll
    for (int o = 16; o > 0; o >>= 1) ss += __shfl_xor_sync(0xffffffffu, ss, o);
    __shared__ float wsum[4];
    if ((d & 31) == 0) wsum[d >> 5] = ss;
    __syncthreads();
    const float tot = wsum[0] + wsum[1] + wsum[2] + wsum[3];
    const float r = rsqrtf(tot * (1.0f / HD) + 1e-6f);

    const bool is_txt = (s < S_TXT);
    const float* w = is_txt ? w_txt : w_img;
    const float nv = v * r * w[d];

    const float other = __shfl_xor_sync(0xffffffffu, nv, 1);
    const float rot = (d & 1) ? other : -other;

    const long long srel = is_txt ? s : (s - S_TXT);
    const float cc = (is_txt ? txt_cos : img_cos)[srel * HD + d];
    const float sn = (is_txt ? txt_sin : img_sin)[srel * HD + d];
    const float f = nv * cc + rot * sn;

    __half hh = __float2half_rn(f);
    hi[off + d] = hh;
    lo[off + d] = __float2half_rn(f - __half2float(hh));
}

// ---------------- V transpose: v[s, DIM] -> vt[head][d][s] fp16 --------------
__global__ void vtrans16(const float* __restrict__ v, __half* __restrict__ vt)
{
    __shared__ float tile[32][33];
    const int c0 = blockIdx.x * 32;
    const int s0 = blockIdx.y * 32;
    const int tx = threadIdx.x, ty = threadIdx.y;

    #pragma unroll
    for (int r = ty; r < 32; r += 8)
        tile[r][tx] = v[(long long)(s0 + r) * DIM + c0 + tx];
    __syncthreads();
    #pragma unroll
    for (int r = ty; r < 32; r += 8) {
        const int c = c0 + r;
        const int head = c >> 7, d = c & 127;
        vt[(long long)head * HD * S_TOT + (long long)d * S_TOT + s0 + tx] =
            __float2half_rn(tile[tx][r]);
    }
}

// ---------------- launch -----------------------------------------------------
extern "C" void kernel_launch(void* const* d_in, const int* in_sizes, int n_in,
                              void* d_out, int out_size)
{
    const float* hidden  = (const float*)d_in[0];
    const float* enc     = (const float*)d_in[1];
    const float* img_cos = (const float*)d_in[2];
    const float* img_sin = (const float*)d_in[3];
    const float* txt_cos = (const float*)d_in[4];
    const float* txt_sin = (const float*)d_in[5];

    const float *W[8];   // 0=Wq 1=Wk 2=Wv 3=Waq 4=Wak 5=Wav 6=Wo 7=Wao
    const float *bq, *bk, *bv, *baq, *bak, *bav, *bo, *bao;
    if (in_sizes[7] == DIM) {
        W[0] = (const float*)d_in[6];  bq  = (const float*)d_in[7];
        W[1] = (const float*)d_in[8];  bk  = (const float*)d_in[9];
        W[2] = (const float*)d_in[10]; bv  = (const float*)d_in[11];
        W[3] = (const float*)d_in[12]; baq = (const float*)d_in[13];
        W[4] = (const float*)d_in[14]; bak = (const float*)d_in[15];
        W[5] = (const float*)d_in[16]; bav = (const float*)d_in[17];
        W[6] = (const float*)d_in[18]; bo  = (const float*)d_in[19];
        W[7] = (const float*)d_in[20]; bao = (const float*)d_in[21];
    } else {
        for (int i = 0; i < 8; i++) W[i] = (const float*)d_in[6 + i];
        bq  = (const float*)d_in[14]; bk  = (const float*)d_in[15];
        bv  = (const float*)d_in[16]; baq = (const float*)d_in[17];
        bak = (const float*)d_in[18]; bav = (const float*)d_in[19];
        bo  = (const float*)d_in[20]; bao = (const float*)d_in[21];
    }
    const float* nq_w  = (const float*)d_in[22];
    const float* nk_w  = (const float*)d_in[23];
    const float* naq_w = (const float*)d_in[24];
    const float* nak_w = (const float*)d_in[25];

    static float *q, *k, *v;
    static __half *xh, *xl, *w16, *qh, *ql, *kh, *kl, *vt, *a16;
    static bool inited = false;
    if (!inited) {
        cudaGetSymbolAddress((void**)&q,   g_q);
        cudaGetSymbolAddress((void**)&k,   g_k);
        cudaGetSymbolAddress((void**)&v,   g_v);
        cudaGetSymbolAddress((void**)&xh,  g_xh);  cudaGetSymbolAddress((void**)&xl, g_xl);
        cudaGetSymbolAddress((void**)&w16, g_w16);
        cudaGetSymbolAddress((void**)&qh,  g_qh);  cudaGetSymbolAddress((void**)&ql, g_ql);
        cudaGetSymbolAddress((void**)&kh,  g_kh);  cudaGetSymbolAddress((void**)&kl, g_kl);
        cudaGetSymbolAddress((void**)&vt,  g_vt);
        cudaGetSymbolAddress((void**)&a16, g_a16);
        cudaFuncSetAttribute(mma_gemm2,  cudaFuncAttributeMaxDynamicSharedMemorySize, G2SM);
        cudaFuncSetAttribute(mma_gemm_h, cudaFuncAttributeMaxDynamicSharedMemorySize, HSM);
        cudaFuncSetAttribute(flash_attn, cudaFuncAttributeMaxDynamicSharedMemorySize, FRING);
        inited = true;
    }

    // 1. conversions: x -> 2-term fp16;  all 8 weights -> fp16 (one launch)
    split_x16<<<(S_TOT * DIM) / 1024, 256>>>(hidden, enc, xh, xl);
    WPtrs wp; for (int i = 0; i < 8; i++) wp.p[i] = W[i];
    cvt_w16<<<dim3((int)(WSZ / 1024), 8), 256>>>(wp, w16);

    // 2. projections: Q,K 2-term fp16;  V single fp16 (A = xh)
    const dim3 gP(DIM / 128, S_TOT / 128, 1);   // (24, 20)
    mma_gemm2<<<gP, 256, G2SM>>>(xh, xl, w16 + 0 * WSZ, w16 + 3 * WSZ, q, bq, baq);
    mma_gemm2<<<gP, 256, G2SM>>>(xh, xl, w16 + 1 * WSZ, w16 + 4 * WSZ, k, bk, bak);
    mma_gemm_h<<<gP, 256, HSM>>>(xh, w16 + 2 * WSZ, w16 + 5 * WSZ, v, bv, bav, 0);

    // 3. RMSNorm + RoPE -> fp16 pairs;  V transpose -> fp16
    const dim3 gNR(S_TOT, HEADS);
    norm_rope16<<<gNR, 128>>>(q, qh, ql, naq_w, nq_w, txt_cos, txt_sin, img_cos, img_sin);
    norm_rope16<<<gNR, 128>>>(k, kh, kl, nak_w, nk_w, txt_cos, txt_sin, img_cos, img_sin);
    vtrans16<<<dim3(DIM / 32, S_TOT / 32), dim3(32, 8)>>>(v, vt);

    // 4. fused attention -> fp16 attn
    flash_attn<<<dim3(S_TOT / 128, HEADS), 256, FRING>>>(qh, ql, kh, vt, a16);

    // 5. output projection (fp16; txt rows -> Wao/bao, remapped: img first)
    mma_gemm_h<<<gP, 256, HSM>>>(a16, w16 + 6 * WSZ, w16 + 7 * WSZ,
        (float*)d_out, bo, bao, 1);
}

// round 9
// speedup vs baseline: 6.4735x; 1.3034x over previous
#include <cuda_runtime.h>
#include <cuda_fp16.h>
#include <cstdint>
#include <math.h>

#define HEADS 24
#define HD    128
#define DIM   3072
#define S_IMG 2048
#define S_TXT 512
#define S_TOT 2560
#define WSZ   ((size_t)DIM * DIM)

// ---------------- scratch (static device memory; no allocations) ------------
__device__ float g_q[(size_t)S_TOT * DIM];
__device__ float g_k[(size_t)S_TOT * DIM];
__device__ float g_v[(size_t)S_TOT * DIM];

__device__ __half g_x16[(size_t)S_TOT * DIM];
__device__ __half g_w16[8 * WSZ];            // Wq Wk Wv Waq Wak Wav Wo Wao
__device__ __half g_q16[(size_t)S_TOT * DIM];
__device__ __half g_k16[(size_t)S_TOT * DIM];
__device__ __half g_vt[(size_t)HEADS * HD * S_TOT];
__device__ __half g_a16[(size_t)S_TOT * DIM];

// ---------------- helpers ----------------------------------------------------
__device__ __forceinline__ uint32_t smem_u32(const void* p) {
    return (uint32_t)__cvta_generic_to_shared(p);
}

__device__ __forceinline__ void cp16(uint32_t dst, const void* src) {
    asm volatile("cp.async.cg.shared.global [%0], [%1], 16;" :: "r"(dst), "l"(src));
}

__device__ __forceinline__ void ldm_x4(uint32_t* r, uint32_t addr) {
    asm volatile("ldmatrix.sync.aligned.m8n8.x4.shared.b16 {%0,%1,%2,%3}, [%4];"
                 : "=r"(r[0]), "=r"(r[1]), "=r"(r[2]), "=r"(r[3]) : "r"(addr));
}

__device__ __forceinline__ void mma16816h(float* c, const uint32_t* a, uint32_t b0, uint32_t b1) {
    asm volatile(
        "mma.sync.aligned.m16n8k16.row.col.f32.f16.f16.f32 "
        "{%0,%1,%2,%3}, {%4,%5,%6,%7}, {%8,%9}, {%0,%1,%2,%3};"
        : "+f"(c[0]), "+f"(c[1]), "+f"(c[2]), "+f"(c[3])
        : "r"(a[0]), "r"(a[1]), "r"(a[2]), "r"(a[3]), "r"(b0), "r"(b1));
}

// ---------------- fp16 GEMM (128x128 tile, 2 CTAs/SM, 3-stage pipeline) ------
// C = A * B^T + bias.  Rows m < S_TXT take (B2, bias2).
// remap=1 relocates output rows (img block first).
#define HT   10240             /* 128 rows * 80 B */
#define HBUF (2 * HT)          /* A B = 20480 */
#define HSM  (3 * HBUF)        /* 61440, 3 stages */
__global__ __launch_bounds__(256, 2) void mma_gemm_h(
    const __half* __restrict__ A,
    const __half* __restrict__ B, const __half* __restrict__ B2,
    float* __restrict__ C,
    const float* __restrict__ bias, const float* __restrict__ bias2, int remap)
{
    extern __shared__ char smem[];
    const uint32_t sb = smem_u32(smem);
    const int tid = threadIdx.x;
    const int wid = tid >> 5;
    const int lane = tid & 31;
    const int wm = wid & 3;           // 4 warps x 32 rows
    const int wn = wid >> 2;          // 2 warps x 64 cols

    const int m0 = blockIdx.y * 128;
    const int n0 = blockIdx.x * 128;
    const bool alt = (m0 < S_TXT);
    const __half* bsrc = alt ? B2 : B;

    float acc[2][8][4];
    #pragma unroll
    for (int mi = 0; mi < 2; mi++)
        #pragma unroll
        for (int ni = 0; ni < 8; ni++)
            #pragma unroll
            for (int j = 0; j < 4; j++) acc[mi][ni][j] = 0.f;

    auto issue = [&](int c) {
        const uint32_t base = sb + (uint32_t)((c % 3) * HBUF);
        const int k0 = c * 32;
        #pragma unroll
        for (int i = 0; i < 4; i++) {
            const int idx = i * 256 + tid;            // 0..1023
            const int arr = idx >> 9;                 // 0=A 1=B
            const int rem = idx & 511;
            const int r = rem >> 2, s4 = rem & 3;
            const __half* s = arr ? bsrc : A;
            const int rbase = arr ? n0 : m0;
            cp16(base + (uint32_t)(arr * HT + r * 80 + s4 * 16),
                 s + (long long)(rbase + r) * DIM + k0 + s4 * 8);
        }
    };

    const int nc = DIM / 32;  // 96
    issue(0); asm volatile("cp.async.commit_group;" ::: "memory");
    issue(1); asm volatile("cp.async.commit_group;" ::: "memory");

    for (int c = 0; c < nc; c++) {
        asm volatile("cp.async.wait_group 1;" ::: "memory");
        __syncthreads();
        if (c + 2 < nc) issue(c + 2);
        asm volatile("cp.async.commit_group;" ::: "memory");

        const uint32_t base = sb + (uint32_t)((c % 3) * HBUF);
        const uint32_t aB = base, bB = base + HT;

        #pragma unroll
        for (int ks = 0; ks < 2; ks++) {
            uint32_t a4[2][4];
            const uint32_t arow = (uint32_t)(wm * 32 + (lane & 15));
            const uint32_t akof = (uint32_t)((ks * 2 + (lane >> 4)) * 16);
            #pragma unroll
            for (int mi = 0; mi < 2; mi++)
                ldm_x4(a4[mi], aB + (arow + mi * 16) * 80 + akof);

            const uint32_t bn = (uint32_t)(wn * 64 + ((lane >> 4) << 3) + (lane & 7));
            const uint32_t bkof = (uint32_t)((ks * 2 + ((lane >> 3) & 1)) * 16);
            #pragma unroll
            for (int njp = 0; njp < 4; njp++) {
                uint32_t b4[4];
                ldm_x4(b4, bB + (bn + njp * 16) * 80 + bkof);
                #pragma unroll
                for (int sub = 0; sub < 2; sub++) {
                    const int ni = njp * 2 + sub;
                    #pragma unroll
                    for (int mi = 0; mi < 2; mi++)
                        mma16816h(acc[mi][ni], a4[mi], b4[sub * 2], b4[sub * 2 + 1]);
                }
            }
        }
    }

    const float* bp = alt ? bias2 : bias;
    #pragma unroll
    for (int mi = 0; mi < 2; mi++) {
        const int rb = m0 + wm * 32 + mi * 16 + (lane >> 2);
        #pragma unroll
        for (int half = 0; half < 2; half++) {
            const int r = rb + half * 8;
            long long orow = r;
            if (remap) orow = (r < S_TXT) ? (long long)(S_IMG + r) : (long long)(r - S_TXT);
            float* crow = C + orow * DIM;
            #pragma unroll
            for (int ni = 0; ni < 8; ni++) {
                const int col = n0 + wn * 64 + ni * 8 + (lane & 3) * 2;
                float2 o;
                o.x = acc[mi][ni][half * 2 + 0] + bp[col];
                o.y = acc[mi][ni][half * 2 + 1] + bp[col + 1];
                *reinterpret_cast<float2*>(crow + col) = o;
            }
        }
    }
}

// ---------------- flash attention (fused scores+softmax+PV, single fp16) -----
#define FB    10240            /* ring slot: one 128x32 fp16 tile */
#define FRING (4 * FB)         /* 40960 */
#define NBLK  (S_TOT / 128)    /* 20 */
#define NITEM (NBLK * 8)
__global__ __launch_bounds__(256) void flash_attn(
    const __half* __restrict__ q16,
    const __half* __restrict__ k16,
    const __half* __restrict__ vtp,
    __half* __restrict__ a16)
{
    extern __shared__ char smem[];
    const uint32_t sb = smem_u32(smem);
    const int tid = threadIdx.x, wid = tid >> 5, lane = tid & 31;
    const int qm0 = blockIdx.x * 128;
    const int h = blockIdx.y;

    // ---- Q fragments into registers, staged through ring area --------------
    uint32_t qh[8][4];
    {
        #pragma unroll
        for (int i = 0; i < 8; i++) {
            const int idx = i * 256 + tid;               // 0..2047
            const int r = idx >> 4, seg = idx & 15;
            cp16(sb + (uint32_t)((seg >> 2) * FB + r * 80 + (seg & 3) * 16),
                 q16 + (long long)(qm0 + r) * DIM + h * HD + seg * 8);
        }
        asm volatile("cp.async.commit_group;" ::: "memory");
        asm volatile("cp.async.wait_group 0;" ::: "memory");
        __syncthreads();
        #pragma unroll
        for (int j = 0; j < 8; j++) {
            const uint32_t addr = sb + (uint32_t)((j >> 1) * FB
                + (wid * 16 + (lane & 15)) * 80 + ((j & 1) * 2 + (lane >> 4)) * 16);
            ldm_x4(qh[j], addr);
        }
        __syncthreads();
    }

    float oacc[16][4];
    #pragma unroll
    for (int di = 0; di < 16; di++)
        #pragma unroll
        for (int j = 0; j < 4; j++) oacc[di][j] = 0.f;
    float sacc[16][4];
    uint32_t ph[8][4];
    float m0r = -1e30f, m1r = -1e30f, l0 = 0.f, l1 = 0.f;

    auto issue_item = [&](int j) {
        const int t = j >> 3, sub = j & 7, pc = sub & 3;
        const uint32_t slot = sb + (uint32_t)((j & 3) * FB);
        if ((sub >> 2) == 0) {            // K chunk pc of s-block t
            #pragma unroll
            for (int i = 0; i < 2; i++) {
                const int idx = i * 256 + tid;
                const int r = idx >> 2, s4 = idx & 3;
                cp16(slot + (uint32_t)(r * 80 + s4 * 16),
                     k16 + (long long)(t * 128 + r) * DIM + h * HD + pc * 32 + s4 * 8);
            }
        } else {                          // V^T chunk pc of s-block t
            #pragma unroll
            for (int i = 0; i < 2; i++) {
                const int idx = i * 256 + tid;
                const int r = idx >> 2, s4 = idx & 3;
                cp16(slot + (uint32_t)(r * 80 + s4 * 16),
                     vtp + (long long)(h * 128 + r) * S_TOT + t * 128 + pc * 32 + s4 * 8);
            }
        }
    };

    issue_item(0); asm volatile("cp.async.commit_group;" ::: "memory");
    issue_item(1); asm volatile("cp.async.commit_group;" ::: "memory");
    issue_item(2); asm volatile("cp.async.commit_group;" ::: "memory");

    const uint32_t bnrow = (uint32_t)(((lane >> 4) << 3) + (lane & 7));
    const uint32_t bksel = (uint32_t)((lane >> 3) & 1);

    for (int j = 0; j < NITEM; j++) {
        asm volatile("cp.async.wait_group 2;" ::: "memory");
        __syncthreads();
        if (j + 3 < NITEM) issue_item(j + 3);
        asm volatile("cp.async.commit_group;" ::: "memory");

        const int sub = j & 7, phase = sub >> 2, c = sub & 3;
        const uint32_t slot = sb + (uint32_t)((j & 3) * FB);

        if (phase == 0) {
            if (c == 0) {
                #pragma unroll
                for (int ni = 0; ni < 16; ni++)
                    #pragma unroll
                    for (int jj = 0; jj < 4; jj++) sacc[ni][jj] = 0.f;
            }
            #pragma unroll
            for (int ks2 = 0; ks2 < 2; ks2++) {
                const int j8 = c * 2 + ks2;
                const uint32_t kof = (uint32_t)((ks2 * 2 + bksel) * 16);
                #pragma unroll
                for (int njp = 0; njp < 8; njp++) {
                    uint32_t b4[4];
                    ldm_x4(b4, slot + (njp * 16 + bnrow) * 80 + kof);
                    #pragma unroll
                    for (int s2 = 0; s2 < 2; s2++) {
                        const int ni = njp * 2 + s2;
                        mma16816h(sacc[ni], qh[j8], b4[s2 * 2], b4[s2 * 2 + 1]);
                    }
                }
            }
            if (c == 3) {
                // ---- online softmax over this 128-col S block --------------
                const float sc = 0.08838834764831845f;
                float mb0 = -1e30f, mb1 = -1e30f;
                #pragma unroll
                for (int ni = 0; ni < 16; ni++) {
                    sacc[ni][0] *= sc; sacc[ni][1] *= sc;
                    sacc[ni][2] *= sc; sacc[ni][3] *= sc;
                    mb0 = fmaxf(mb0, fmaxf(sacc[ni][0], sacc[ni][1]));
                    mb1 = fmaxf(mb1, fmaxf(sacc[ni][2], sacc[ni][3]));
                }
                mb0 = fmaxf(mb0, __shfl_xor_sync(0xffffffffu, mb0, 1));
                mb0 = fmaxf(mb0, __shfl_xor_sync(0xffffffffu, mb0, 2));
                mb1 = fmaxf(mb1, __shfl_xor_sync(0xffffffffu, mb1, 1));
                mb1 = fmaxf(mb1, __shfl_xor_sync(0xffffffffu, mb1, 2));
                const float mn0 = fmaxf(m0r, mb0), mn1 = fmaxf(m1r, mb1);
                const float a0 = __expf(m0r - mn0), a1 = __expf(m1r - mn1);
                m0r = mn0; m1r = mn1;
                l0 *= a0; l1 *= a1;
                #pragma unroll
                for (int di = 0; di < 16; di++) {
                    oacc[di][0] *= a0; oacc[di][1] *= a0;
                    oacc[di][2] *= a1; oacc[di][3] *= a1;
                }
                float rs0 = 0.f, rs1 = 0.f;
                #pragma unroll
                for (int ni = 0; ni < 16; ni++) {
                    const float p0 = __expf(sacc[ni][0] - mn0);
                    const float p1 = __expf(sacc[ni][1] - mn0);
                    const float p2 = __expf(sacc[ni][2] - mn1);
                    const float p3 = __expf(sacc[ni][3] - mn1);
                    rs0 += p0 + p1; rs1 += p2 + p3;
                    const int j8 = ni >> 1;
                    __half2 lo2 = __floats2half2_rn(p0, p1);
                    __half2 hi2 = __floats2half2_rn(p2, p3);
                    if ((ni & 1) == 0) {
                        ph[j8][0] = *reinterpret_cast<uint32_t*>(&lo2);
                        ph[j8][1] = *reinterpret_cast<uint32_t*>(&hi2);
                    } else {
                        ph[j8][2] = *reinterpret_cast<uint32_t*>(&lo2);
                        ph[j8][3] = *reinterpret_cast<uint32_t*>(&hi2);
                    }
                }
                l0 += rs0; l1 += rs1;
            }
        } else {
            // ---- O += P * V --------------------------------------------------
            #pragma unroll
            for (int ks2 = 0; ks2 < 2; ks2++) {
                const int j8 = c * 2 + ks2;
                const uint32_t kof = (uint32_t)((ks2 * 2 + bksel) * 16);
                #pragma unroll
                for (int djp = 0; djp < 8; djp++) {
                    uint32_t b4[4];
                    ldm_x4(b4, slot + (djp * 16 + bnrow) * 80 + kof);
                    #pragma unroll
                    for (int s2 = 0; s2 < 2; s2++) {
                        const int di = djp * 2 + s2;
                        mma16816h(oacc[di], ph[j8], b4[s2 * 2], b4[s2 * 2 + 1]);
                    }
                }
            }
        }
    }

    // ---- normalize and store fp16 ------------------------------------------
    l0 += __shfl_xor_sync(0xffffffffu, l0, 1);
    l0 += __shfl_xor_sync(0xffffffffu, l0, 2);
    l1 += __shfl_xor_sync(0xffffffffu, l1, 1);
    l1 += __shfl_xor_sync(0xffffffffu, l1, 2);
    const float i0 = 1.0f / l0, i1 = 1.0f / l1;
    const int r0 = qm0 + wid * 16 + (lane >> 2);
    const int r1 = r0 + 8;
    #pragma unroll
    for (int di = 0; di < 16; di++) {
        const int col = h * HD + di * 8 + (lane & 3) * 2;
        __half2 o0 = __floats2half2_rn(oacc[di][0] * i0, oacc[di][1] * i0);
        __half2 o1 = __floats2half2_rn(oacc[di][2] * i1, oacc[di][3] * i1);
        *reinterpret_cast<__half2*>(a16 + (long long)r0 * DIM + col) = o0;
        *reinterpret_cast<__half2*>(a16 + (long long)r1 * DIM + col) = o1;
    }
}

// ---------------- conversion kernels -----------------------------------------
// x = [txt rows from enc; img rows from hidden] -> fp16
__global__ void cvt_x16(const float* __restrict__ hidden, const float* __restrict__ enc,
                        __half* __restrict__ dst) {
    const long long i4 = ((long long)blockIdx.x * 256 + threadIdx.x) * 4;
    const long long row = i4 / DIM;
    const float* src = (row < S_TXT) ? (enc + i4) : (hidden + i4 - (long long)S_TXT * DIM);
    const float4 v = *reinterpret_cast<const float4*>(src);
    *reinterpret_cast<__half2*>(dst + i4)     = __floats2half2_rn(v.x, v.y);
    *reinterpret_cast<__half2*>(dst + i4 + 2) = __floats2half2_rn(v.z, v.w);
}

struct WPtrs { const float* p[8]; };
__global__ void cvt_w16(WPtrs W, __half* __restrict__ dst) {
    const long long i4 = ((long long)blockIdx.x * 256 + threadIdx.x) * 4;
    const float* src = W.p[blockIdx.y];
    __half* d = dst + (size_t)blockIdx.y * WSZ;
    const float4 v = *reinterpret_cast<const float4*>(src + i4);
    *reinterpret_cast<__half2*>(d + i4)     = __floats2half2_rn(v.x, v.y);
    *reinterpret_cast<__half2*>(d + i4 + 2) = __floats2half2_rn(v.z, v.w);
}

// ---------------- RMSNorm + RoPE -> fp16 -------------------------------------
__global__ void norm_rope16(
    const float* __restrict__ x,
    __half* __restrict__ out,
    const float* __restrict__ w_txt, const float* __restrict__ w_img,
    const float* __restrict__ txt_cos, const float* __restrict__ txt_sin,
    const float* __restrict__ img_cos, const float* __restrict__ img_sin)
{
    const int s = blockIdx.x;
    const int h = blockIdx.y;
    const int d = threadIdx.x;
    const long long off = (long long)s * DIM + h * HD;

    float v = x[off + d];
    float ss = v * v;
    #pragma unroll
    for (int o = 16; o > 0; o >>= 1) ss += __shfl_xor_sync(0xffffffffu, ss, o);
    __shared__ float wsum[4];
    if ((d & 31) == 0) wsum[d >> 5] = ss;
    __syncthreads();
    const float tot = wsum[0] + wsum[1] + wsum[2] + wsum[3];
    const float r = rsqrtf(tot * (1.0f / HD) + 1e-6f);

    const bool is_txt = (s < S_TXT);
    const float* w = is_txt ? w_txt : w_img;
    const float nv = v * r * w[d];

    const float other = __shfl_xor_sync(0xffffffffu, nv, 1);
    const float rot = (d & 1) ? other : -other;

    const long long srel = is_txt ? s : (s - S_TXT);
    const float cc = (is_txt ? txt_cos : img_cos)[srel * HD + d];
    const float sn = (is_txt ? txt_sin : img_sin)[srel * HD + d];
    out[off + d] = __float2half_rn(nv * cc + rot * sn);
}

// ---------------- V transpose: v[s, DIM] -> vt[head][d][s] fp16 --------------
__global__ void vtrans16(const float* __restrict__ v, __half* __restrict__ vt)
{
    __shared__ float tile[32][33];
    const int c0 = blockIdx.x * 32;
    const int s0 = blockIdx.y * 32;
    const int tx = threadIdx.x, ty = threadIdx.y;

    #pragma unroll
    for (int r = ty; r < 32; r += 8)
        tile[r][tx] = v[(long long)(s0 + r) * DIM + c0 + tx];
    __syncthreads();
    #pragma unroll
    for (int r = ty; r < 32; r += 8) {
        const int c = c0 + r;
        const int head = c >> 7, d = c & 127;
        vt[(long long)head * HD * S_TOT + (long long)d * S_TOT + s0 + tx] =
            __float2half_rn(tile[tx][r]);
    }
}

// ---------------- launch -----------------------------------------------------
extern "C" void kernel_launch(void* const* d_in, const int* in_sizes, int n_in,
                              void* d_out, int out_size)
{
    const float* hidden  = (const float*)d_in[0];
    const float* enc     = (const float*)d_in[1];
    const float* img_cos = (const float*)d_in[2];
    const float* img_sin = (const float*)d_in[3];
    const float* txt_cos = (const float*)d_in[4];
    const float* txt_sin = (const float*)d_in[5];

    const float *W[8];   // 0=Wq 1=Wk 2=Wv 3=Waq 4=Wak 5=Wav 6=Wo 7=Wao
    const float *bq, *bk, *bv, *baq, *bak, *bav, *bo, *bao;
    if (in_sizes[7] == DIM) {
        W[0] = (const float*)d_in[6];  bq  = (const float*)d_in[7];
        W[1] = (const float*)d_in[8];  bk  = (const float*)d_in[9];
        W[2] = (const float*)d_in[10]; bv  = (const float*)d_in[11];
        W[3] = (const float*)d_in[12]; baq = (const float*)d_in[13];
        W[4] = (const float*)d_in[14]; bak = (const float*)d_in[15];
        W[5] = (const float*)d_in[16]; bav = (const float*)d_in[17];
        W[6] = (const float*)d_in[18]; bo  = (const float*)d_in[19];
        W[7] = (const float*)d_in[20]; bao = (const float*)d_in[21];
    } else {
        for (int i = 0; i < 8; i++) W[i] = (const float*)d_in[6 + i];
        bq  = (const float*)d_in[14]; bk  = (const float*)d_in[15];
        bv  = (const float*)d_in[16]; baq = (const float*)d_in[17];
        bak = (const float*)d_in[18]; bav = (const float*)d_in[19];
        bo  = (const float*)d_in[20]; bao = (const float*)d_in[21];
    }
    const float* nq_w  = (const float*)d_in[22];
    const float* nk_w  = (const float*)d_in[23];
    const float* naq_w = (const float*)d_in[24];
    const float* nak_w = (const float*)d_in[25];

    static float *q, *k, *v;
    static __half *x16, *w16, *q16, *k16, *vt, *a16;
    static bool inited = false;
    if (!inited) {
        cudaGetSymbolAddress((void**)&q,   g_q);
        cudaGetSymbolAddress((void**)&k,   g_k);
        cudaGetSymbolAddress((void**)&v,   g_v);
        cudaGetSymbolAddress((void**)&x16, g_x16);
        cudaGetSymbolAddress((void**)&w16, g_w16);
        cudaGetSymbolAddress((void**)&q16, g_q16);
        cudaGetSymbolAddress((void**)&k16, g_k16);
        cudaGetSymbolAddress((void**)&vt,  g_vt);
        cudaGetSymbolAddress((void**)&a16, g_a16);
        cudaFuncSetAttribute(mma_gemm_h, cudaFuncAttributeMaxDynamicSharedMemorySize, HSM);
        cudaFuncSetAttribute(flash_attn, cudaFuncAttributeMaxDynamicSharedMemorySize, FRING);
        inited = true;
    }

    // 1. conversions: x -> fp16;  all 8 weights -> fp16 (one launch)
    cvt_x16<<<(S_TOT * DIM) / 1024, 256>>>(hidden, enc, x16);
    WPtrs wp; for (int i = 0; i < 8; i++) wp.p[i] = W[i];
    cvt_w16<<<dim3((int)(WSZ / 1024), 8), 256>>>(wp, w16);

    // 2. projections: all single fp16
    const dim3 gP(DIM / 128, S_TOT / 128, 1);   // (24, 20)
    mma_gemm_h<<<gP, 256, HSM>>>(x16, w16 + 0 * WSZ, w16 + 3 * WSZ, q, bq, baq, 0);
    mma_gemm_h<<<gP, 256, HSM>>>(x16, w16 + 1 * WSZ, w16 + 4 * WSZ, k, bk, bak, 0);
    mma_gemm_h<<<gP, 256, HSM>>>(x16, w16 + 2 * WSZ, w16 + 5 * WSZ, v, bv, bav, 0);

    // 3. RMSNorm + RoPE -> fp16;  V transpose -> fp16
    const dim3 gNR(S_TOT, HEADS);
    norm_rope16<<<gNR, 128>>>(q, q16, naq_w, nq_w, txt_cos, txt_sin, img_cos, img_sin);
    norm_rope16<<<gNR, 128>>>(k, k16, nak_w, nk_w, txt_cos, txt_sin, img_cos, img_sin);
    vtrans16<<<dim3(DIM / 32, S_TOT / 32), dim3(32, 8)>>>(v, vt);

    // 4. fused attention -> fp16 attn
    flash_attn<<<dim3(S_TOT / 128, HEADS), 256, FRING>>>(q16, k16, vt, a16);

    // 5. output projection (fp16; txt rows -> Wao/bao, remapped: img first)
    mma_gemm_h<<<gP, 256, HSM>>>(a16, w16 + 6 * WSZ, w16 + 7 * WSZ,
        (float*)d_out, bo, bao, 1);
}

// round 10
// speedup vs baseline: 7.3419x; 1.1341x over previous
#include <cuda_runtime.h>
#include <cuda_fp16.h>
#include <cstdint>
#include <math.h>

#define HEADS 24
#define HD    128
#define DIM   3072
#define S_IMG 2048
#define S_TXT 512
#define S_TOT 2560
#define WSZ   ((size_t)DIM * DIM)
#define SD    ((size_t)S_TOT * DIM)

// ---------------- scratch (static device memory; no allocations) ------------
__device__ float g_qkv[3 * SD];

__device__ __half g_x16[SD];
__device__ __half g_w16[8 * WSZ];            // Wq Wk Wv Waq Wak Wav Wo Wao
__device__ __half g_q16[SD];
__device__ __half g_k16[SD];
__device__ __half g_vt[(size_t)HEADS * HD * S_TOT];
__device__ __half g_a16[SD];

// ---------------- helpers ----------------------------------------------------
__device__ __forceinline__ uint32_t smem_u32(const void* p) {
    return (uint32_t)__cvta_generic_to_shared(p);
}

__device__ __forceinline__ void cp16(uint32_t dst, const void* src) {
    asm volatile("cp.async.cg.shared.global [%0], [%1], 16;" :: "r"(dst), "l"(src));
}

__device__ __forceinline__ void ldm_x4(uint32_t* r, uint32_t addr) {
    asm volatile("ldmatrix.sync.aligned.m8n8.x4.shared.b16 {%0,%1,%2,%3}, [%4];"
                 : "=r"(r[0]), "=r"(r[1]), "=r"(r[2]), "=r"(r[3]) : "r"(addr));
}

__device__ __forceinline__ void mma16816h(float* c, const uint32_t* a, uint32_t b0, uint32_t b1) {
    asm volatile(
        "mma.sync.aligned.m16n8k16.row.col.f32.f16.f16.f32 "
        "{%0,%1,%2,%3}, {%4,%5,%6,%7}, {%8,%9}, {%0,%1,%2,%3};"
        : "+f"(c[0]), "+f"(c[1]), "+f"(c[2]), "+f"(c[3])
        : "r"(a[0]), "r"(a[1]), "r"(a[2]), "r"(a[3]), "r"(b0), "r"(b1));
}

// ---------------- fp16 GEMM body (128x128 tile, 512 thr, 16 warps 4x4) -------
// 3-stage cp.async pipeline, BK=32, one __syncthreads per chunk.
#define HT   10240             /* 128 rows * 80 B */
#define HBUF (2 * HT)          /* A B = 20480 */
#define HSM  (3 * HBUF)        /* 61440, 3 stages */
__device__ __forceinline__ void gemm_body(
    const __half* __restrict__ A,
    const __half* __restrict__ B, const __half* __restrict__ B2,
    float* __restrict__ C,
    const float* __restrict__ bias, const float* __restrict__ bias2,
    int remap, char* smem)
{
    const uint32_t sb = smem_u32(smem);
    const int tid = threadIdx.x;          // 0..511
    const int wid = tid >> 5;             // 0..15
    const int lane = tid & 31;
    const int wm = wid & 3;               // 4 warps x 32 rows
    const int wn = wid >> 2;              // 4 warps x 32 cols

    const int m0 = blockIdx.y * 128;
    const int n0 = blockIdx.x * 128;
    const bool alt = (m0 < S_TXT);
    const __half* bsrc = alt ? B2 : B;

    float acc[2][4][4];
    #pragma unroll
    for (int mi = 0; mi < 2; mi++)
        #pragma unroll
        for (int ni = 0; ni < 4; ni++)
            #pragma unroll
            for (int j = 0; j < 4; j++) acc[mi][ni][j] = 0.f;

    auto issue = [&](int c) {
        const uint32_t base = sb + (uint32_t)((c % 3) * HBUF);
        const int k0 = c * 32;
        #pragma unroll
        for (int i = 0; i < 2; i++) {
            const int idx = i * 512 + tid;            // 0..1023
            const int arr = idx >> 9;                 // 0=A 1=B
            const int rem = idx & 511;
            const int r = rem >> 2, s4 = rem & 3;
            const __half* s = arr ? bsrc : A;
            const int rbase = arr ? n0 : m0;
            cp16(base + (uint32_t)(arr * HT + r * 80 + s4 * 16),
                 s + (long long)(rbase + r) * DIM + k0 + s4 * 8);
        }
    };

    const int nc = DIM / 32;  // 96
    issue(0); asm volatile("cp.async.commit_group;" ::: "memory");
    issue(1); asm volatile("cp.async.commit_group;" ::: "memory");

    for (int c = 0; c < nc; c++) {
        asm volatile("cp.async.wait_group 1;" ::: "memory");
        __syncthreads();
        if (c + 2 < nc) issue(c + 2);
        asm volatile("cp.async.commit_group;" ::: "memory");

        const uint32_t base = sb + (uint32_t)((c % 3) * HBUF);
        const uint32_t aB = base, bB = base + HT;

        #pragma unroll
        for (int ks = 0; ks < 2; ks++) {
            uint32_t a4[2][4];
            const uint32_t arow = (uint32_t)(wm * 32 + (lane & 15));
            const uint32_t akof = (uint32_t)((ks * 2 + (lane >> 4)) * 16);
            #pragma unroll
            for (int mi = 0; mi < 2; mi++)
                ldm_x4(a4[mi], aB + (arow + mi * 16) * 80 + akof);

            const uint32_t bn = (uint32_t)(wn * 32 + ((lane >> 4) << 3) + (lane & 7));
            const uint32_t bkof = (uint32_t)((ks * 2 + ((lane >> 3) & 1)) * 16);
            #pragma unroll
            for (int njp = 0; njp < 2; njp++) {
                uint32_t b4[4];
                ldm_x4(b4, bB + (bn + njp * 16) * 80 + bkof);
                #pragma unroll
                for (int sub = 0; sub < 2; sub++) {
                    const int ni = njp * 2 + sub;
                    #pragma unroll
                    for (int mi = 0; mi < 2; mi++)
                        mma16816h(acc[mi][ni], a4[mi], b4[sub * 2], b4[sub * 2 + 1]);
                }
            }
        }
    }

    const float* bp = alt ? bias2 : bias;
    #pragma unroll
    for (int mi = 0; mi < 2; mi++) {
        const int rb = m0 + wm * 32 + mi * 16 + (lane >> 2);
        #pragma unroll
        for (int half = 0; half < 2; half++) {
            const int r = rb + half * 8;
            long long orow = r;
            if (remap) orow = (r < S_TXT) ? (long long)(S_IMG + r) : (long long)(r - S_TXT);
            float* crow = C + orow * DIM;
            #pragma unroll
            for (int ni = 0; ni < 4; ni++) {
                const int col = n0 + wn * 32 + ni * 8 + (lane & 3) * 2;
                float2 o;
                o.x = acc[mi][ni][half * 2 + 0] + bp[col];
                o.y = acc[mi][ni][half * 2 + 1] + bp[col + 1];
                *reinterpret_cast<float2*>(crow + col) = o;
            }
        }
    }
}

struct Bias6 { const float* p[6]; };   // bq bk bv baq bak bav

// fused Q/K/V projection: blockIdx.z selects output
__global__ __launch_bounds__(512, 2) void mma_qkv(
    const __half* __restrict__ x, const __half* __restrict__ w,
    float* __restrict__ qkv, Bias6 bias)
{
    extern __shared__ char smem[];
    const int z = blockIdx.z;
    gemm_body(x, w + (size_t)z * WSZ, w + (size_t)(z + 3) * WSZ,
              qkv + (size_t)z * SD, bias.p[z], bias.p[z + 3], 0, smem);
}

// output projection (remap: img rows first)
__global__ __launch_bounds__(512, 2) void mma_out(
    const __half* __restrict__ a, const __half* __restrict__ w,
    float* __restrict__ out, const float* bo, const float* bao)
{
    extern __shared__ char smem[];
    gemm_body(a, w + (size_t)6 * WSZ, w + (size_t)7 * WSZ, out, bo, bao, 1, smem);
}

// ---------------- flash attention (fused scores+softmax+PV, single fp16) -----
#define FB    10240            /* ring slot: one 128x32 fp16 tile */
#define FRING (4 * FB)         /* 40960 */
#define NBLK  (S_TOT / 128)    /* 20 */
#define NITEM (NBLK * 8)
__global__ __launch_bounds__(256) void flash_attn(
    const __half* __restrict__ q16,
    const __half* __restrict__ k16,
    const __half* __restrict__ vtp,
    __half* __restrict__ a16)
{
    extern __shared__ char smem[];
    const uint32_t sb = smem_u32(smem);
    const int tid = threadIdx.x, wid = tid >> 5, lane = tid & 31;
    const int qm0 = blockIdx.x * 128;
    const int h = blockIdx.y;

    // ---- Q fragments into registers, staged through ring area --------------
    uint32_t qh[8][4];
    {
        #pragma unroll
        for (int i = 0; i < 8; i++) {
            const int idx = i * 256 + tid;               // 0..2047
            const int r = idx >> 4, seg = idx & 15;
            cp16(sb + (uint32_t)((seg >> 2) * FB + r * 80 + (seg & 3) * 16),
                 q16 + (long long)(qm0 + r) * DIM + h * HD + seg * 8);
        }
        asm volatile("cp.async.commit_group;" ::: "memory");
        asm volatile("cp.async.wait_group 0;" ::: "memory");
        __syncthreads();
        #pragma unroll
        for (int j = 0; j < 8; j++) {
            const uint32_t addr = sb + (uint32_t)((j >> 1) * FB
                + (wid * 16 + (lane & 15)) * 80 + ((j & 1) * 2 + (lane >> 4)) * 16);
            ldm_x4(qh[j], addr);
        }
        __syncthreads();
    }

    float oacc[16][4];
    #pragma unroll
    for (int di = 0; di < 16; di++)
        #pragma unroll
        for (int j = 0; j < 4; j++) oacc[di][j] = 0.f;
    float sacc[16][4];
    uint32_t ph[8][4];
    float m0r = -1e30f, m1r = -1e30f, l0 = 0.f, l1 = 0.f;

    auto issue_item = [&](int j) {
        const int t = j >> 3, sub = j & 7, pc = sub & 3;
        const uint32_t slot = sb + (uint32_t)((j & 3) * FB);
        if ((sub >> 2) == 0) {            // K chunk pc of s-block t
            #pragma unroll
            for (int i = 0; i < 2; i++) {
                const int idx = i * 256 + tid;
                const int r = idx >> 2, s4 = idx & 3;
                cp16(slot + (uint32_t)(r * 80 + s4 * 16),
                     k16 + (long long)(t * 128 + r) * DIM + h * HD + pc * 32 + s4 * 8);
            }
        } else {                          // V^T chunk pc of s-block t
            #pragma unroll
            for (int i = 0; i < 2; i++) {
                const int idx = i * 256 + tid;
                const int r = idx >> 2, s4 = idx & 3;
                cp16(slot + (uint32_t)(r * 80 + s4 * 16),
                     vtp + (long long)(h * 128 + r) * S_TOT + t * 128 + pc * 32 + s4 * 8);
            }
        }
    };

    issue_item(0); asm volatile("cp.async.commit_group;" ::: "memory");
    issue_item(1); asm volatile("cp.async.commit_group;" ::: "memory");
    issue_item(2); asm volatile("cp.async.commit_group;" ::: "memory");

    const uint32_t bnrow = (uint32_t)(((lane >> 4) << 3) + (lane & 7));
    const uint32_t bksel = (uint32_t)((lane >> 3) & 1);

    for (int j = 0; j < NITEM; j++) {
        asm volatile("cp.async.wait_group 2;" ::: "memory");
        __syncthreads();
        if (j + 3 < NITEM) issue_item(j + 3);
        asm volatile("cp.async.commit_group;" ::: "memory");

        const int sub = j & 7, phase = sub >> 2, c = sub & 3;
        const uint32_t slot = sb + (uint32_t)((j & 3) * FB);

        if (phase == 0) {
            if (c == 0) {
                #pragma unroll
                for (int ni = 0; ni < 16; ni++)
                    #pragma unroll
                    for (int jj = 0; jj < 4; jj++) sacc[ni][jj] = 0.f;
            }
            #pragma unroll
            for (int ks2 = 0; ks2 < 2; ks2++) {
                const int j8 = c * 2 + ks2;
                const uint32_t kof = (uint32_t)((ks2 * 2 + bksel) * 16);
                #pragma unroll
                for (int njp = 0; njp < 8; njp++) {
                    uint32_t b4[4];
                    ldm_x4(b4, slot + (njp * 16 + bnrow) * 80 + kof);
                    #pragma unroll
                    for (int s2 = 0; s2 < 2; s2++) {
                        const int ni = njp * 2 + s2;
                        mma16816h(sacc[ni], qh[j8], b4[s2 * 2], b4[s2 * 2 + 1]);
                    }
                }
            }
            if (c == 3) {
                // ---- online softmax over this 128-col S block --------------
                const float sc = 0.08838834764831845f;
                float mb0 = -1e30f, mb1 = -1e30f;
                #pragma unroll
                for (int ni = 0; ni < 16; ni++) {
                    sacc[ni][0] *= sc; sacc[ni][1] *= sc;
                    sacc[ni][2] *= sc; sacc[ni][3] *= sc;
                    mb0 = fmaxf(mb0, fmaxf(sacc[ni][0], sacc[ni][1]));
                    mb1 = fmaxf(mb1, fmaxf(sacc[ni][2], sacc[ni][3]));
                }
                mb0 = fmaxf(mb0, __shfl_xor_sync(0xffffffffu, mb0, 1));
                mb0 = fmaxf(mb0, __shfl_xor_sync(0xffffffffu, mb0, 2));
                mb1 = fmaxf(mb1, __shfl_xor_sync(0xffffffffu, mb1, 1));
                mb1 = fmaxf(mb1, __shfl_xor_sync(0xffffffffu, mb1, 2));
                const float mn0 = fmaxf(m0r, mb0), mn1 = fmaxf(m1r, mb1);
                const float a0 = __expf(m0r - mn0), a1 = __expf(m1r - mn1);
                m0r = mn0; m1r = mn1;
                l0 *= a0; l1 *= a1;
                #pragma unroll
                for (int di = 0; di < 16; di++) {
                    oacc[di][0] *= a0; oacc[di][1] *= a0;
                    oacc[di][2] *= a1; oacc[di][3] *= a1;
                }
                float rs0 = 0.f, rs1 = 0.f;
                #pragma unroll
                for (int ni = 0; ni < 16; ni++) {
                    const float p0 = __expf(sacc[ni][0] - mn0);
                    const float p1 = __expf(sacc[ni][1] - mn0);
                    const float p2 = __expf(sacc[ni][2] - mn1);
                    const float p3 = __expf(sacc[ni][3] - mn1);
                    rs0 += p0 + p1; rs1 += p2 + p3;
                    const int j8 = ni >> 1;
                    __half2 lo2 = __floats2half2_rn(p0, p1);
                    __half2 hi2 = __floats2half2_rn(p2, p3);
                    if ((ni & 1) == 0) {
                        ph[j8][0] = *reinterpret_cast<uint32_t*>(&lo2);
                        ph[j8][1] = *reinterpret_cast<uint32_t*>(&hi2);
                    } else {
                        ph[j8][2] = *reinterpret_cast<uint32_t*>(&lo2);
                        ph[j8][3] = *reinterpret_cast<uint32_t*>(&hi2);
                    }
                }
                l0 += rs0; l1 += rs1;
            }
        } else {
            // ---- O += P * V --------------------------------------------------
            #pragma unroll
            for (int ks2 = 0; ks2 < 2; ks2++) {
                const int j8 = c * 2 + ks2;
                const uint32_t kof = (uint32_t)((ks2 * 2 + bksel) * 16);
                #pragma unroll
                for (int djp = 0; djp < 8; djp++) {
                    uint32_t b4[4];
                    ldm_x4(b4, slot + (djp * 16 + bnrow) * 80 + kof);
                    #pragma unroll
                    for (int s2 = 0; s2 < 2; s2++) {
                        const int di = djp * 2 + s2;
                        mma16816h(oacc[di], ph[j8], b4[s2 * 2], b4[s2 * 2 + 1]);
                    }
                }
            }
        }
    }

    // ---- normalize and store fp16 ------------------------------------------
    l0 += __shfl_xor_sync(0xffffffffu, l0, 1);
    l0 += __shfl_xor_sync(0xffffffffu, l0, 2);
    l1 += __shfl_xor_sync(0xffffffffu, l1, 1);
    l1 += __shfl_xor_sync(0xffffffffu, l1, 2);
    const float i0 = 1.0f / l0, i1 = 1.0f / l1;
    const int r0 = qm0 + wid * 16 + (lane >> 2);
    const int r1 = r0 + 8;
    #pragma unroll
    for (int di = 0; di < 16; di++) {
        const int col = h * HD + di * 8 + (lane & 3) * 2;
        __half2 o0 = __floats2half2_rn(oacc[di][0] * i0, oacc[di][1] * i0);
        __half2 o1 = __floats2half2_rn(oacc[di][2] * i1, oacc[di][3] * i1);
        *reinterpret_cast<__half2*>(a16 + (long long)r0 * DIM + col) = o0;
        *reinterpret_cast<__half2*>(a16 + (long long)r1 * DIM + col) = o1;
    }
}

// ---------------- conversion kernels -----------------------------------------
// x = [txt rows from enc; img rows from hidden] -> fp16
__global__ void cvt_x16(const float* __restrict__ hidden, const float* __restrict__ enc,
                        __half* __restrict__ dst) {
    const long long i4 = ((long long)blockIdx.x * 256 + threadIdx.x) * 4;
    const long long row = i4 / DIM;
    const float* src = (row < S_TXT) ? (enc + i4) : (hidden + i4 - (long long)S_TXT * DIM);
    const float4 v = *reinterpret_cast<const float4*>(src);
    *reinterpret_cast<__half2*>(dst + i4)     = __floats2half2_rn(v.x, v.y);
    *reinterpret_cast<__half2*>(dst + i4 + 2) = __floats2half2_rn(v.z, v.w);
}

struct WPtrs { const float* p[8]; };
// all 8 weights -> fp16; 2 float4 per thread for MLP
__global__ void cvt_w16(WPtrs W, __half* __restrict__ dst) {
    const long long i8 = ((long long)blockIdx.x * 256 + threadIdx.x) * 8;
    const float* src = W.p[blockIdx.y];
    __half* d = dst + (size_t)blockIdx.y * WSZ;
    const float4 v0 = *reinterpret_cast<const float4*>(src + i8);
    const float4 v1 = *reinterpret_cast<const float4*>(src + i8 + 4);
    *reinterpret_cast<__half2*>(d + i8)     = __floats2half2_rn(v0.x, v0.y);
    *reinterpret_cast<__half2*>(d + i8 + 2) = __floats2half2_rn(v0.z, v0.w);
    *reinterpret_cast<__half2*>(d + i8 + 4) = __floats2half2_rn(v1.x, v1.y);
    *reinterpret_cast<__half2*>(d + i8 + 6) = __floats2half2_rn(v1.z, v1.w);
}

// ---------------- RMSNorm + RoPE -> fp16 -------------------------------------
__global__ void norm_rope16(
    const float* __restrict__ x,
    __half* __restrict__ out,
    const float* __restrict__ w_txt, const float* __restrict__ w_img,
    const float* __restrict__ txt_cos, const float* __restrict__ txt_sin,
    const float* __restrict__ img_cos, const float* __restrict__ img_sin)
{
    const int s = blockIdx.x;
    const int h = blockIdx.y;
    const int d = threadIdx.x;
    const long long off = (long long)s * DIM + h * HD;

    float v = x[off + d];
    float ss = v * v;
    #pragma unroll
    for (int o = 16; o > 0; o >>= 1) ss += __shfl_xor_sync(0xffffffffu, ss, o);
    __shared__ float wsum[4];
    if ((d & 31) == 0) wsum[d >> 5] = ss;
    __syncthreads();
    const float tot = wsum[0] + wsum[1] + wsum[2] + wsum[3];
    const float r = rsqrtf(tot * (1.0f / HD) + 1e-6f);

    const bool is_txt = (s < S_TXT);
    const float* w = is_txt ? w_txt : w_img;
    const float nv = v * r * w[d];

    const float other = __shfl_xor_sync(0xffffffffu, nv, 1);
    const float rot = (d & 1) ? other : -other;

    const long long srel = is_txt ? s : (s - S_TXT);
    const float cc = (is_txt ? txt_cos : img_cos)[srel * HD + d];
    const float sn = (is_txt ? txt_sin : img_sin)[srel * HD + d];
    out[off + d] = __float2half_rn(nv * cc + rot * sn);
}

// ---------------- V transpose: v[s, DIM] -> vt[head][d][s] fp16 --------------
__global__ void vtrans16(const float* __restrict__ v, __half* __restrict__ vt)
{
    __shared__ float tile[32][33];
    const int c0 = blockIdx.x * 32;
    const int s0 = blockIdx.y * 32;
    const int tx = threadIdx.x, ty = threadIdx.y;

    #pragma unroll
    for (int r = ty; r < 32; r += 8)
        tile[r][tx] = v[(long long)(s0 + r) * DIM + c0 + tx];
    __syncthreads();
    #pragma unroll
    for (int r = ty; r < 32; r += 8) {
        const int c = c0 + r;
        const int head = c >> 7, d = c & 127;
        vt[(long long)head * HD * S_TOT + (long long)d * S_TOT + s0 + tx] =
            __float2half_rn(tile[tx][r]);
    }
}

// ---------------- launch -----------------------------------------------------
extern "C" void kernel_launch(void* const* d_in, const int* in_sizes, int n_in,
                              void* d_out, int out_size)
{
    const float* hidden  = (const float*)d_in[0];
    const float* enc     = (const float*)d_in[1];
    const float* img_cos = (const float*)d_in[2];
    const float* img_sin = (const float*)d_in[3];
    const float* txt_cos = (const float*)d_in[4];
    const float* txt_sin = (const float*)d_in[5];

    const float *W[8];   // 0=Wq 1=Wk 2=Wv 3=Waq 4=Wak 5=Wav 6=Wo 7=Wao
    const float *bq, *bk, *bv, *baq, *bak, *bav, *bo, *bao;
    if (in_sizes[7] == DIM) {
        W[0] = (const float*)d_in[6];  bq  = (const float*)d_in[7];
        W[1] = (const float*)d_in[8];  bk  = (const float*)d_in[9];
        W[2] = (const float*)d_in[10]; bv  = (const float*)d_in[11];
        W[3] = (const float*)d_in[12]; baq = (const float*)d_in[13];
        W[4] = (const float*)d_in[14]; bak = (const float*)d_in[15];
        W[5] = (const float*)d_in[16]; bav = (const float*)d_in[17];
        W[6] = (const float*)d_in[18]; bo  = (const float*)d_in[19];
        W[7] = (const float*)d_in[20]; bao = (const float*)d_in[21];
    } else {
        for (int i = 0; i < 8; i++) W[i] = (const float*)d_in[6 + i];
        bq  = (const float*)d_in[14]; bk  = (const float*)d_in[15];
        bv  = (const float*)d_in[16]; baq = (const float*)d_in[17];
        bak = (const float*)d_in[18]; bav = (const float*)d_in[19];
        bo  = (const float*)d_in[20]; bao = (const float*)d_in[21];
    }
    const float* nq_w  = (const float*)d_in[22];
    const float* nk_w  = (const float*)d_in[23];
    const float* naq_w = (const float*)d_in[24];
    const float* nak_w = (const float*)d_in[25];

    static float *qkv;
    static __half *x16, *w16, *q16, *k16, *vt, *a16;
    static bool inited = false;
    if (!inited) {
        cudaGetSymbolAddress((void**)&qkv, g_qkv);
        cudaGetSymbolAddress((void**)&x16, g_x16);
        cudaGetSymbolAddress((void**)&w16, g_w16);
        cudaGetSymbolAddress((void**)&q16, g_q16);
        cudaGetSymbolAddress((void**)&k16, g_k16);
        cudaGetSymbolAddress((void**)&vt,  g_vt);
        cudaGetSymbolAddress((void**)&a16, g_a16);
        cudaFuncSetAttribute(mma_qkv,    cudaFuncAttributeMaxDynamicSharedMemorySize, HSM);
        cudaFuncSetAttribute(mma_out,    cudaFuncAttributeMaxDynamicSharedMemorySize, HSM);
        cudaFuncSetAttribute(flash_attn, cudaFuncAttributeMaxDynamicSharedMemorySize, FRING);
        inited = true;
    }

    // 1. conversions: x -> fp16;  all 8 weights -> fp16 (one launch)
    cvt_x16<<<(S_TOT * DIM) / 1024, 256>>>(hidden, enc, x16);
    WPtrs wp; for (int i = 0; i < 8; i++) wp.p[i] = W[i];
    cvt_w16<<<dim3((int)(WSZ / 2048), 8), 256>>>(wp, w16);

    // 2. fused QKV projections (one launch, z = q/k/v)
    Bias6 b6; b6.p[0] = bq; b6.p[1] = bk; b6.p[2] = bv;
              b6.p[3] = baq; b6.p[4] = bak; b6.p[5] = bav;
    mma_qkv<<<dim3(DIM / 128, S_TOT / 128, 3), 512, HSM>>>(x16, w16, qkv, b6);

    // 3. RMSNorm + RoPE -> fp16;  V transpose -> fp16
    const dim3 gNR(S_TOT, HEADS);
    norm_rope16<<<gNR, 128>>>(qkv + 0 * SD, q16, naq_w, nq_w, txt_cos, txt_sin, img_cos, img_sin);
    norm_rope16<<<gNR, 128>>>(qkv + 1 * SD, k16, nak_w, nk_w, txt_cos, txt_sin, img_cos, img_sin);
    vtrans16<<<dim3(DIM / 32, S_TOT / 32), dim3(32, 8)>>>(qkv + 2 * SD, vt);

    // 4. fused attention -> fp16 attn
    flash_attn<<<dim3(S_TOT / 128, HEADS), 256, FRING>>>(q16, k16, vt, a16);

    // 5. output projection (fp16; txt rows -> Wao/bao, remapped: img first)
    mma_out<<<dim3(DIM / 128, S_TOT / 128, 1), 512, HSM>>>(a16, w16, (float*)d_out, bo, bao);
}